// round 2
// baseline (speedup 1.0000x reference)
#include <cuda_runtime.h>
#include <cstdint>

// Problem constants
#define Bsz 4
#define Cc 256
#define CE 64
#define Tt 16
#define Hh 56
#define Ww 56
#define HW (Hh*Ww)            // 3136
#define THW (Tt*HW)           // 50176
#define NPOS (Bsz*THW)        // 200704
#define KK 49
#define K2G 196
#define EPS 1e-5f

// Scratch (allocation-free rule: __device__ globals)
__device__ float g_xenc[(size_t)NPOS * CE];    // [b][t][h][w][ce]  (~51 MB)
__device__ float g_corr[(size_t)K2G * NPOS];   // [k][pos]          (~157 MB)
__device__ float g_dwT[K2G * Cc];              // dec_w transposed [k][o]

// ---- packed f32x2 helpers ----------------------------------------------
__device__ __forceinline__ void ffma2(unsigned long long& d,
                                      unsigned long long a,
                                      unsigned long long b) {
    asm("fma.rn.f32x2 %0, %1, %2, %0;" : "+l"(d) : "l"(a), "l"(b));
}
__device__ __forceinline__ unsigned long long dup2(float v) {
    unsigned long long r;
    unsigned int u = __float_as_uint(v);
    asm("mov.b64 %0, {%1, %2};" : "=l"(r) : "r"(u), "r"(u));
    return r;
}
__device__ __forceinline__ float lo2(unsigned long long v) {
    return __uint_as_float((unsigned int)v);
}
__device__ __forceinline__ float hi2(unsigned long long v) {
    return __uint_as_float((unsigned int)(v >> 32));
}

// ---------------------------------------------------------------------------
// Kernel 0: transpose dec_w [o][k] -> g_dwT [k][o]
// ---------------------------------------------------------------------------
__global__ void k_prep(const float* __restrict__ dw) {
    int k = blockIdx.x;      // 0..195
    int o = threadIdx.x;     // 0..255
    g_dwT[k * Cc + o] = dw[o * K2G + k];
}

// ---------------------------------------------------------------------------
// Kernel 1: encode  — out[p,ce] = relu(bn(sum_c x[b,c,p] * enc_w[ce,c]))
// 128 p x 64 ce tile, K-chunk 16, 256 threads, packed f32x2 math.
// ---------------------------------------------------------------------------
__global__ void k_encode(const float* __restrict__ x, const float* __restrict__ w,
                         const float* __restrict__ gamma, const float* __restrict__ beta,
                         const float* __restrict__ mean, const float* __restrict__ var) {
    __shared__ __align__(16) float As[16][132];  // [c][p]
    __shared__ __align__(16) float Bs[16][68];   // [c][ce]
    const int b  = blockIdx.y;
    const int p0 = blockIdx.x * 128;
    const float* xb = x + (size_t)b * Cc * THW;
    const int tid = threadIdx.x;
    const int px = tid & 15;   // ce dim (quads)
    const int py = tid >> 4;   // p dim  (quads)

    unsigned long long acc2[4][4];   // pairs along p x 4 ce
#pragma unroll
    for (int i = 0; i < 4; i++)
#pragma unroll
        for (int j = 0; j < 4; j++) acc2[i][j] = 0ULL;

    for (int k0 = 0; k0 < Cc; k0 += 16) {
        {
            const int row = tid >> 5;
            const int col = (tid & 31) * 4;
#pragma unroll
            for (int r = 0; r < 16; r += 8) {
                float4 v = *reinterpret_cast<const float4*>(
                    xb + (size_t)(k0 + row + r) * THW + p0 + col);
                *reinterpret_cast<float4*>(&As[row + r][col]) = v;
            }
        }
        {
            const int ce = tid >> 2;
            const int cl = (tid & 3) * 4;
            float4 v = *reinterpret_cast<const float4*>(w + ce * Cc + k0 + cl);
            Bs[cl + 0][ce] = v.x; Bs[cl + 1][ce] = v.y;
            Bs[cl + 2][ce] = v.z; Bs[cl + 3][ce] = v.w;
        }
        __syncthreads();
#pragma unroll
        for (int k = 0; k < 16; k++) {
            const unsigned long long* A64 =
                reinterpret_cast<const unsigned long long*>(&As[k][0]);
            unsigned long long a2[4];
            a2[0] = A64[py * 2];     a2[1] = A64[py * 2 + 1];
            a2[2] = A64[32 + py * 2]; a2[3] = A64[32 + py * 2 + 1];
            float4 B0 = *reinterpret_cast<const float4*>(&Bs[k][px * 4]);
            unsigned long long bd[4] = {dup2(B0.x), dup2(B0.y), dup2(B0.z), dup2(B0.w)};
#pragma unroll
            for (int q = 0; q < 4; q++)
#pragma unroll
                for (int j = 0; j < 4; j++) ffma2(acc2[q][j], a2[q], bd[j]);
        }
        __syncthreads();
    }

    float sc[4], bi[4];
#pragma unroll
    for (int j = 0; j < 4; j++) {
        int ce = px * 4 + j;
        sc[j] = gamma[ce] * rsqrtf(var[ce] + EPS);
        bi[j] = beta[ce] - mean[ce] * sc[j];
    }
#pragma unroll
    for (int i = 0; i < 8; i++) {
        int p = p0 + ((i >> 2) * 64) + py * 4 + (i & 3);
        float a0 = (i & 1) ? hi2(acc2[i >> 1][0]) : lo2(acc2[i >> 1][0]);
        float a1 = (i & 1) ? hi2(acc2[i >> 1][1]) : lo2(acc2[i >> 1][1]);
        float a2v = (i & 1) ? hi2(acc2[i >> 1][2]) : lo2(acc2[i >> 1][2]);
        float a3 = (i & 1) ? hi2(acc2[i >> 1][3]) : lo2(acc2[i >> 1][3]);
        float4 r;
        r.x = fmaxf(a0 * sc[0] + bi[0], 0.f);
        r.y = fmaxf(a1 * sc[1] + bi[1], 0.f);
        r.z = fmaxf(a2v * sc[2] + bi[2], 0.f);
        r.w = fmaxf(a3 * sc[3] + bi[3], 0.f);
        *reinterpret_cast<float4*>(&g_xenc[((size_t)b * THW + p) * CE + px * 4]) = r;
    }
}

// ---------------------------------------------------------------------------
// Kernel 2: correlation — one warp per (b,t,h,w); 8 warps/block share (b,t,h).
// Output written k-major: g_corr[j*NPOS + pos].
// ---------------------------------------------------------------------------
__global__ void k_corr(const float* __restrict__ fw) {
    __shared__ __align__(16) float fws[KK * CE];   // fws[ko*64 + c]
    __shared__ __align__(16) float res[K2G][8];    // [j][warp]
    const int tid  = threadIdx.x;
    const int warp = tid >> 5;
    const int lane = tid & 31;

    const int pos0 = blockIdx.x * 8;        // 8 | 56 -> same (b,t,h) per block
    const int w0 = pos0 % Ww;
    int rest = pos0 / Ww;
    const int h = rest % Hh; rest /= Hh;
    const int t = rest % Tt;
    const int b = rest / Tt;

    for (int idx = tid; idx < KK * CE; idx += 256) {
        int c = idx / KK, ko = idx % KK;
        fws[ko * CE + c] = fw[c * (Tt * KK) + t * KK + ko];
    }
    __syncthreads();

    const int wp = w0 + warp;
    const int t1 = (t == 0) ? 0 : t - 1;
    const float* x1p = g_xenc + (((size_t)(b * Tt + t1) * Hh + h) * Ww + wp) * CE;
    float2 a = *reinterpret_cast<const float2*>(x1p + 2 * lane);
    const float* x2base = g_xenc + ((size_t)(b * Tt + t) * HW) * CE;

    const int g = lane >> 3;
#pragma unroll 1
    for (int ko = 0; ko < KK; ko++) {
        int ky = ko / 7, kx = ko - ky * 7;
        int y  = h + ky - 3;
        int xx = wp + kx - 3;
        float2 v = make_float2(0.f, 0.f);
        if ((unsigned)y < (unsigned)Hh && (unsigned)xx < (unsigned)Ww)
            v = *reinterpret_cast<const float2*>(x2base + ((size_t)(y * Ww + xx)) * CE + 2 * lane);
        float2 f = *reinterpret_cast<const float2*>(&fws[ko * CE + 2 * lane]);
        float s = f.x * a.x * v.x + f.y * a.y * v.y;
        s += __shfl_xor_sync(0xffffffffu, s, 1);
        s += __shfl_xor_sync(0xffffffffu, s, 2);
        s += __shfl_xor_sync(0xffffffffu, s, 4);
        if ((lane & 7) == 0) res[ko * 4 + g][warp] = s * 0.0625f;
    }
    __syncthreads();

    if (tid < K2G) {
        float4 v0 = *reinterpret_cast<const float4*>(&res[tid][0]);
        float4 v1 = *reinterpret_cast<const float4*>(&res[tid][4]);
        float* o = g_corr + (size_t)tid * NPOS + pos0;
        *reinterpret_cast<float4*>(o)     = v0;
        *reinterpret_cast<float4*>(o + 4) = v1;
    }
}

// ---------------------------------------------------------------------------
// Kernel 3: decode — C[p,o] = sum_k corr[k,p]*dwT[k,o]; out = relu(x + bn(C))
// 128 p x 128 o tile, exact K=196 in 7 chunks of 28, packed f32x2 math.
// ---------------------------------------------------------------------------
__global__ void k_dec(const float* __restrict__ x,
                      const float* __restrict__ gamma, const float* __restrict__ beta,
                      const float* __restrict__ mean, const float* __restrict__ var,
                      float* __restrict__ out) {
    __shared__ __align__(16) float As[28][132];  // [k][p]
    __shared__ __align__(16) float Bs[28][132];  // [k][o]
    const int tid = threadIdx.x;
    const size_t P0 = (size_t)blockIdx.x * 128;
    const int o0 = blockIdx.y * 128;
    const int px = tid & 15;   // p quads
    const int py = tid >> 4;   // o quads

    unsigned long long acc2[4][8];   // p pairs x 8 o
#pragma unroll
    for (int i = 0; i < 4; i++)
#pragma unroll
        for (int j = 0; j < 8; j++) acc2[i][j] = 0ULL;

    for (int k0 = 0; k0 < K2G; k0 += 28) {
        // A: g_corr[k0+r][P0+col] -> As[r][col] (direct, coalesced)
#pragma unroll
        for (int i = tid; i < 896; i += 256) {
            int r = i >> 5, col = (i & 31) * 4;
            float4 v = *reinterpret_cast<const float4*>(
                g_corr + (size_t)(k0 + r) * NPOS + P0 + col);
            *reinterpret_cast<float4*>(&As[r][col]) = v;
        }
        // B: g_dwT[k0+r][o0+col] -> Bs[r][col] (direct, coalesced)
#pragma unroll
        for (int i = tid; i < 896; i += 256) {
            int r = i >> 5, col = (i & 31) * 4;
            float4 v = *reinterpret_cast<const float4*>(
                g_dwT + (size_t)(k0 + r) * Cc + o0 + col);
            *reinterpret_cast<float4*>(&Bs[r][col]) = v;
        }
        __syncthreads();
#pragma unroll
        for (int k = 0; k < 28; k++) {
            const unsigned long long* A64 =
                reinterpret_cast<const unsigned long long*>(&As[k][0]);
            unsigned long long a2[4];
            a2[0] = A64[px * 2];      a2[1] = A64[px * 2 + 1];
            a2[2] = A64[32 + px * 2]; a2[3] = A64[32 + px * 2 + 1];
            float4 B0 = *reinterpret_cast<const float4*>(&Bs[k][py * 4]);
            float4 B1 = *reinterpret_cast<const float4*>(&Bs[k][64 + py * 4]);
            unsigned long long bd[8] = {dup2(B0.x), dup2(B0.y), dup2(B0.z), dup2(B0.w),
                                        dup2(B1.x), dup2(B1.y), dup2(B1.z), dup2(B1.w)};
#pragma unroll
            for (int q = 0; q < 4; q++)
#pragma unroll
                for (int j = 0; j < 8; j++) ffma2(acc2[q][j], a2[q], bd[j]);
        }
        __syncthreads();
    }

    // Epilogue: bn + residual + relu. 50176 % 128 == 0 -> no batch straddle.
    const int b   = (int)(P0 / THW);
    const int tp0 = (int)(P0 % THW);
#pragma unroll
    for (int j = 0; j < 8; j++) {
        const int o = o0 + ((j >> 2) * 64) + py * 4 + (j & 3);
        const float sc = gamma[o] * rsqrtf(var[o] + EPS);
        const float bi = beta[o] - mean[o] * sc;
        const float* xrow = x   + ((size_t)b * Cc + o) * THW + tp0;
        float*       orow = out + ((size_t)b * Cc + o) * THW + tp0;
#pragma unroll
        for (int v = 0; v < 2; v++) {
            const int pl = v * 64 + px * 4;
            float4 xr = *reinterpret_cast<const float4*>(xrow + pl);
            float4 r;
            r.x = fmaxf(lo2(acc2[v * 2 + 0][j]) * sc + bi + xr.x, 0.f);
            r.y = fmaxf(hi2(acc2[v * 2 + 0][j]) * sc + bi + xr.y, 0.f);
            r.z = fmaxf(lo2(acc2[v * 2 + 1][j]) * sc + bi + xr.z, 0.f);
            r.w = fmaxf(hi2(acc2[v * 2 + 1][j]) * sc + bi + xr.w, 0.f);
            *reinterpret_cast<float4*>(orow + pl) = r;
        }
    }
}

// ---------------------------------------------------------------------------
extern "C" void kernel_launch(void* const* d_in, const int* in_sizes, int n_in,
                              void* d_out, int out_size) {
    const float* x         = (const float*)d_in[0];
    const float* enc_w     = (const float*)d_in[1];
    const float* enc_gamma = (const float*)d_in[2];
    const float* enc_beta  = (const float*)d_in[3];
    const float* enc_mean  = (const float*)d_in[4];
    const float* enc_var   = (const float*)d_in[5];
    const float* fw        = (const float*)d_in[6];
    const float* dec_w     = (const float*)d_in[7];
    const float* dec_gamma = (const float*)d_in[8];
    const float* dec_beta  = (const float*)d_in[9];
    const float* dec_mean  = (const float*)d_in[10];
    const float* dec_var   = (const float*)d_in[11];
    float* out = (float*)d_out;

    k_prep<<<K2G, Cc>>>(dec_w);
    k_encode<<<dim3(THW / 128, Bsz), 256>>>(x, enc_w, enc_gamma, enc_beta, enc_mean, enc_var);
    k_corr<<<NPOS / 8, 256>>>(fw);
    k_dec<<<dim3(NPOS / 128, Cc / 128), 256>>>(x, dec_gamma, dec_beta, dec_mean, dec_var, out);
}

// round 5
// speedup vs baseline: 1.2901x; 1.2901x over previous
#include <cuda_runtime.h>
#include <cuda_bf16.h>
#include <cstdint>

// Problem constants
#define Bsz 4
#define Cc 256
#define CE 64
#define Tt 16
#define Hh 56
#define Ww 56
#define HW (Hh*Ww)            // 3136
#define THW (Tt*HW)           // 50176
#define NPOS (Bsz*THW)        // 200704
#define KK 49
#define K2G 196
#define KPAD 208              // 13 * 16
#define NKS 13                // k-steps of 16
#define EPS 1e-5f

// Scratch (allocation-free rule: __device__ globals)
__device__ float g_xenc[(size_t)NPOS * CE];                 // [pos][64] fp32
__device__ __nv_bfloat16 g_corrh[(size_t)NPOS * KPAD];      // corr hi bf16 [pos][208]
__device__ __nv_bfloat16 g_corrl[(size_t)NPOS * KPAD];      // corr lo bf16 [pos][208]
__device__ __nv_bfloat16 g_dwh[Cc * KPAD];                  // dec_w hi [o][208]
__device__ __nv_bfloat16 g_dwl[Cc * KPAD];                  // dec_w lo [o][208]

__device__ __forceinline__ uint32_t smem_u32(const void* p) {
    uint32_t a;
    asm("{ .reg .u64 t; cvta.to.shared.u64 t, %1; cvt.u32.u64 %0, t; }"
        : "=r"(a) : "l"(p));
    return a;
}

// ---------------------------------------------------------------------------
// Kernel 0: split dec_w [o][196] fp32 -> g_dwh/g_dwl [o][208] bf16 (zero-pad)
// ---------------------------------------------------------------------------
__global__ void k_prep(const float* __restrict__ dw) {
    int k = blockIdx.x;      // 0..207
    int o = threadIdx.x;     // 0..255
    float v = (k < K2G) ? dw[o * K2G + k] : 0.f;
    __nv_bfloat16 h = __float2bfloat16(v);
    float r = v - __bfloat162float(h);
    g_dwh[o * KPAD + k] = h;
    g_dwl[o * KPAD + k] = __float2bfloat16(r);
}

// ---------------------------------------------------------------------------
// Kernel 1: encode (R1 version, known good: 146us, fma-bound)
// ---------------------------------------------------------------------------
__global__ void k_encode(const float* __restrict__ x, const float* __restrict__ w,
                         const float* __restrict__ gamma, const float* __restrict__ beta,
                         const float* __restrict__ mean, const float* __restrict__ var) {
    __shared__ __align__(16) float As[16][132];
    __shared__ __align__(16) float Bs[16][68];
    const int b  = blockIdx.y;
    const int p0 = blockIdx.x * 128;
    const float* xb = x + (size_t)b * Cc * THW;
    const int tid = threadIdx.x;
    const int px = tid & 15;
    const int py = tid >> 4;

    float acc[8][4];
#pragma unroll
    for (int i = 0; i < 8; i++)
#pragma unroll
        for (int j = 0; j < 4; j++) acc[i][j] = 0.f;

    for (int k0 = 0; k0 < Cc; k0 += 16) {
        {
            const int row = tid >> 5;
            const int col = (tid & 31) * 4;
#pragma unroll
            for (int r = 0; r < 16; r += 8) {
                float4 v = *reinterpret_cast<const float4*>(
                    xb + (size_t)(k0 + row + r) * THW + p0 + col);
                *reinterpret_cast<float4*>(&As[row + r][col]) = v;
            }
        }
        {
            const int ce = tid >> 2;
            const int cl = (tid & 3) * 4;
            float4 v = *reinterpret_cast<const float4*>(w + ce * Cc + k0 + cl);
            Bs[cl + 0][ce] = v.x; Bs[cl + 1][ce] = v.y;
            Bs[cl + 2][ce] = v.z; Bs[cl + 3][ce] = v.w;
        }
        __syncthreads();
#pragma unroll
        for (int k = 0; k < 16; k++) {
            float4 A0 = *reinterpret_cast<const float4*>(&As[k][py * 4]);
            float4 A1 = *reinterpret_cast<const float4*>(&As[k][64 + py * 4]);
            float4 B0 = *reinterpret_cast<const float4*>(&Bs[k][px * 4]);
            float a[8] = {A0.x, A0.y, A0.z, A0.w, A1.x, A1.y, A1.z, A1.w};
            float bb[4] = {B0.x, B0.y, B0.z, B0.w};
#pragma unroll
            for (int i = 0; i < 8; i++)
#pragma unroll
                for (int j = 0; j < 4; j++) acc[i][j] += a[i] * bb[j];
        }
        __syncthreads();
    }

    float sc[4], bi[4];
#pragma unroll
    for (int j = 0; j < 4; j++) {
        int ce = px * 4 + j;
        sc[j] = gamma[ce] * rsqrtf(var[ce] + EPS);
        bi[j] = beta[ce] - mean[ce] * sc[j];
    }
#pragma unroll
    for (int i = 0; i < 8; i++) {
        int p = p0 + ((i >> 2) * 64) + py * 4 + (i & 3);
        float4 r;
        r.x = fmaxf(acc[i][0] * sc[0] + bi[0], 0.f);
        r.y = fmaxf(acc[i][1] * sc[1] + bi[1], 0.f);
        r.z = fmaxf(acc[i][2] * sc[2] + bi[2], 0.f);
        r.w = fmaxf(acc[i][3] * sc[3] + bi[3], 0.f);
        *reinterpret_cast<float4*>(&g_xenc[((size_t)b * THW + p) * CE + px * 4]) = r;
    }
}

// ---------------------------------------------------------------------------
// Kernel 2: correlation — one warp per (b,t,h,w); writes bf16 hi/lo [pos][208]
// ---------------------------------------------------------------------------
__global__ void k_corr(const float* __restrict__ fw) {
    __shared__ __align__(16) float fws[KK * CE];
    __shared__ __align__(16) float res[8][KPAD];
    const int tid  = threadIdx.x;
    const int warp = tid >> 5;
    const int lane = tid & 31;

    const int pos0 = blockIdx.x * 8;
    const int w0 = pos0 % Ww;
    int rest = pos0 / Ww;
    const int h = rest % Hh; rest /= Hh;
    const int t = rest % Tt;
    const int b = rest / Tt;

    for (int idx = tid; idx < KK * CE; idx += 256) {
        int c = idx / KK, ko = idx % KK;
        fws[ko * CE + c] = fw[c * (Tt * KK) + t * KK + ko];
    }
    __syncthreads();

    const int wp = w0 + warp;
    const int t1 = (t == 0) ? 0 : t - 1;
    const float* x1p = g_xenc + (((size_t)(b * Tt + t1) * Hh + h) * Ww + wp) * CE;
    float2 a = *reinterpret_cast<const float2*>(x1p + 2 * lane);
    const float* x2base = g_xenc + ((size_t)(b * Tt + t) * HW) * CE;

    const int g = lane >> 3;
#pragma unroll 1
    for (int ko = 0; ko < KK; ko++) {
        int ky = ko / 7, kx = ko - ky * 7;
        int y  = h + ky - 3;
        int xx = wp + kx - 3;
        float2 v = make_float2(0.f, 0.f);
        if ((unsigned)y < (unsigned)Hh && (unsigned)xx < (unsigned)Ww)
            v = *reinterpret_cast<const float2*>(x2base + ((size_t)(y * Ww + xx)) * CE + 2 * lane);
        float2 f = *reinterpret_cast<const float2*>(&fws[ko * CE + 2 * lane]);
        float s = f.x * a.x * v.x + f.y * a.y * v.y;
        s += __shfl_xor_sync(0xffffffffu, s, 1);
        s += __shfl_xor_sync(0xffffffffu, s, 2);
        s += __shfl_xor_sync(0xffffffffu, s, 4);
        if ((lane & 7) == 0) res[warp][ko * 4 + g] = s * 0.0625f;
    }
    __syncwarp();

    const int pos = pos0 + warp;
    uint32_t* oh = reinterpret_cast<uint32_t*>(g_corrh) + (size_t)pos * (KPAD / 2);
    uint32_t* ol = reinterpret_cast<uint32_t*>(g_corrl) + (size_t)pos * (KPAD / 2);
#pragma unroll
    for (int i = 0; i < 4; i++) {
        int u = lane + 32 * i;             // pair index 0..103
        if (u >= KPAD / 2) break;
        uint32_t ph = 0, pl = 0;
        if (u < K2G / 2) {                 // 98 real pairs
            float v0 = res[warp][2 * u], v1 = res[warp][2 * u + 1];
            __nv_bfloat16 h0 = __float2bfloat16(v0);
            __nv_bfloat16 h1 = __float2bfloat16(v1);
            float r0 = v0 - __bfloat162float(h0);
            float r1 = v1 - __bfloat162float(h1);
            __nv_bfloat16 l0 = __float2bfloat16(r0);
            __nv_bfloat16 l1 = __float2bfloat16(r1);
            ph = (uint32_t)__bfloat16_as_ushort(h0) |
                 ((uint32_t)__bfloat16_as_ushort(h1) << 16);
            pl = (uint32_t)__bfloat16_as_ushort(l0) |
                 ((uint32_t)__bfloat16_as_ushort(l1) << 16);
        }
        oh[u] = ph;
        ol[u] = pl;
    }
}

// ---------------------------------------------------------------------------
// Kernel 3: decode via mma.sync bf16 hi/lo split.
// CTA: 128 p x 128 o, full K=208 in smem. Warp tile 32p x 64o.
// D[p][o] = sum_k corr[p][k]*dw[o][k]  (A row-major, B "col-major" = [o][k])
// ---------------------------------------------------------------------------
#define PITCH 216                      // bf16 per smem row (208 + 8 pad)
#define PITCHB (PITCH*2)               // 432 bytes
#define ROWU4 26                       // uint4 per 416B row of real data
#define TILE_BYTES (128*PITCHB)        // 55296
#define SA_H 0
#define SA_L (TILE_BYTES)
#define SB_H (2*TILE_BYTES)
#define SB_L (3*TILE_BYTES)
#define SM_SCB (4*TILE_BYTES)          // 221184: float2 scb[128]
#define SMEM_DEC (SM_SCB + 128*8)      // 222208

__device__ __forceinline__ void ldmat4(uint32_t* d, uint32_t addr) {
    asm volatile("ldmatrix.sync.aligned.m8n8.x4.shared.b16 {%0,%1,%2,%3}, [%4];"
                 : "=r"(d[0]), "=r"(d[1]), "=r"(d[2]), "=r"(d[3]) : "r"(addr));
}
__device__ __forceinline__ void mma16816(float* c, const uint32_t* a, const uint32_t* b) {
    asm volatile(
        "mma.sync.aligned.m16n8k16.row.col.f32.bf16.bf16.f32 "
        "{%0,%1,%2,%3}, {%4,%5,%6,%7}, {%8,%9}, {%0,%1,%2,%3};"
        : "+f"(c[0]), "+f"(c[1]), "+f"(c[2]), "+f"(c[3])
        : "r"(a[0]), "r"(a[1]), "r"(a[2]), "r"(a[3]), "r"(b[0]), "r"(b[1]));
}

__global__ void __launch_bounds__(256, 1) k_dec(
    const float* __restrict__ x,
    const float* __restrict__ gamma, const float* __restrict__ beta,
    const float* __restrict__ mean, const float* __restrict__ var,
    float* __restrict__ out) {
    extern __shared__ __align__(16) char sm[];
    const uint32_t sb = smem_u32(sm);
    float2* scb = reinterpret_cast<float2*>(sm + SM_SCB);
    const int tid  = threadIdx.x;
    const int wid  = tid >> 5;
    const int lane = tid & 31;
    const size_t P0 = (size_t)blockIdx.x * 128;
    const int o0 = blockIdx.y * 128;
    const int wm = wid & 3;            // p: 4 x 32
    const int wn = wid >> 2;           // o: 2 x 64

    // Stage A (corr rows) and B (weight rows): 128 rows x 26 uint4 each.
#pragma unroll 1
    for (int i = tid; i < 128 * ROWU4; i += 256) {
        int r = i / ROWU4, c = i % ROWU4;
        uint32_t d = r * PITCHB + c * 16;
        *reinterpret_cast<uint4*>(sm + SA_H + d) =
            *(reinterpret_cast<const uint4*>(g_corrh + (P0 + r) * KPAD) + c);
        *reinterpret_cast<uint4*>(sm + SA_L + d) =
            *(reinterpret_cast<const uint4*>(g_corrl + (P0 + r) * KPAD) + c);
        *reinterpret_cast<uint4*>(sm + SB_H + d) =
            *(reinterpret_cast<const uint4*>(g_dwh + (size_t)(o0 + r) * KPAD) + c);
        *reinterpret_cast<uint4*>(sm + SB_L + d) =
            *(reinterpret_cast<const uint4*>(g_dwl + (size_t)(o0 + r) * KPAD) + c);
    }
    if (tid < 128) {
        int o = o0 + tid;
        float s = gamma[o] * rsqrtf(var[o] + EPS);
        scb[tid] = make_float2(s, beta[o] - mean[o] * s);
    }
    __syncthreads();

    float acc[16][4];
#pragma unroll
    for (int i = 0; i < 16; i++)
#pragma unroll
        for (int j = 0; j < 4; j++) acc[i][j] = 0.f;

    // Precompute lane-invariant address parts
    const uint32_t a_row = wm * 32 + (lane & 15);
    const uint32_t a_colb = ((lane >> 4) << 4);              // 0 or 16 bytes
    const uint32_t b_row0 = wn * 64 + ((lane >> 4) << 3) + (lane & 7);
    const uint32_t b_colb = (((lane >> 3) & 1) << 4);        // 0 or 16 bytes

#pragma unroll 1
    for (int ks = 0; ks < NKS; ks++) {
        const uint32_t kb = ks * 32;                          // 16 bf16 = 32B
        uint32_t ah[2][4], al[2][4];
#pragma unroll
        for (int mt = 0; mt < 2; mt++) {
            uint32_t ad = sb + SA_H + (a_row + mt * 16) * PITCHB + kb + a_colb;
            ldmat4(ah[mt], ad);
            ldmat4(al[mt], ad + TILE_BYTES);
        }
        uint32_t bh[8][2], bl[8][2];
#pragma unroll
        for (int np = 0; np < 4; np++) {
            uint32_t bd = sb + SB_H + (b_row0 + np * 16) * PITCHB + kb + b_colb;
            uint32_t r[4];
            ldmat4(r, bd);
            bh[2 * np][0] = r[0]; bh[2 * np][1] = r[1];
            bh[2 * np + 1][0] = r[2]; bh[2 * np + 1][1] = r[3];
            ldmat4(r, bd + TILE_BYTES);
            bl[2 * np][0] = r[0]; bl[2 * np][1] = r[1];
            bl[2 * np + 1][0] = r[2]; bl[2 * np + 1][1] = r[3];
        }
#pragma unroll
        for (int mt = 0; mt < 2; mt++)
#pragma unroll
            for (int nt = 0; nt < 8; nt++) {
                float* c = acc[mt * 8 + nt];
                mma16816(c, ah[mt], bh[nt]);
                mma16816(c, al[mt], bh[nt]);
                mma16816(c, ah[mt], bl[nt]);
            }
    }

    // Epilogue: bn + residual + relu, write out [b][o][tp].
    const int b   = (int)(P0 / THW);
    const int tp0 = (int)(P0 % THW);
    const int g = lane >> 2, tq = lane & 3;
#pragma unroll
    for (int mt = 0; mt < 2; mt++) {
        const int pl = wm * 32 + mt * 16 + g;
        const int tp = tp0 + pl;
#pragma unroll
        for (int nt = 0; nt < 8; nt++) {
            const float* c = acc[mt * 8 + nt];
            const int ol = wn * 64 + nt * 8 + 2 * tq;
            const float2 s0 = scb[ol];
            const float2 s1 = scb[ol + 1];
            const size_t base0 = ((size_t)b * Cc + (o0 + ol)) * THW + tp;
            const size_t base1 = base0 + THW;
            float r0 = fmaxf(c[0] * s0.x + s0.y + x[base0],     0.f);
            float r1 = fmaxf(c[1] * s1.x + s1.y + x[base1],     0.f);
            float r2 = fmaxf(c[2] * s0.x + s0.y + x[base0 + 8], 0.f);
            float r3 = fmaxf(c[3] * s1.x + s1.y + x[base1 + 8], 0.f);
            out[base0]     = r0;
            out[base1]     = r1;
            out[base0 + 8] = r2;
            out[base1 + 8] = r3;
        }
    }
}

// ---------------------------------------------------------------------------
extern "C" void kernel_launch(void* const* d_in, const int* in_sizes, int n_in,
                              void* d_out, int out_size) {
    const float* x         = (const float*)d_in[0];
    const float* enc_w     = (const float*)d_in[1];
    const float* enc_gamma = (const float*)d_in[2];
    const float* enc_beta  = (const float*)d_in[3];
    const float* enc_mean  = (const float*)d_in[4];
    const float* enc_var   = (const float*)d_in[5];
    const float* fw        = (const float*)d_in[6];
    const float* dec_w     = (const float*)d_in[7];
    const float* dec_gamma = (const float*)d_in[8];
    const float* dec_beta  = (const float*)d_in[9];
    const float* dec_mean  = (const float*)d_in[10];
    const float* dec_var   = (const float*)d_in[11];
    float* out = (float*)d_out;

    cudaFuncSetAttribute(k_dec, cudaFuncAttributeMaxDynamicSharedMemorySize, SMEM_DEC);

    k_prep<<<KPAD, Cc>>>(dec_w);
    k_encode<<<dim3(THW / 128, Bsz), 256>>>(x, enc_w, enc_gamma, enc_beta, enc_mean, enc_var);
    k_corr<<<NPOS / 8, 256>>>(fw);
    k_dec<<<dim3(NPOS / 128, Cc / 128), 256, SMEM_DEC>>>(x, dec_gamma, dec_beta,
                                                         dec_mean, dec_var, out);
}

// round 6
// speedup vs baseline: 2.3103x; 1.7908x over previous
#include <cuda_runtime.h>
#include <cuda_bf16.h>
#include <cstdint>

// Problem constants
#define Bsz 4
#define Cc 256
#define CE 64
#define Tt 16
#define Hh 56
#define Ww 56
#define HW (Hh*Ww)            // 3136
#define THW (Tt*HW)           // 50176
#define NPOS (Bsz*THW)        // 200704
#define KK 49
#define K2G 196
#define KPAD 208              // 13 * 16
#define NKS 13
#define EPS 1e-5f

// Scratch (allocation-free rule: __device__ globals; zero-initialized at load,
// and rows >= 196 of g_corrh/l are never written -> stay zero, giving K padding)
__device__ float g_xenc[(size_t)Bsz * CE * THW];            // [b][ce][t][h][w]
__device__ __nv_bfloat16 g_corrh[(size_t)KPAD * NPOS];      // corr hi [k][pos]
__device__ __nv_bfloat16 g_corrl[(size_t)KPAD * NPOS];      // corr lo [k][pos]
__device__ __nv_bfloat16 g_dwh[Cc * KPAD];                  // dec_w hi [o][208]
__device__ __nv_bfloat16 g_dwl[Cc * KPAD];                  // dec_w lo [o][208]

__device__ __forceinline__ uint32_t smem_u32(const void* p) {
    uint32_t a;
    asm("{ .reg .u64 t; cvta.to.shared.u64 t, %1; cvt.u32.u64 %0, t; }"
        : "=r"(a) : "l"(p));
    return a;
}
__device__ __forceinline__ void cpasync16(uint32_t saddr, const void* g) {
    asm volatile("cp.async.cg.shared.global [%0], [%1], 16;"
                 :: "r"(saddr), "l"(g) : "memory");
}

// ---------------------------------------------------------------------------
// Kernel 0: split dec_w [o][196] fp32 -> g_dwh/g_dwl [o][208] bf16 (zero-pad)
// ---------------------------------------------------------------------------
__global__ void k_prep(const float* __restrict__ dw) {
    int k = blockIdx.x;      // 0..207
    int o = threadIdx.x;     // 0..255
    float v = (k < K2G) ? dw[o * K2G + k] : 0.f;
    __nv_bfloat16 h = __float2bfloat16(v);
    float r = v - __bfloat162float(h);
    g_dwh[o * KPAD + k] = h;
    g_dwl[o * KPAD + k] = __float2bfloat16(r);
}

// ---------------------------------------------------------------------------
// Kernel 1: encode — x_enc[b][ce][p] = relu(bn(sum_c x[b,c,p] * enc_w[ce,c]))
// 128 p x 64 ce tile. px (tid&15) -> p quads, py (tid>>4) -> ce quads.
// ---------------------------------------------------------------------------
__global__ void k_encode(const float* __restrict__ x, const float* __restrict__ w,
                         const float* __restrict__ gamma, const float* __restrict__ beta,
                         const float* __restrict__ mean, const float* __restrict__ var) {
    __shared__ __align__(16) float As[16][132];  // [c][p]
    __shared__ __align__(16) float Bs[16][68];   // [c][ce]
    const int b  = blockIdx.y;
    const int p0 = blockIdx.x * 128;
    const float* xb = x + (size_t)b * Cc * THW;
    const int tid = threadIdx.x;
    const int px = tid & 15;   // p quads
    const int py = tid >> 4;   // ce quads

    float acc[8][4];
#pragma unroll
    for (int i = 0; i < 8; i++)
#pragma unroll
        for (int j = 0; j < 4; j++) acc[i][j] = 0.f;

    for (int k0 = 0; k0 < Cc; k0 += 16) {
        {
            const int row = tid >> 5;
            const int col = (tid & 31) * 4;
#pragma unroll
            for (int r = 0; r < 16; r += 8) {
                float4 v = *reinterpret_cast<const float4*>(
                    xb + (size_t)(k0 + row + r) * THW + p0 + col);
                *reinterpret_cast<float4*>(&As[row + r][col]) = v;
            }
        }
        {
            const int ce = tid >> 2;
            const int cl = (tid & 3) * 4;
            float4 v = *reinterpret_cast<const float4*>(w + ce * Cc + k0 + cl);
            Bs[cl + 0][ce] = v.x; Bs[cl + 1][ce] = v.y;
            Bs[cl + 2][ce] = v.z; Bs[cl + 3][ce] = v.w;
        }
        __syncthreads();
#pragma unroll
        for (int k = 0; k < 16; k++) {
            float4 A0 = *reinterpret_cast<const float4*>(&As[k][px * 4]);
            float4 A1 = *reinterpret_cast<const float4*>(&As[k][64 + px * 4]);
            float4 B0 = *reinterpret_cast<const float4*>(&Bs[k][py * 4]);
            float a[8] = {A0.x, A0.y, A0.z, A0.w, A1.x, A1.y, A1.z, A1.w};
            float bb[4] = {B0.x, B0.y, B0.z, B0.w};
#pragma unroll
            for (int i = 0; i < 8; i++)
#pragma unroll
                for (int j = 0; j < 4; j++) acc[i][j] += a[i] * bb[j];
        }
        __syncthreads();
    }

    float sc[4], bi[4];
#pragma unroll
    for (int j = 0; j < 4; j++) {
        int ce = py * 4 + j;
        sc[j] = gamma[ce] * rsqrtf(var[ce] + EPS);
        bi[j] = beta[ce] - mean[ce] * sc[j];
    }
    // write spatial-major: rows = ce, contiguous p
#pragma unroll
    for (int hi = 0; hi < 2; hi++) {
#pragma unroll
        for (int j = 0; j < 4; j++) {
            int ce = py * 4 + j;
            float4 r;
            r.x = fmaxf(acc[hi * 4 + 0][j] * sc[j] + bi[j], 0.f);
            r.y = fmaxf(acc[hi * 4 + 1][j] * sc[j] + bi[j], 0.f);
            r.z = fmaxf(acc[hi * 4 + 2][j] * sc[j] + bi[j], 0.f);
            r.w = fmaxf(acc[hi * 4 + 3][j] * sc[j] + bi[j], 0.f);
            *reinterpret_cast<float4*>(
                &g_xenc[((size_t)b * CE + ce) * THW + p0 + hi * 64 + px * 4]) = r;
        }
    }
}

// ---------------------------------------------------------------------------
// Kernel 2: correlation — block = (b,t,4 h-rows x 56 w), thread = one position.
// Per channel-pair: stage 10x64 x2 window in smem, accumulate 49 offsets in regs.
// Output k-major bf16 hi/lo: g_corr[(ko*4+g)*NPOS + pos] (coalesced stores).
// ---------------------------------------------------------------------------
__global__ void __launch_bounds__(224) k_corr(const float* __restrict__ fw) {
    __shared__ __align__(16) float2 fws2[32 * KK];   // [cpair][ko]
    __shared__ __align__(16) float2 buf[10][64];     // x2 window, 2 channels
    const int tid = threadIdx.x;
    const int bx = blockIdx.x;
    const int h0 = (bx % 14) * 4;
    const int t  = (bx / 14) % Tt;
    const int b  = bx / (14 * Tt);
    const int hr = tid / Ww;
    const int w  = tid % Ww;
    const int t1 = (t == 0) ? 0 : t - 1;

    for (int idx = tid; idx < 32 * KK; idx += 224) {
        int cp = idx / KK, ko = idx % KK;
        int c = cp * 2;
        fws2[idx] = make_float2(fw[(c * Tt + t) * KK + ko],
                                fw[((c + 1) * Tt + t) * KK + ko]);
    }

    const size_t posg = ((size_t)(b * Tt + t) * Hh + h0 + hr) * Ww + w;
    const float* x1base = g_xenc + (size_t)b * CE * THW + (size_t)t1 * HW
                        + (h0 + hr) * Ww + w;
    const float* x2base = g_xenc + (size_t)b * CE * THW + (size_t)t * HW;

    float acc[KK];
#pragma unroll
    for (int i = 0; i < KK; i++) acc[i] = 0.f;

#pragma unroll 1
    for (int g4 = 0; g4 < 4; g4++) {
#pragma unroll 1
        for (int cp = 0; cp < 8; cp++) {
            const int c = g4 * 16 + cp * 2;
            __syncthreads();               // protect buf from previous readers
            for (int idx = tid; idx < 640; idx += 224) {
                int j = idx >> 6, m = idx & 63;
                int gh = h0 + j - 3, gx = m - 3;
                float2 v = make_float2(0.f, 0.f);
                if ((unsigned)gh < (unsigned)Hh && (unsigned)gx < (unsigned)Ww) {
                    size_t o = (size_t)c * THW + gh * Ww + gx;
                    v.x = x2base[o];
                    v.y = x2base[o + THW];
                }
                buf[j][m] = v;
            }
            float2 xv;
            xv.x = x1base[(size_t)c * THW];
            xv.y = x1base[(size_t)(c + 1) * THW];
            __syncthreads();
            const float2* fp = &fws2[(c >> 1) * KK];
#pragma unroll
            for (int ky = 0; ky < 7; ky++) {
#pragma unroll
                for (int kx = 0; kx < 7; kx++) {
                    const int ko = ky * 7 + kx;
                    float2 f = fp[ko];
                    float2 v = buf[hr + ky][w + kx];
                    acc[ko] += f.x * xv.x * v.x + f.y * xv.y * v.y;
                }
            }
        }
        // flush group g4 (mean over 16 channels)
#pragma unroll
        for (int ko = 0; ko < KK; ko++) {
            float v = acc[ko] * 0.0625f;
            __nv_bfloat16 h = __float2bfloat16(v);
            __nv_bfloat16 l = __float2bfloat16(v - __bfloat162float(h));
            size_t row = (size_t)(ko * 4 + g4) * NPOS + posg;
            g_corrh[row] = h;
            g_corrl[row] = l;
            acc[ko] = 0.f;
        }
    }
}

// ---------------------------------------------------------------------------
// Kernel 3: decode via mma.sync bf16 hi/lo split. 512 threads, 16 warps.
// CTA 128p x 128o, full K=208 resident, cp.async staging.
// A from k-major corr via ldmatrix.trans; B from [o][k] via plain ldmatrix.
// ---------------------------------------------------------------------------
#define APITCH 272                     // bytes per k-row (128 pos * 2B + 16 pad)
#define ATILE (KPAD * APITCH)          // 56576
#define BPITCH 432                     // bytes per o-row (208*2 + 16 pad)
#define BTILE (128 * BPITCH)           // 55296
#define SA_H 0
#define SA_L ATILE
#define SB_H (2 * ATILE)
#define SB_L (2 * ATILE + BTILE)
#define SM_SCB (2 * ATILE + 2 * BTILE) // 223744
#define SMEM_DEC (SM_SCB + 1024)       // 224768

__device__ __forceinline__ void ldmat4(uint32_t* d, uint32_t addr) {
    asm volatile("ldmatrix.sync.aligned.m8n8.x4.shared.b16 {%0,%1,%2,%3}, [%4];"
                 : "=r"(d[0]), "=r"(d[1]), "=r"(d[2]), "=r"(d[3]) : "r"(addr));
}
__device__ __forceinline__ void ldmat4t(uint32_t* d, uint32_t addr) {
    asm volatile("ldmatrix.sync.aligned.m8n8.x4.trans.shared.b16 {%0,%1,%2,%3}, [%4];"
                 : "=r"(d[0]), "=r"(d[1]), "=r"(d[2]), "=r"(d[3]) : "r"(addr));
}
__device__ __forceinline__ void mma16816(float* c, const uint32_t* a, const uint32_t* b) {
    asm volatile(
        "mma.sync.aligned.m16n8k16.row.col.f32.bf16.bf16.f32 "
        "{%0,%1,%2,%3}, {%4,%5,%6,%7}, {%8,%9}, {%0,%1,%2,%3};"
        : "+f"(c[0]), "+f"(c[1]), "+f"(c[2]), "+f"(c[3])
        : "r"(a[0]), "r"(a[1]), "r"(a[2]), "r"(a[3]), "r"(b[0]), "r"(b[1]));
}

__global__ void __launch_bounds__(512, 1) k_dec(
    const float* __restrict__ x,
    const float* __restrict__ gamma, const float* __restrict__ beta,
    const float* __restrict__ mean, const float* __restrict__ var,
    float* __restrict__ out) {
    extern __shared__ __align__(16) char sm[];
    const uint32_t sb = smem_u32(sm);
    float2* scb = reinterpret_cast<float2*>(sm + SM_SCB);
    const int tid  = threadIdx.x;
    const int wid  = tid >> 5;
    const int lane = tid & 31;
    const size_t P0 = (size_t)blockIdx.x * 128;
    const int o0 = blockIdx.y * 128;
    const int wm = wid & 3;            // p: 4 x 32
    const int wn = wid >> 2;           // o: 4 x 32

    // Stage A (k-major corr): 208 rows x 16 uint4 per tile, via cp.async.
    for (int i = tid; i < KPAD * 16; i += 512) {
        int r = i >> 4, c = i & 15;
        uint32_t d = r * APITCH + c * 16;
        size_t go = ((size_t)r * NPOS + P0) * 2 + c * 16;
        cpasync16(sb + SA_H + d, (const char*)g_corrh + go);
        cpasync16(sb + SA_L + d, (const char*)g_corrl + go);
    }
    // Stage B (weights [o][k]): 128 rows x 26 uint4 per tile.
    for (int i = tid; i < 128 * 26; i += 512) {
        int r = i / 26, c = i % 26;
        uint32_t d = r * BPITCH + c * 16;
        size_t go = ((size_t)(o0 + r) * KPAD) * 2 + c * 16;
        cpasync16(sb + SB_H + d, (const char*)g_dwh + go);
        cpasync16(sb + SB_L + d, (const char*)g_dwl + go);
    }
    asm volatile("cp.async.commit_group;" ::: "memory");
    if (tid < 128) {
        int o = o0 + tid;
        float s = gamma[o] * rsqrtf(var[o] + EPS);
        scb[tid] = make_float2(s, beta[o] - mean[o] * s);
    }
    asm volatile("cp.async.wait_group 0;" ::: "memory");
    __syncthreads();

    float acc[2][4][4];
#pragma unroll
    for (int i = 0; i < 2; i++)
#pragma unroll
        for (int j = 0; j < 4; j++)
#pragma unroll
            for (int q = 0; q < 4; q++) acc[i][j][q] = 0.f;

    // A (trans) lane mapping: k row + m offset
    const uint32_t a_kr = (lane & 7) + ((lane >> 4) << 3);
    const uint32_t a_mr = ((lane >> 3) & 1) << 3;
    // B lane mapping (plain)
    const uint32_t b_row0 = wn * 32 + ((lane >> 4) << 3) + (lane & 7);
    const uint32_t b_colb = (((lane >> 3) & 1) << 4);

#pragma unroll 1
    for (int ks = 0; ks < NKS; ks++) {
        uint32_t ah[2][4], al[2][4];
#pragma unroll
        for (int mt = 0; mt < 2; mt++) {
            uint32_t ad = sb + SA_H + (ks * 16 + a_kr) * APITCH
                        + (wm * 32 + mt * 16 + a_mr) * 2;
            ldmat4t(ah[mt], ad);
            ldmat4t(al[mt], ad + ATILE);
        }
        uint32_t bh[4][2], bl[4][2];
#pragma unroll
        for (int np = 0; np < 2; np++) {
            uint32_t bd = sb + SB_H + (b_row0 + np * 16) * BPITCH + ks * 32 + b_colb;
            uint32_t r[4];
            ldmat4(r, bd);
            bh[2 * np][0] = r[0]; bh[2 * np][1] = r[1];
            bh[2 * np + 1][0] = r[2]; bh[2 * np + 1][1] = r[3];
            ldmat4(r, bd + BTILE);
            bl[2 * np][0] = r[0]; bl[2 * np][1] = r[1];
            bl[2 * np + 1][0] = r[2]; bl[2 * np + 1][1] = r[3];
        }
#pragma unroll
        for (int mt = 0; mt < 2; mt++)
#pragma unroll
            for (int nt = 0; nt < 4; nt++) {
                float* c = acc[mt][nt];
                mma16816(c, ah[mt], bh[nt]);
                mma16816(c, al[mt], bh[nt]);
                mma16816(c, ah[mt], bl[nt]);
            }
    }

    // Epilogue: bn + residual + relu, out[b][o][tp].
    const int b   = (int)(P0 / THW);
    const int tp0 = (int)(P0 % THW);
    const int g = lane >> 2, tq = lane & 3;
#pragma unroll
    for (int mt = 0; mt < 2; mt++) {
        const int pl = wm * 32 + mt * 16 + g;
        const int tp = tp0 + pl;
#pragma unroll
        for (int nt = 0; nt < 4; nt++) {
            const float* c = acc[mt][nt];
            const int ol = wn * 32 + nt * 8 + 2 * tq;
            const float2 s0 = scb[ol];
            const float2 s1 = scb[ol + 1];
            const size_t base0 = ((size_t)b * Cc + (o0 + ol)) * THW + tp;
            const size_t base1 = base0 + THW;
            float r0 = fmaxf(c[0] * s0.x + s0.y + x[base0],     0.f);
            float r1 = fmaxf(c[1] * s1.x + s1.y + x[base1],     0.f);
            float r2 = fmaxf(c[2] * s0.x + s0.y + x[base0 + 8], 0.f);
            float r3 = fmaxf(c[3] * s1.x + s1.y + x[base1 + 8], 0.f);
            out[base0]     = r0;
            out[base1]     = r1;
            out[base0 + 8] = r2;
            out[base1 + 8] = r3;
        }
    }
}

// ---------------------------------------------------------------------------
extern "C" void kernel_launch(void* const* d_in, const int* in_sizes, int n_in,
                              void* d_out, int out_size) {
    const float* x         = (const float*)d_in[0];
    const float* enc_w     = (const float*)d_in[1];
    const float* enc_gamma = (const float*)d_in[2];
    const float* enc_beta  = (const float*)d_in[3];
    const float* enc_mean  = (const float*)d_in[4];
    const float* enc_var   = (const float*)d_in[5];
    const float* fw        = (const float*)d_in[6];
    const float* dec_w     = (const float*)d_in[7];
    const float* dec_gamma = (const float*)d_in[8];
    const float* dec_beta  = (const float*)d_in[9];
    const float* dec_mean  = (const float*)d_in[10];
    const float* dec_var   = (const float*)d_in[11];
    float* out = (float*)d_out;

    cudaFuncSetAttribute(k_dec, cudaFuncAttributeMaxDynamicSharedMemorySize, SMEM_DEC);

    k_prep<<<KPAD, Cc>>>(dec_w);
    k_encode<<<dim3(THW / 128, Bsz), 256>>>(x, enc_w, enc_gamma, enc_beta, enc_mean, enc_var);
    k_corr<<<Bsz * Tt * (Hh / 4), 224>>>(fw);
    k_dec<<<dim3(NPOS / 128, Cc / 128), 512, SMEM_DEC>>>(x, dec_gamma, dec_beta,
                                                         dec_mean, dec_var, out);
}

// round 7
// speedup vs baseline: 2.3321x; 1.0094x over previous
#include <cuda_runtime.h>
#include <cuda_bf16.h>
#include <cstdint>

// Problem constants
#define Bsz 4
#define Cc 256
#define CE 64
#define Tt 16
#define Hh 56
#define Ww 56
#define HW (Hh*Ww)            // 3136
#define THW (Tt*HW)           // 50176
#define NPOS (Bsz*THW)        // 200704
#define KK 49
#define K2G 196
#define KPAD 208              // 13 * 16
#define NKS 13
#define EPS 1e-5f

// Scratch. Zero-initialized at load; g_corr rows >= 196 never written -> K pad.
__device__ float g_xenc[(size_t)Bsz * 32 * THW * 2];       // [b][cpair][p][2]
__device__ __nv_bfloat16 g_corrh[(size_t)KPAD * NPOS];     // corr hi [k][pos]
__device__ __nv_bfloat16 g_corrl[(size_t)KPAD * NPOS];     // corr lo [k][pos]
__device__ __nv_bfloat16 g_dwh[Cc * KPAD];                 // dec_w hi [o][208]
__device__ __nv_bfloat16 g_dwl[Cc * KPAD];                 // dec_w lo [o][208]

__device__ __forceinline__ uint32_t smem_u32(const void* p) {
    uint32_t a;
    asm("{ .reg .u64 t; cvta.to.shared.u64 t, %1; cvt.u32.u64 %0, t; }"
        : "=r"(a) : "l"(p));
    return a;
}
__device__ __forceinline__ void cpasync16(uint32_t saddr, const void* g) {
    asm volatile("cp.async.cg.shared.global [%0], [%1], 16;"
                 :: "r"(saddr), "l"(g) : "memory");
}

// ---------------------------------------------------------------------------
// Kernel 0: split dec_w [o][196] fp32 -> g_dwh/g_dwl [o][208] bf16 (zero-pad)
// ---------------------------------------------------------------------------
__global__ void k_prep(const float* __restrict__ dw) {
    int k = blockIdx.x;      // 0..207
    int o = threadIdx.x;     // 0..255
    float v = (k < K2G) ? dw[o * K2G + k] : 0.f;
    __nv_bfloat16 h = __float2bfloat16(v);
    float r = v - __bfloat162float(h);
    g_dwh[o * KPAD + k] = h;
    g_dwl[o * KPAD + k] = __float2bfloat16(r);
}

// ---------------------------------------------------------------------------
// Kernel 1: encode -> pair-interleaved layout [b][cpair][p][2]
// ---------------------------------------------------------------------------
__global__ void k_encode(const float* __restrict__ x, const float* __restrict__ w,
                         const float* __restrict__ gamma, const float* __restrict__ beta,
                         const float* __restrict__ mean, const float* __restrict__ var) {
    __shared__ __align__(16) float As[16][132];  // [c][p]
    __shared__ __align__(16) float Bs[16][68];   // [c][ce]
    const int b  = blockIdx.y;
    const int p0 = blockIdx.x * 128;
    const float* xb = x + (size_t)b * Cc * THW;
    const int tid = threadIdx.x;
    const int px = tid & 15;   // p quads
    const int py = tid >> 4;   // ce quads

    float acc[8][4];
#pragma unroll
    for (int i = 0; i < 8; i++)
#pragma unroll
        for (int j = 0; j < 4; j++) acc[i][j] = 0.f;

    for (int k0 = 0; k0 < Cc; k0 += 16) {
        {
            const int row = tid >> 5;
            const int col = (tid & 31) * 4;
#pragma unroll
            for (int r = 0; r < 16; r += 8) {
                float4 v = *reinterpret_cast<const float4*>(
                    xb + (size_t)(k0 + row + r) * THW + p0 + col);
                *reinterpret_cast<float4*>(&As[row + r][col]) = v;
            }
        }
        {
            const int ce = tid >> 2;
            const int cl = (tid & 3) * 4;
            float4 v = *reinterpret_cast<const float4*>(w + ce * Cc + k0 + cl);
            Bs[cl + 0][ce] = v.x; Bs[cl + 1][ce] = v.y;
            Bs[cl + 2][ce] = v.z; Bs[cl + 3][ce] = v.w;
        }
        __syncthreads();
#pragma unroll
        for (int k = 0; k < 16; k++) {
            float4 A0 = *reinterpret_cast<const float4*>(&As[k][px * 4]);
            float4 A1 = *reinterpret_cast<const float4*>(&As[k][64 + px * 4]);
            float4 B0 = *reinterpret_cast<const float4*>(&Bs[k][py * 4]);
            float a[8] = {A0.x, A0.y, A0.z, A0.w, A1.x, A1.y, A1.z, A1.w};
            float bb[4] = {B0.x, B0.y, B0.z, B0.w};
#pragma unroll
            for (int i = 0; i < 8; i++)
#pragma unroll
                for (int j = 0; j < 4; j++) acc[i][j] += a[i] * bb[j];
        }
        __syncthreads();
    }

    float sc[4], bi[4];
#pragma unroll
    for (int j = 0; j < 4; j++) {
        int ce = py * 4 + j;
        sc[j] = gamma[ce] * rsqrtf(var[ce] + EPS);
        bi[j] = beta[ce] - mean[ce] * sc[j];
    }
    // store pair-interleaved: (b,cpair,p,parity)
#pragma unroll
    for (int hi = 0; hi < 2; hi++) {
#pragma unroll
        for (int m = 0; m < 2; m++) {
            const int cp = py * 2 + m;
#pragma unroll
            for (int ii = 0; ii < 4; ii += 2) {
                const int i = hi * 4 + ii;
                const int p = p0 + hi * 64 + px * 4 + ii;
                float4 r;
                r.x = fmaxf(acc[i][2 * m]     * sc[2 * m]     + bi[2 * m],     0.f);
                r.y = fmaxf(acc[i][2 * m + 1] * sc[2 * m + 1] + bi[2 * m + 1], 0.f);
                r.z = fmaxf(acc[i + 1][2 * m]     * sc[2 * m]     + bi[2 * m],     0.f);
                r.w = fmaxf(acc[i + 1][2 * m + 1] * sc[2 * m + 1] + bi[2 * m + 1], 0.f);
                *reinterpret_cast<float4*>(
                    &g_xenc[(((size_t)b * 32 + cp) * THW + p) * 2]) = r;
            }
        }
    }
}

// ---------------------------------------------------------------------------
// Kernel 2: correlation — block = (b,t,4 h-rows x 56 w), 224 threads.
// 32 stages of 2 channels; double-buffered smem window + LDG prefetch.
// ---------------------------------------------------------------------------
__global__ void __launch_bounds__(224) k_corr(const float* __restrict__ fw) {
    __shared__ __align__(16) float2 fws2[32 * KK];     // [cpair][ko]
    __shared__ __align__(16) float2 buf[2][10][64];    // double-buffered window
    const int tid = threadIdx.x;
    const int bx = blockIdx.x;
    const int h0 = (bx % 14) * 4;
    const int t  = (bx / 14) % Tt;
    const int b  = bx / (14 * Tt);
    const int hr = tid / Ww;
    const int w  = tid % Ww;
    const int t1 = (t == 0) ? 0 : t - 1;

    for (int idx = tid; idx < 32 * KK; idx += 224) {
        int cp = idx / KK, ko = idx % KK;
        int c = cp * 2;
        fws2[idx] = make_float2(fw[(c * Tt + t) * KK + ko],
                                fw[((c + 1) * Tt + t) * KK + ko]);
    }

    const float2* xe = reinterpret_cast<const float2*>(g_xenc);
    const size_t cstride = THW;                       // float2 units per cpair
    const size_t cb0 = (size_t)(b * 32) * cstride;    // cpair 0 of this batch

    // staging entry geometry (3 entries per thread, 640 total)
    int je[3], me[3];
    bool in[3];
    size_t off[3];
#pragma unroll
    for (int e = 0; e < 3; e++) {
        int idx = tid + 224 * e;
        int j = idx >> 6, m = idx & 63;
        je[e] = j; me[e] = m;
        int gh = h0 + j - 3, gx = m - 3;
        in[e] = (idx < 640) && (unsigned)gh < (unsigned)Hh && (unsigned)gx < (unsigned)Ww;
        off[e] = (size_t)t * HW + (size_t)gh * Ww + gx;
    }
    const size_t x1off = (size_t)t1 * HW + (size_t)(h0 + hr) * Ww + w;
    const size_t posg  = ((size_t)(b * Tt + t) * Hh + h0 + hr) * Ww + w;

    float acc[KK];
#pragma unroll
    for (int i = 0; i < KK; i++) acc[i] = 0.f;

    // prologue: stage 0
    float2 pf[3], x1c, x1n;
#pragma unroll
    for (int e = 0; e < 3; e++)
        pf[e] = in[e] ? xe[cb0 + off[e]] : make_float2(0.f, 0.f);
    x1c = xe[cb0 + x1off];
#pragma unroll
    for (int e = 0; e < 3; e++)
        if (tid + 224 * e < 640) buf[0][je[e]][me[e]] = pf[e];
    __syncthreads();

#pragma unroll 1
    for (int s = 0; s < 32; s++) {
        const size_t cbn = cb0 + (size_t)(s + 1) * cstride;
        if (s < 31) {
#pragma unroll
            for (int e = 0; e < 3; e++)
                pf[e] = in[e] ? xe[cbn + off[e]] : make_float2(0.f, 0.f);
            x1n = xe[cbn + x1off];
        }
        const float2* fp = &fws2[s * KK];
#pragma unroll
        for (int ky = 0; ky < 7; ky++) {
#pragma unroll
            for (int kx = 0; kx < 7; kx++) {
                const int ko = ky * 7 + kx;
                float2 f = fp[ko];
                float2 v = buf[s & 1][hr + ky][w + kx];
                acc[ko] += f.x * x1c.x * v.x + f.y * x1c.y * v.y;
            }
        }
        if ((s & 7) == 7) {   // flush 16-channel group
            const int g4 = s >> 3;
#pragma unroll
            for (int ko = 0; ko < KK; ko++) {
                float v = acc[ko] * 0.0625f;
                __nv_bfloat16 h = __float2bfloat16(v);
                __nv_bfloat16 l = __float2bfloat16(v - __bfloat162float(h));
                size_t row = (size_t)(ko * 4 + g4) * NPOS + posg;
                g_corrh[row] = h;
                g_corrl[row] = l;
                acc[ko] = 0.f;
            }
        }
        __syncthreads();       // all reads of buf[(s+1)&1] (stage s-1) done
        if (s < 31) {
#pragma unroll
            for (int e = 0; e < 3; e++)
                if (tid + 224 * e < 640) buf[(s + 1) & 1][je[e]][me[e]] = pf[e];
            x1c = x1n;
        }
        __syncthreads();
    }
}

// ---------------------------------------------------------------------------
// Kernel 3: decode — CTA 128p x 256o (full C), K pipelined in 13 chunks of 16,
// double-buffered cp.async. 512 threads, warp tile 32p x 64o. bf16 hi/lo MMA.
// ---------------------------------------------------------------------------
#define ACH 16
#define APITCH2 272
#define ASTG (ACH * APITCH2)          // 4352
#define BPITCH2 48
#define BSTG (256 * BPITCH2)          // 12288
#define OFF_A 0
#define OFF_B (4 * ASTG)              // 17408
#define SM_SCB2 (4 * ASTG + 4 * BSTG) // 66560
#define SMEM_DEC (SM_SCB2 + 2048)     // 68608
#define DAHL (2 * ASTG)               // A hi->lo offset
#define DBHL (2 * BSTG)               // B hi->lo offset

__device__ __forceinline__ void ldmat4(uint32_t* d, uint32_t addr) {
    asm volatile("ldmatrix.sync.aligned.m8n8.x4.shared.b16 {%0,%1,%2,%3}, [%4];"
                 : "=r"(d[0]), "=r"(d[1]), "=r"(d[2]), "=r"(d[3]) : "r"(addr));
}
__device__ __forceinline__ void ldmat4t(uint32_t* d, uint32_t addr) {
    asm volatile("ldmatrix.sync.aligned.m8n8.x4.trans.shared.b16 {%0,%1,%2,%3}, [%4];"
                 : "=r"(d[0]), "=r"(d[1]), "=r"(d[2]), "=r"(d[3]) : "r"(addr));
}
__device__ __forceinline__ void mma16816(float* c, const uint32_t* a, const uint32_t* b) {
    asm volatile(
        "mma.sync.aligned.m16n8k16.row.col.f32.bf16.bf16.f32 "
        "{%0,%1,%2,%3}, {%4,%5,%6,%7}, {%8,%9}, {%0,%1,%2,%3};"
        : "+f"(c[0]), "+f"(c[1]), "+f"(c[2]), "+f"(c[3])
        : "r"(a[0]), "r"(a[1]), "r"(a[2]), "r"(a[3]), "r"(b[0]), "r"(b[1]));
}

__global__ void __launch_bounds__(512, 1) k_dec(
    const float* __restrict__ x,
    const float* __restrict__ gamma, const float* __restrict__ beta,
    const float* __restrict__ mean, const float* __restrict__ var,
    float* __restrict__ out) {
    extern __shared__ __align__(16) char sm[];
    const uint32_t sb = smem_u32(sm);
    float2* scb = reinterpret_cast<float2*>(sm + SM_SCB2);
    const int tid  = threadIdx.x;
    const int wid  = tid >> 5;
    const int lane = tid & 31;
    const size_t P0 = (size_t)blockIdx.x * 128;
    const int wm = wid & 3;            // p: 4 x 32
    const int wn = wid >> 2;           // o: 4 x 64

    // chunk loader: A 16k x 128p (hi/lo), B 256o x 16k (hi/lo)
    auto load_chunk = [&](int ks, int st) {
        if (tid < 256) {
            int r = tid >> 4, c = tid & 15;
            uint32_t d = sb + OFF_A + st * ASTG + r * APITCH2 + c * 16;
            size_t go = ((size_t)(ks * 16 + r) * NPOS + P0) * 2 + c * 16;
            cpasync16(d,        (const char*)g_corrh + go);
            cpasync16(d + DAHL, (const char*)g_corrl + go);
        }
        {
            int r = tid >> 1, c = tid & 1;
            uint32_t d = sb + OFF_B + st * BSTG + r * BPITCH2 + c * 16;
            size_t go = (size_t)r * (KPAD * 2) + ks * 32 + c * 16;
            cpasync16(d,        (const char*)g_dwh + go);
            cpasync16(d + DBHL, (const char*)g_dwl + go);
        }
        asm volatile("cp.async.commit_group;" ::: "memory");
    };

    load_chunk(0, 0);
    load_chunk(1, 1);
    if (tid < 256) {
        float s = gamma[tid] * rsqrtf(var[tid] + EPS);
        scb[tid] = make_float2(s, beta[tid] - mean[tid] * s);
    }

    float acc[2][8][4];
#pragma unroll
    for (int i = 0; i < 2; i++)
#pragma unroll
        for (int j = 0; j < 8; j++)
#pragma unroll
            for (int q = 0; q < 4; q++) acc[i][j][q] = 0.f;

    const uint32_t a_kr = (lane & 7) + ((lane >> 4) << 3);
    const uint32_t a_mrb = (wm * 32 + (((lane >> 3) & 1) << 3)) * 2;
    const uint32_t b_row0 = wn * 64 + ((lane >> 4) << 3) + (lane & 7);
    const uint32_t b_colb = (((lane >> 3) & 1) << 4);

#pragma unroll 1
    for (int ks = 0; ks < NKS; ks++) {
        if (ks == NKS - 1)
            asm volatile("cp.async.wait_group 0;" ::: "memory");
        else
            asm volatile("cp.async.wait_group 1;" ::: "memory");
        __syncthreads();
        const int st = ks & 1;
        const uint32_t sah = sb + OFF_A + st * ASTG;
        const uint32_t sbh = sb + OFF_B + st * BSTG;

        uint32_t ah[2][4], al[2][4];
#pragma unroll
        for (int mt = 0; mt < 2; mt++) {
            uint32_t ad = sah + a_kr * APITCH2 + a_mrb + mt * 32;
            ldmat4t(ah[mt], ad);
            ldmat4t(al[mt], ad + DAHL);
        }
#pragma unroll
        for (int np = 0; np < 4; np++) {
            uint32_t bd = sbh + (b_row0 + np * 16) * BPITCH2 + b_colb;
            uint32_t bh[4], bl[4];
            ldmat4(bh, bd);
            ldmat4(bl, bd + DBHL);
#pragma unroll
            for (int mt = 0; mt < 2; mt++) {
                float* c0 = acc[mt][2 * np];
                float* c1 = acc[mt][2 * np + 1];
                mma16816(c0, ah[mt], bh);
                mma16816(c0, al[mt], bh);
                mma16816(c0, ah[mt], bl);
                mma16816(c1, ah[mt], bh + 2);
                mma16816(c1, al[mt], bh + 2);
                mma16816(c1, ah[mt], bl + 2);
            }
        }
        __syncthreads();
        if (ks + 2 < NKS) load_chunk(ks + 2, st);
    }

    // Epilogue: bn + residual + relu, out[b][o][tp].
    const int b   = (int)(P0 / THW);
    const int tp0 = (int)(P0 % THW);
    const int g = lane >> 2, tq = lane & 3;
#pragma unroll
    for (int mt = 0; mt < 2; mt++) {
        const int pl = wm * 32 + mt * 16 + g;
        const int tp = tp0 + pl;
#pragma unroll
        for (int nt = 0; nt < 8; nt++) {
            const float* c = acc[mt][nt];
            const int ol = wn * 64 + nt * 8 + 2 * tq;
            const float2 s0 = scb[ol];
            const float2 s1 = scb[ol + 1];
            const size_t base0 = ((size_t)b * Cc + ol) * THW + tp;
            const size_t base1 = base0 + THW;
            float r0 = fmaxf(c[0] * s0.x + s0.y + x[base0],     0.f);
            float r1 = fmaxf(c[1] * s1.x + s1.y + x[base1],     0.f);
            float r2 = fmaxf(c[2] * s0.x + s0.y + x[base0 + 8], 0.f);
            float r3 = fmaxf(c[3] * s1.x + s1.y + x[base1 + 8], 0.f);
            out[base0]     = r0;
            out[base1]     = r1;
            out[base0 + 8] = r2;
            out[base1 + 8] = r3;
        }
    }
}

// ---------------------------------------------------------------------------
extern "C" void kernel_launch(void* const* d_in, const int* in_sizes, int n_in,
                              void* d_out, int out_size) {
    const float* x         = (const float*)d_in[0];
    const float* enc_w     = (const float*)d_in[1];
    const float* enc_gamma = (const float*)d_in[2];
    const float* enc_beta  = (const float*)d_in[3];
    const float* enc_mean  = (const float*)d_in[4];
    const float* enc_var   = (const float*)d_in[5];
    const float* fw        = (const float*)d_in[6];
    const float* dec_w     = (const float*)d_in[7];
    const float* dec_gamma = (const float*)d_in[8];
    const float* dec_beta  = (const float*)d_in[9];
    const float* dec_mean  = (const float*)d_in[10];
    const float* dec_var   = (const float*)d_in[11];
    float* out = (float*)d_out;

    cudaFuncSetAttribute(k_dec, cudaFuncAttributeMaxDynamicSharedMemorySize, SMEM_DEC);

    k_prep<<<KPAD, Cc>>>(dec_w);
    k_encode<<<dim3(THW / 128, Bsz), 256>>>(x, enc_w, enc_gamma, enc_beta, enc_mean, enc_var);
    k_corr<<<Bsz * Tt * (Hh / 4), 224>>>(fw);
    k_dec<<<NPOS / 128, 512, SMEM_DEC>>>(x, dec_gamma, dec_beta, dec_mean, dec_var, out);
}

// round 9
// speedup vs baseline: 2.5849x; 1.1084x over previous
#include <cuda_runtime.h>
#include <cuda_bf16.h>
#include <cstdint>

// Problem constants
#define Bsz 4
#define Cc 256
#define CE 64
#define Tt 16
#define Hh 56
#define Ww 56
#define HW (Hh*Ww)            // 3136
#define THW (Tt*HW)           // 50176
#define NPOS (Bsz*THW)        // 200704
#define KK 49
#define K2G 196
#define KPAD 208              // 13 * 16
#define NKS 13
#define EPS 1e-5f

// Scratch. Zero-initialized at load; g_corr rows >= 196 never written -> K pad.
__device__ float g_xenc[(size_t)Bsz * 32 * THW * 2];       // [b][cpair][p][2]
__device__ __nv_bfloat16 g_corrh[(size_t)KPAD * NPOS];     // corr hi [k][pos]
__device__ __nv_bfloat16 g_corrl[(size_t)KPAD * NPOS];     // corr lo [k][pos]
__device__ __nv_bfloat16 g_dwh[Cc * KPAD];                 // dec_w hi [o][208]
__device__ __nv_bfloat16 g_dwl[Cc * KPAD];                 // dec_w lo [o][208]
__device__ __nv_bfloat16 g_ewh[CE * Cc];                   // enc_w hi [ce][256]
__device__ __nv_bfloat16 g_ewl[CE * Cc];                   // enc_w lo [ce][256]

__device__ __forceinline__ uint32_t smem_u32(const void* p) {
    uint32_t a;
    asm("{ .reg .u64 t; cvta.to.shared.u64 t, %1; cvt.u32.u64 %0, t; }"
        : "=r"(a) : "l"(p));
    return a;
}
__device__ __forceinline__ void cpasync16(uint32_t saddr, const void* g) {
    asm volatile("cp.async.cg.shared.global [%0], [%1], 16;"
                 :: "r"(saddr), "l"(g) : "memory");
}
__device__ __forceinline__ void sts8(uint32_t saddr, uint32_t a, uint32_t b) {
    asm volatile("st.shared.v2.b32 [%0], {%1, %2};" :: "r"(saddr), "r"(a), "r"(b)
                 : "memory");
}
__device__ __forceinline__ void ldmat4(uint32_t* d, uint32_t addr) {
    asm volatile("ldmatrix.sync.aligned.m8n8.x4.shared.b16 {%0,%1,%2,%3}, [%4];"
                 : "=r"(d[0]), "=r"(d[1]), "=r"(d[2]), "=r"(d[3]) : "r"(addr));
}
__device__ __forceinline__ void ldmat4t(uint32_t* d, uint32_t addr) {
    asm volatile("ldmatrix.sync.aligned.m8n8.x4.trans.shared.b16 {%0,%1,%2,%3}, [%4];"
                 : "=r"(d[0]), "=r"(d[1]), "=r"(d[2]), "=r"(d[3]) : "r"(addr));
}
__device__ __forceinline__ void mma16816(float* c, const uint32_t* a, const uint32_t* b) {
    asm volatile(
        "mma.sync.aligned.m16n8k16.row.col.f32.bf16.bf16.f32 "
        "{%0,%1,%2,%3}, {%4,%5,%6,%7}, {%8,%9}, {%0,%1,%2,%3};"
        : "+f"(c[0]), "+f"(c[1]), "+f"(c[2]), "+f"(c[3])
        : "r"(a[0]), "r"(a[1]), "r"(a[2]), "r"(a[3]), "r"(b[0]), "r"(b[1]));
}
__device__ __forceinline__ uint32_t packhi(float a, float b, float& ra, float& rb) {
    __nv_bfloat16 ha = __float2bfloat16(a), hb = __float2bfloat16(b);
    ra = a - __bfloat162float(ha);
    rb = b - __bfloat162float(hb);
    return (uint32_t)__bfloat16_as_ushort(ha) |
           ((uint32_t)__bfloat16_as_ushort(hb) << 16);
}
__device__ __forceinline__ uint32_t packbf(float a, float b) {
    return (uint32_t)__bfloat16_as_ushort(__float2bfloat16(a)) |
           ((uint32_t)__bfloat16_as_ushort(__float2bfloat16(b)) << 16);
}

// ---------------------------------------------------------------------------
// Kernel 0a: split dec_w [o][196] -> [o][208] bf16 hi/lo (zero-pad)
// ---------------------------------------------------------------------------
__global__ void k_prep(const float* __restrict__ dw) {
    int k = blockIdx.x;
    int o = threadIdx.x;
    float v = (k < K2G) ? dw[o * K2G + k] : 0.f;
    __nv_bfloat16 h = __float2bfloat16(v);
    float r = v - __bfloat162float(h);
    g_dwh[o * KPAD + k] = h;
    g_dwl[o * KPAD + k] = __float2bfloat16(r);
}
// Kernel 0b: split enc_w [ce][256] -> bf16 hi/lo
__global__ void k_prep_enc(const float* __restrict__ ew) {
    int ce = blockIdx.x;
    int c  = threadIdx.x;
    float v = ew[ce * Cc + c];
    __nv_bfloat16 h = __float2bfloat16(v);
    g_ewh[ce * Cc + c] = h;
    g_ewl[ce * Cc + c] = __float2bfloat16(v - __bfloat162float(h));
}

// ---------------------------------------------------------------------------
// Kernel 1: encode via bf16 hi/lo HMMA. CTA 256p x 64ce, K=256 in 8 chunks of
// 32 (double-buffered register-split staging). Warp tile 32p x 32ce.
// Output pair-interleaved: g_xenc[((b*32+cp)*THW + p)*2 + parity].
// ---------------------------------------------------------------------------
#define E_PITCH 528
#define E_ATILE (32 * E_PITCH)            // 16896 (one chunk, hi or lo)
#define E_BTILE (64 * E_PITCH)            // 33792
#define E_OFFB (4 * E_ATILE)              // 67584
#define E_SCB (E_OFFB + 2 * E_BTILE)      // 135168
#define SMEM_ENC (E_SCB + 512)            // 135680

__global__ void __launch_bounds__(512, 1) k_encode(
    const float* __restrict__ x,
    const float* __restrict__ gamma, const float* __restrict__ beta,
    const float* __restrict__ mean, const float* __restrict__ var) {
    extern __shared__ __align__(16) char sm[];
    const uint32_t sb = smem_u32(sm);
    float2* scb = reinterpret_cast<float2*>(sm + E_SCB);
    const int tid  = threadIdx.x;
    const int wid  = tid >> 5;
    const int lane = tid & 31;
    const int b  = blockIdx.y;
    const int P0 = blockIdx.x * 256;
    const int wm = wid & 7;            // p: 8 x 32
    const int wn = wid >> 3;           // ce: 2 x 32

    // Stage B (enc_w hi/lo, 64 rows x 512B) via cp.async
    for (int i = tid; i < 64 * 32; i += 512) {
        int r = i >> 5, c = i & 31;
        uint32_t d = sb + E_OFFB + r * E_PITCH + c * 16;
        size_t go = (size_t)r * 512 + c * 16;
        cpasync16(d,           (const char*)g_ewh + go);
        cpasync16(d + E_BTILE, (const char*)g_ewl + go);
    }
    asm volatile("cp.async.commit_group;" ::: "memory");
    if (tid < 64) {
        float s = gamma[tid] * rsqrtf(var[tid] + EPS);
        scb[tid] = make_float2(s, beta[tid] - mean[tid] * s);
    }

    const float* xb = x + (size_t)b * Cc * THW + P0;
    // A staging geometry: idx = tid + 512*e (e<4), r = c-row 0..31, c4 = p quad
    const int st_r  = tid >> 6;             // base row
    const int st_c4 = (tid & 63) * 4;       // p offset

    // stage chunk 0 into buffer 0
#pragma unroll
    for (int e = 0; e < 4; e++) {
        int r = st_r + 8 * e;
        float4 v = *reinterpret_cast<const float4*>(xb + (size_t)r * THW + st_c4);
        float rx, ry, rz, rw;
        uint32_t h0 = packhi(v.x, v.y, rx, ry);
        uint32_t h1 = packhi(v.z, v.w, rz, rw);
        uint32_t d = sb + r * E_PITCH + st_c4 * 2;
        sts8(d, h0, h1);
        sts8(d + E_ATILE, packbf(rx, ry), packbf(rz, rw));
    }
    asm volatile("cp.async.wait_group 0;" ::: "memory");
    __syncthreads();

    float acc[2][4][4];
#pragma unroll
    for (int i = 0; i < 2; i++)
#pragma unroll
        for (int j = 0; j < 4; j++)
#pragma unroll
            for (int q = 0; q < 4; q++) acc[i][j][q] = 0.f;

    const uint32_t a_kr = (lane & 7) + ((lane >> 4) << 3);
    const uint32_t a_mr = ((lane >> 3) & 1) << 3;
    const uint32_t b_row0 = wn * 32 + ((lane >> 4) << 3) + (lane & 7);
    const uint32_t b_colb = (((lane >> 3) & 1) << 4);

#pragma unroll 1
    for (int kc = 0; kc < 8; kc++) {
        float4 v[4];
        if (kc < 7) {
            const float* xk = xb + (size_t)(kc + 1) * 32 * THW;
#pragma unroll
            for (int e = 0; e < 4; e++)
                v[e] = *reinterpret_cast<const float4*>(
                    xk + (size_t)(st_r + 8 * e) * THW + st_c4);
        }
        const uint32_t ab = sb + (kc & 1) * (2 * E_ATILE);
#pragma unroll
        for (int ks2 = 0; ks2 < 2; ks2++) {
            uint32_t ah[2][4], al[2][4];
#pragma unroll
            for (int mt = 0; mt < 2; mt++) {
                uint32_t ad = ab + (ks2 * 16 + a_kr) * E_PITCH
                            + (wm * 32 + mt * 16 + a_mr) * 2;
                ldmat4t(ah[mt], ad);
                ldmat4t(al[mt], ad + E_ATILE);
            }
#pragma unroll
            for (int np = 0; np < 2; np++) {
                uint32_t bd = sb + E_OFFB + (b_row0 + np * 16) * E_PITCH
                            + (kc * 32 + ks2 * 16) * 2 + b_colb;
                uint32_t bh[4], bl[4];
                ldmat4(bh, bd);
                ldmat4(bl, bd + E_BTILE);
#pragma unroll
                for (int mt = 0; mt < 2; mt++) {
                    float* c0 = acc[mt][2 * np];
                    float* c1 = acc[mt][2 * np + 1];
                    mma16816(c0, ah[mt], bh);
                    mma16816(c0, al[mt], bh);
                    mma16816(c0, ah[mt], bl);
                    mma16816(c1, ah[mt], bh + 2);
                    mma16816(c1, al[mt], bh + 2);
                    mma16816(c1, ah[mt], bl + 2);
                }
            }
        }
        __syncthreads();      // readers of buffer kc&1 done
        if (kc < 7) {
            const uint32_t nb = sb + ((kc + 1) & 1) * (2 * E_ATILE);
#pragma unroll
            for (int e = 0; e < 4; e++) {
                int r = st_r + 8 * e;
                float rx, ry, rz, rw;
                uint32_t h0 = packhi(v[e].x, v[e].y, rx, ry);
                uint32_t h1 = packhi(v[e].z, v[e].w, rz, rw);
                uint32_t d = nb + r * E_PITCH + st_c4 * 2;
                sts8(d, h0, h1);
                sts8(d + E_ATILE, packbf(rx, ry), packbf(rz, rw));
            }
            __syncthreads();  // writes visible before next chunk's reads
        }
    }

    // Epilogue: BN + ReLU, pair-interleaved float2 stores.
    const int g = lane >> 2, tq = lane & 3;
#pragma unroll
    for (int mt = 0; mt < 2; mt++) {
        const int p = P0 + wm * 32 + mt * 16 + g;
#pragma unroll
        for (int nt = 0; nt < 4; nt++) {
            const float* c = acc[mt][nt];
            const int ol = wn * 32 + nt * 8 + 2 * tq;
            const float2 s0 = scb[ol];
            const float2 s1 = scb[ol + 1];
            const int cp = ol >> 1;
            float* base = &g_xenc[(((size_t)b * 32 + cp) * THW + p) * 2];
            float2 v0, v1;
            v0.x = fmaxf(c[0] * s0.x + s0.y, 0.f);
            v0.y = fmaxf(c[1] * s1.x + s1.y, 0.f);
            v1.x = fmaxf(c[2] * s0.x + s0.y, 0.f);
            v1.y = fmaxf(c[3] * s1.x + s1.y, 0.f);
            *reinterpret_cast<float2*>(base)      = v0;   // row p
            *reinterpret_cast<float2*>(base + 16) = v1;   // row p+8
        }
    }
}

// ---------------------------------------------------------------------------
// Kernel 2: correlation (R7 version, ~185us)
// ---------------------------------------------------------------------------
__global__ void __launch_bounds__(224) k_corr(const float* __restrict__ fw) {
    __shared__ __align__(16) float2 fws2[32 * KK];
    __shared__ __align__(16) float2 buf[2][10][64];
    const int tid = threadIdx.x;
    const int bx = blockIdx.x;
    const int h0 = (bx % 14) * 4;
    const int t  = (bx / 14) % Tt;
    const int b  = bx / (14 * Tt);
    const int hr = tid / Ww;
    const int w  = tid % Ww;
    const int t1 = (t == 0) ? 0 : t - 1;

    for (int idx = tid; idx < 32 * KK; idx += 224) {
        int cp = idx / KK, ko = idx % KK;
        int c = cp * 2;
        fws2[idx] = make_float2(fw[(c * Tt + t) * KK + ko],
                                fw[((c + 1) * Tt + t) * KK + ko]);
    }

    const float2* xe = reinterpret_cast<const float2*>(g_xenc);
    const size_t cstride = THW;
    const size_t cb0 = (size_t)(b * 32) * cstride;

    int je[3], me[3];
    bool in[3];
    size_t off[3];
#pragma unroll
    for (int e = 0; e < 3; e++) {
        int idx = tid + 224 * e;
        int j = idx >> 6, m = idx & 63;
        je[e] = j; me[e] = m;
        int gh = h0 + j - 3, gx = m - 3;
        in[e] = (idx < 640) && (unsigned)gh < (unsigned)Hh && (unsigned)gx < (unsigned)Ww;
        off[e] = (size_t)t * HW + (size_t)gh * Ww + gx;
    }
    const size_t x1off = (size_t)t1 * HW + (size_t)(h0 + hr) * Ww + w;
    const size_t posg  = ((size_t)(b * Tt + t) * Hh + h0 + hr) * Ww + w;

    float acc[KK];
#pragma unroll
    for (int i = 0; i < KK; i++) acc[i] = 0.f;

    float2 pf[3], x1c, x1n;
#pragma unroll
    for (int e = 0; e < 3; e++)
        pf[e] = in[e] ? xe[cb0 + off[e]] : make_float2(0.f, 0.f);
    x1c = xe[cb0 + x1off];
#pragma unroll
    for (int e = 0; e < 3; e++)
        if (tid + 224 * e < 640) buf[0][je[e]][me[e]] = pf[e];
    __syncthreads();

#pragma unroll 1
    for (int s = 0; s < 32; s++) {
        const size_t cbn = cb0 + (size_t)(s + 1) * cstride;
        if (s < 31) {
#pragma unroll
            for (int e = 0; e < 3; e++)
                pf[e] = in[e] ? xe[cbn + off[e]] : make_float2(0.f, 0.f);
            x1n = xe[cbn + x1off];
        }
        const float2* fp = &fws2[s * KK];
#pragma unroll
        for (int ky = 0; ky < 7; ky++) {
#pragma unroll
            for (int kx = 0; kx < 7; kx++) {
                const int ko = ky * 7 + kx;
                float2 f = fp[ko];
                float2 v = buf[s & 1][hr + ky][w + kx];
                acc[ko] += f.x * x1c.x * v.x + f.y * x1c.y * v.y;
            }
        }
        if ((s & 7) == 7) {
            const int g4 = s >> 3;
#pragma unroll
            for (int ko = 0; ko < KK; ko++) {
                float v = acc[ko] * 0.0625f;
                __nv_bfloat16 h = __float2bfloat16(v);
                __nv_bfloat16 l = __float2bfloat16(v - __bfloat162float(h));
                size_t row = (size_t)(ko * 4 + g4) * NPOS + posg;
                g_corrh[row] = h;
                g_corrl[row] = l;
                acc[ko] = 0.f;
            }
        }
        __syncthreads();
        if (s < 31) {
#pragma unroll
            for (int e = 0; e < 3; e++)
                if (tid + 224 * e < 640) buf[(s + 1) & 1][je[e]][me[e]] = pf[e];
            x1c = x1n;
        }
        __syncthreads();
    }
}

// ---------------------------------------------------------------------------
// Kernel 3: decode — full-K resident (R6 structure) + 2-phase staging overlap.
// CTA 128p x 128o, 512 threads, warp tile 32p x 32o. bf16 hi/lo MMA.
// ---------------------------------------------------------------------------
#define APITCH 272
#define ATILE (KPAD * APITCH)          // 56576
#define BPITCH 432
#define BTILE (128 * BPITCH)           // 55296
#define SA_H 0
#define SA_L ATILE
#define SB_H (2 * ATILE)
#define SB_L (2 * ATILE + BTILE)
#define SM_SCB (2 * ATILE + 2 * BTILE) // 223744
#define SMEM_DEC (SM_SCB + 1024)       // 224768
#define SPLIT_R 112                    // A rows staged in phase 1 (7 k-chunks)

__global__ void __launch_bounds__(512, 1) k_dec(
    const float* __restrict__ x,
    const float* __restrict__ gamma, const float* __restrict__ beta,
    const float* __restrict__ mean, const float* __restrict__ var,
    float* __restrict__ out) {
    extern __shared__ __align__(16) char sm[];
    const uint32_t sb = smem_u32(sm);
    float2* scb = reinterpret_cast<float2*>(sm + SM_SCB);
    const int tid  = threadIdx.x;
    const int wid  = tid >> 5;
    const int lane = tid & 31;
    const size_t P0 = (size_t)blockIdx.x * 128;
    const int o0 = blockIdx.y * 128;
    const int wm = wid & 3;            // p: 4 x 32
    const int wn = wid >> 2;           // o: 4 x 32

    // Phase 1: B (all) + A rows [0, 112)
    for (int i = tid; i < 128 * 26; i += 512) {
        int r = i / 26, c = i % 26;
        uint32_t d = r * BPITCH + c * 16;
        size_t go = ((size_t)(o0 + r) * KPAD) * 2 + c * 16;
        cpasync16(sb + SB_H + d, (const char*)g_dwh + go);
        cpasync16(sb + SB_L + d, (const char*)g_dwl + go);
    }
    for (int i = tid; i < SPLIT_R * 16; i += 512) {
        int r = i >> 4, c = i & 15;
        uint32_t d = r * APITCH + c * 16;
        size_t go = ((size_t)r * NPOS + P0) * 2 + c * 16;
        cpasync16(sb + SA_H + d, (const char*)g_corrh + go);
        cpasync16(sb + SA_L + d, (const char*)g_corrl + go);
    }
    asm volatile("cp.async.commit_group;" ::: "memory");
    // Phase 2: A rows [112, 208)
    for (int i = tid + SPLIT_R * 16; i < KPAD * 16; i += 512) {
        int r = i >> 4, c = i & 15;
        uint32_t d = r * APITCH + c * 16;
        size_t go = ((size_t)r * NPOS + P0) * 2 + c * 16;
        cpasync16(sb + SA_H + d, (const char*)g_corrh + go);
        cpasync16(sb + SA_L + d, (const char*)g_corrl + go);
    }
    asm volatile("cp.async.commit_group;" ::: "memory");
    if (tid < 128) {
        int o = o0 + tid;
        float s = gamma[o] * rsqrtf(var[o] + EPS);
        scb[tid] = make_float2(s, beta[o] - mean[o] * s);
    }
    asm volatile("cp.async.wait_group 1;" ::: "memory");
    __syncthreads();

    float acc[2][4][4];
#pragma unroll
    for (int i = 0; i < 2; i++)
#pragma unroll
        for (int j = 0; j < 4; j++)
#pragma unroll
            for (int q = 0; q < 4; q++) acc[i][j][q] = 0.f;

    const uint32_t a_kr = (lane & 7) + ((lane >> 4) << 3);
    const uint32_t a_mr = ((lane >> 3) & 1) << 3;
    const uint32_t b_row0 = wn * 32 + ((lane >> 4) << 3) + (lane & 7);
    const uint32_t b_colb = (((lane >> 3) & 1) << 4);

#pragma unroll 1
    for (int ks = 0; ks < NKS; ks++) {
        if (ks == 7) {
            asm volatile("cp.async.wait_group 0;" ::: "memory");
            __syncthreads();
        }
        uint32_t ah[2][4], al[2][4];
#pragma unroll
        for (int mt = 0; mt < 2; mt++) {
            uint32_t ad = sb + SA_H + (ks * 16 + a_kr) * APITCH
                        + (wm * 32 + mt * 16 + a_mr) * 2;
            ldmat4t(ah[mt], ad);
            ldmat4t(al[mt], ad + ATILE);
        }
#pragma unroll
        for (int np = 0; np < 2; np++) {
            uint32_t bd = sb + SB_H + (b_row0 + np * 16) * BPITCH + ks * 32 + b_colb;
            uint32_t bh[4], bl[4];
            ldmat4(bh, bd);
            ldmat4(bl, bd + BTILE);
#pragma unroll
            for (int mt = 0; mt < 2; mt++) {
                float* c0 = acc[mt][2 * np];
                float* c1 = acc[mt][2 * np + 1];
                mma16816(c0, ah[mt], bh);
                mma16816(c0, al[mt], bh);
                mma16816(c0, ah[mt], bl);
                mma16816(c1, ah[mt], bh + 2);
                mma16816(c1, al[mt], bh + 2);
                mma16816(c1, ah[mt], bl + 2);
            }
        }
    }

    // Epilogue: bn + residual + relu, out[b][o][tp].
    const int b   = (int)(P0 / THW);
    const int tp0 = (int)(P0 % THW);
    const int g = lane >> 2, tq = lane & 3;
#pragma unroll
    for (int mt = 0; mt < 2; mt++) {
        const int pl = wm * 32 + mt * 16 + g;
        const int tp = tp0 + pl;
#pragma unroll
        for (int nt = 0; nt < 4; nt++) {
            const float* c = acc[mt][nt];
            const int ol = wn * 32 + nt * 8 + 2 * tq;
            const float2 s0 = scb[ol];
            const float2 s1 = scb[ol + 1];
            const size_t base0 = ((size_t)b * Cc + (o0 + ol)) * THW + tp;
            const size_t base1 = base0 + THW;
            float r0 = fmaxf(c[0] * s0.x + s0.y + x[base0],     0.f);
            float r1 = fmaxf(c[1] * s1.x + s1.y + x[base1],     0.f);
            float r2 = fmaxf(c[2] * s0.x + s0.y + x[base0 + 8], 0.f);
            float r3 = fmaxf(c[3] * s1.x + s1.y + x[base1 + 8], 0.f);
            out[base0]     = r0;
            out[base1]     = r1;
            out[base0 + 8] = r2;
            out[base1 + 8] = r3;
        }
    }
}

// ---------------------------------------------------------------------------
extern "C" void kernel_launch(void* const* d_in, const int* in_sizes, int n_in,
                              void* d_out, int out_size) {
    const float* x         = (const float*)d_in[0];
    const float* enc_w     = (const float*)d_in[1];
    const float* enc_gamma = (const float*)d_in[2];
    const float* enc_beta  = (const float*)d_in[3];
    const float* enc_mean  = (const float*)d_in[4];
    const float* enc_var   = (const float*)d_in[5];
    const float* fw        = (const float*)d_in[6];
    const float* dec_w     = (const float*)d_in[7];
    const float* dec_gamma = (const float*)d_in[8];
    const float* dec_beta  = (const float*)d_in[9];
    const float* dec_mean  = (const float*)d_in[10];
    const float* dec_var   = (const float*)d_in[11];
    float* out = (float*)d_out;

    cudaFuncSetAttribute(k_encode, cudaFuncAttributeMaxDynamicSharedMemorySize, SMEM_ENC);
    cudaFuncSetAttribute(k_dec, cudaFuncAttributeMaxDynamicSharedMemorySize, SMEM_DEC);

    k_prep<<<KPAD, Cc>>>(dec_w);
    k_prep_enc<<<CE, Cc>>>(enc_w);
    k_encode<<<dim3(THW / 256, Bsz), 512, SMEM_ENC>>>(x, enc_gamma, enc_beta,
                                                      enc_mean, enc_var);
    k_corr<<<Bsz * Tt * (Hh / 4), 224>>>(fw);
    k_dec<<<dim3(NPOS / 128, Cc / 128), 512, SMEM_DEC>>>(x, dec_gamma, dec_beta,
                                                         dec_mean, dec_var, out);
}

// round 10
// speedup vs baseline: 2.6474x; 1.0242x over previous
#include <cuda_runtime.h>
#include <cuda_bf16.h>
#include <cstdint>

// Problem constants
#define Bsz 4
#define Cc 256
#define CE 64
#define Tt 16
#define Hh 56
#define Ww 56
#define HW (Hh*Ww)            // 3136
#define THW (Tt*HW)           // 50176
#define NPOS (Bsz*THW)        // 200704
#define KK 49
#define K2G 196
#define KPAD 208              // 13 * 16
#define NKS 13
#define EPS 1e-5f

// Scratch. Zero-initialized at load; g_corr rows >= 196 never written -> K pad.
__device__ float g_xenc[(size_t)Bsz * 32 * THW * 2];       // [b][cpair][p][2]
__device__ __nv_bfloat16 g_corrh[(size_t)KPAD * NPOS];     // corr hi [k][pos]
__device__ __nv_bfloat16 g_corrl[(size_t)KPAD * NPOS];     // corr lo [k][pos]
__device__ __nv_bfloat16 g_dwh[Cc * KPAD];                 // dec_w hi [o][208]
__device__ __nv_bfloat16 g_dwl[Cc * KPAD];                 // dec_w lo [o][208]
__device__ __nv_bfloat16 g_ewh[CE * Cc];                   // enc_w hi [ce][256]
__device__ __nv_bfloat16 g_ewl[CE * Cc];                   // enc_w lo [ce][256]

__device__ __forceinline__ uint32_t smem_u32(const void* p) {
    uint32_t a;
    asm("{ .reg .u64 t; cvta.to.shared.u64 t, %1; cvt.u32.u64 %0, t; }"
        : "=r"(a) : "l"(p));
    return a;
}
__device__ __forceinline__ void cpasync16(uint32_t saddr, const void* g) {
    asm volatile("cp.async.cg.shared.global [%0], [%1], 16;"
                 :: "r"(saddr), "l"(g) : "memory");
}
__device__ __forceinline__ void sts8(uint32_t saddr, uint32_t a, uint32_t b) {
    asm volatile("st.shared.v2.b32 [%0], {%1, %2};" :: "r"(saddr), "r"(a), "r"(b)
                 : "memory");
}
__device__ __forceinline__ void ldmat4(uint32_t* d, uint32_t addr) {
    asm volatile("ldmatrix.sync.aligned.m8n8.x4.shared.b16 {%0,%1,%2,%3}, [%4];"
                 : "=r"(d[0]), "=r"(d[1]), "=r"(d[2]), "=r"(d[3]) : "r"(addr));
}
__device__ __forceinline__ void ldmat4t(uint32_t* d, uint32_t addr) {
    asm volatile("ldmatrix.sync.aligned.m8n8.x4.trans.shared.b16 {%0,%1,%2,%3}, [%4];"
                 : "=r"(d[0]), "=r"(d[1]), "=r"(d[2]), "=r"(d[3]) : "r"(addr));
}
__device__ __forceinline__ void mma16816(float* c, const uint32_t* a, const uint32_t* b) {
    asm volatile(
        "mma.sync.aligned.m16n8k16.row.col.f32.bf16.bf16.f32 "
        "{%0,%1,%2,%3}, {%4,%5,%6,%7}, {%8,%9}, {%0,%1,%2,%3};"
        : "+f"(c[0]), "+f"(c[1]), "+f"(c[2]), "+f"(c[3])
        : "r"(a[0]), "r"(a[1]), "r"(a[2]), "r"(a[3]), "r"(b[0]), "r"(b[1]));
}
__device__ __forceinline__ uint32_t packhi(float a, float b, float& ra, float& rb) {
    __nv_bfloat16 ha = __float2bfloat16(a), hb = __float2bfloat16(b);
    ra = a - __bfloat162float(ha);
    rb = b - __bfloat162float(hb);
    return (uint32_t)__bfloat16_as_ushort(ha) |
           ((uint32_t)__bfloat16_as_ushort(hb) << 16);
}
__device__ __forceinline__ uint32_t packbf(float a, float b) {
    return (uint32_t)__bfloat16_as_ushort(__float2bfloat16(a)) |
           ((uint32_t)__bfloat16_as_ushort(__float2bfloat16(b)) << 16);
}

// ---------------------------------------------------------------------------
// Kernel 0a: split dec_w [o][196] -> [o][208] bf16 hi/lo (zero-pad)
// ---------------------------------------------------------------------------
__global__ void k_prep(const float* __restrict__ dw) {
    int k = blockIdx.x;
    int o = threadIdx.x;
    float v = (k < K2G) ? dw[o * K2G + k] : 0.f;
    __nv_bfloat16 h = __float2bfloat16(v);
    float r = v - __bfloat162float(h);
    g_dwh[o * KPAD + k] = h;
    g_dwl[o * KPAD + k] = __float2bfloat16(r);
}
// Kernel 0b: split enc_w [ce][256] -> bf16 hi/lo
__global__ void k_prep_enc(const float* __restrict__ ew) {
    int ce = blockIdx.x;
    int c  = threadIdx.x;
    float v = ew[ce * Cc + c];
    __nv_bfloat16 h = __float2bfloat16(v);
    g_ewh[ce * Cc + c] = h;
    g_ewl[ce * Cc + c] = __float2bfloat16(v - __bfloat162float(h));
}

// ---------------------------------------------------------------------------
// Kernel 1: encode via bf16 hi/lo HMMA (R9 version).
// ---------------------------------------------------------------------------
#define E_PITCH 528
#define E_ATILE (32 * E_PITCH)
#define E_BTILE (64 * E_PITCH)
#define E_OFFB (4 * E_ATILE)
#define E_SCB (E_OFFB + 2 * E_BTILE)
#define SMEM_ENC (E_SCB + 512)

__global__ void __launch_bounds__(512, 1) k_encode(
    const float* __restrict__ x,
    const float* __restrict__ gamma, const float* __restrict__ beta,
    const float* __restrict__ mean, const float* __restrict__ var) {
    extern __shared__ __align__(16) char sm[];
    const uint32_t sb = smem_u32(sm);
    float2* scb = reinterpret_cast<float2*>(sm + E_SCB);
    const int tid  = threadIdx.x;
    const int wid  = tid >> 5;
    const int lane = tid & 31;
    const int b  = blockIdx.y;
    const int P0 = blockIdx.x * 256;
    const int wm = wid & 7;
    const int wn = wid >> 3;

    for (int i = tid; i < 64 * 32; i += 512) {
        int r = i >> 5, c = i & 31;
        uint32_t d = sb + E_OFFB + r * E_PITCH + c * 16;
        size_t go = (size_t)r * 512 + c * 16;
        cpasync16(d,           (const char*)g_ewh + go);
        cpasync16(d + E_BTILE, (const char*)g_ewl + go);
    }
    asm volatile("cp.async.commit_group;" ::: "memory");
    if (tid < 64) {
        float s = gamma[tid] * rsqrtf(var[tid] + EPS);
        scb[tid] = make_float2(s, beta[tid] - mean[tid] * s);
    }

    const float* xb = x + (size_t)b * Cc * THW + P0;
    const int st_r  = tid >> 6;
    const int st_c4 = (tid & 63) * 4;

#pragma unroll
    for (int e = 0; e < 4; e++) {
        int r = st_r + 8 * e;
        float4 v = *reinterpret_cast<const float4*>(xb + (size_t)r * THW + st_c4);
        float rx, ry, rz, rw;
        uint32_t h0 = packhi(v.x, v.y, rx, ry);
        uint32_t h1 = packhi(v.z, v.w, rz, rw);
        uint32_t d = sb + r * E_PITCH + st_c4 * 2;
        sts8(d, h0, h1);
        sts8(d + E_ATILE, packbf(rx, ry), packbf(rz, rw));
    }
    asm volatile("cp.async.wait_group 0;" ::: "memory");
    __syncthreads();

    float acc[2][4][4];
#pragma unroll
    for (int i = 0; i < 2; i++)
#pragma unroll
        for (int j = 0; j < 4; j++)
#pragma unroll
            for (int q = 0; q < 4; q++) acc[i][j][q] = 0.f;

    const uint32_t a_kr = (lane & 7) + ((lane >> 4) << 3);
    const uint32_t a_mr = ((lane >> 3) & 1) << 3;
    const uint32_t b_row0 = wn * 32 + ((lane >> 4) << 3) + (lane & 7);
    const uint32_t b_colb = (((lane >> 3) & 1) << 4);

#pragma unroll 1
    for (int kc = 0; kc < 8; kc++) {
        float4 v[4];
        if (kc < 7) {
            const float* xk = xb + (size_t)(kc + 1) * 32 * THW;
#pragma unroll
            for (int e = 0; e < 4; e++)
                v[e] = *reinterpret_cast<const float4*>(
                    xk + (size_t)(st_r + 8 * e) * THW + st_c4);
        }
        const uint32_t ab = sb + (kc & 1) * (2 * E_ATILE);
#pragma unroll
        for (int ks2 = 0; ks2 < 2; ks2++) {
            uint32_t ah[2][4], al[2][4];
#pragma unroll
            for (int mt = 0; mt < 2; mt++) {
                uint32_t ad = ab + (ks2 * 16 + a_kr) * E_PITCH
                            + (wm * 32 + mt * 16 + a_mr) * 2;
                ldmat4t(ah[mt], ad);
                ldmat4t(al[mt], ad + E_ATILE);
            }
#pragma unroll
            for (int np = 0; np < 2; np++) {
                uint32_t bd = sb + E_OFFB + (b_row0 + np * 16) * E_PITCH
                            + (kc * 32 + ks2 * 16) * 2 + b_colb;
                uint32_t bh[4], bl[4];
                ldmat4(bh, bd);
                ldmat4(bl, bd + E_BTILE);
#pragma unroll
                for (int mt = 0; mt < 2; mt++) {
                    float* c0 = acc[mt][2 * np];
                    float* c1 = acc[mt][2 * np + 1];
                    mma16816(c0, ah[mt], bh);
                    mma16816(c0, al[mt], bh);
                    mma16816(c0, ah[mt], bl);
                    mma16816(c1, ah[mt], bh + 2);
                    mma16816(c1, al[mt], bh + 2);
                    mma16816(c1, ah[mt], bl + 2);
                }
            }
        }
        __syncthreads();
        if (kc < 7) {
            const uint32_t nb = sb + ((kc + 1) & 1) * (2 * E_ATILE);
#pragma unroll
            for (int e = 0; e < 4; e++) {
                int r = st_r + 8 * e;
                float rx, ry, rz, rw;
                uint32_t h0 = packhi(v[e].x, v[e].y, rx, ry);
                uint32_t h1 = packhi(v[e].z, v[e].w, rz, rw);
                uint32_t d = nb + r * E_PITCH + st_c4 * 2;
                sts8(d, h0, h1);
                sts8(d + E_ATILE, packbf(rx, ry), packbf(rz, rw));
            }
            __syncthreads();
        }
    }

    const int g = lane >> 2, tq = lane & 3;
#pragma unroll
    for (int mt = 0; mt < 2; mt++) {
        const int p = P0 + wm * 32 + mt * 16 + g;
#pragma unroll
        for (int nt = 0; nt < 4; nt++) {
            const float* c = acc[mt][nt];
            const int ol = wn * 32 + nt * 8 + 2 * tq;
            const float2 s0 = scb[ol];
            const float2 s1 = scb[ol + 1];
            const int cp = ol >> 1;
            float* base = &g_xenc[(((size_t)b * 32 + cp) * THW + p) * 2];
            float2 v0, v1;
            v0.x = fmaxf(c[0] * s0.x + s0.y, 0.f);
            v0.y = fmaxf(c[1] * s1.x + s1.y, 0.f);
            v1.x = fmaxf(c[2] * s0.x + s0.y, 0.f);
            v1.y = fmaxf(c[3] * s1.x + s1.y, 0.f);
            *reinterpret_cast<float2*>(base)      = v0;
            *reinterpret_cast<float2*>(base + 16) = v1;
        }
    }
}

// ---------------------------------------------------------------------------
// Kernel 2: correlation v3 — 2 vertically-adjacent positions per thread.
// Block = (b,t, 8 h-rows x 56 w) = 448 positions, 224 threads.
// Window 14x64 float2, double-buffered. kx-outer inner loop shares f and
// window rows between the two positions (ky=r for A, ky=r-1 for B).
// ---------------------------------------------------------------------------
__global__ void __launch_bounds__(224, 2) k_corr(const float* __restrict__ fw) {
    __shared__ __align__(16) float2 fws2[32 * KK];     // [cpair][ko]
    __shared__ __align__(16) float2 buf[2][14][64];    // double-buffered window
    const int tid = threadIdx.x;
    const int bx = blockIdx.x;
    const int h0 = (bx % 7) * 8;
    const int t  = (bx / 7) % Tt;
    const int b  = bx / (7 * Tt);
    const int a  = tid / 56;          // 0..3 -> row pair
    const int w  = tid % 56;
    const int jA = 2 * a;             // buf-local row of posA
    const int hA = h0 + jA;           // global h of posA; posB = hA+1
    const int t1 = (t == 0) ? 0 : t - 1;

    for (int idx = tid; idx < 32 * KK; idx += 224) {
        int cp = idx / KK, ko = idx % KK;
        int c = cp * 2;
        fws2[idx] = make_float2(fw[(c * Tt + t) * KK + ko],
                                fw[((c + 1) * Tt + t) * KK + ko]);
    }

    const float2* xe = reinterpret_cast<const float2*>(g_xenc);
    const size_t cstride = THW;
    const size_t cb0 = (size_t)(b * 32) * cstride;

    // staging: 14*64 = 896 entries, 4 per thread
    int je[4], me[4];
    bool in[4];
    size_t off[4];
#pragma unroll
    for (int e = 0; e < 4; e++) {
        int idx = tid + 224 * e;
        int j = idx >> 6, m = idx & 63;
        je[e] = j; me[e] = m;
        int gh = h0 + j - 3, gx = m - 3;
        in[e] = (unsigned)gh < (unsigned)Hh && (unsigned)gx < (unsigned)Ww;
        off[e] = (size_t)t * HW + (size_t)gh * Ww + gx;
    }
    const size_t x1offA = (size_t)t1 * HW + (size_t)hA * Ww + w;
    const size_t posA   = ((size_t)(b * Tt + t) * Hh + hA) * Ww + w;

    float accA[KK], accB[KK];
#pragma unroll
    for (int i = 0; i < KK; i++) { accA[i] = 0.f; accB[i] = 0.f; }

    // prologue: stage 0
    float2 pf[4], x1Ac, x1Bc, x1An, x1Bn;
#pragma unroll
    for (int e = 0; e < 4; e++)
        pf[e] = in[e] ? xe[cb0 + off[e]] : make_float2(0.f, 0.f);
    x1Ac = xe[cb0 + x1offA];
    x1Bc = xe[cb0 + x1offA + Ww];
#pragma unroll
    for (int e = 0; e < 4; e++) buf[0][je[e]][me[e]] = pf[e];
    __syncthreads();

#pragma unroll 1
    for (int s = 0; s < 32; s++) {
        const size_t cbn = cb0 + (size_t)(s + 1) * cstride;
        if (s < 31) {
#pragma unroll
            for (int e = 0; e < 4; e++)
                pf[e] = in[e] ? xe[cbn + off[e]] : make_float2(0.f, 0.f);
            x1An = xe[cbn + x1offA];
            x1Bn = xe[cbn + x1offA + Ww];
        }
        const float2* fp = &fws2[s * KK];
        const float2 (*bw)[64] = buf[s & 1];
#pragma unroll
        for (int kx = 0; kx < 7; kx++) {
            float2 fcol[7];
#pragma unroll
            for (int r = 0; r < 7; r++) fcol[r] = fp[r * 7 + kx];
#pragma unroll
            for (int r = 0; r < 8; r++) {
                float2 v = bw[jA + r][w + kx];
                if (r < 7)
                    accA[r * 7 + kx] += fcol[r].x * x1Ac.x * v.x
                                      + fcol[r].y * x1Ac.y * v.y;
                if (r >= 1)
                    accB[(r - 1) * 7 + kx] += fcol[r - 1].x * x1Bc.x * v.x
                                            + fcol[r - 1].y * x1Bc.y * v.y;
            }
        }
        if ((s & 7) == 7) {   // flush 16-channel group
            const int g4 = s >> 3;
#pragma unroll
            for (int ko = 0; ko < KK; ko++) {
                size_t row = (size_t)(ko * 4 + g4) * NPOS;
                float vA = accA[ko] * 0.0625f;
                __nv_bfloat16 hA2 = __float2bfloat16(vA);
                g_corrh[row + posA] = hA2;
                g_corrl[row + posA] = __float2bfloat16(vA - __bfloat162float(hA2));
                float vB = accB[ko] * 0.0625f;
                __nv_bfloat16 hB2 = __float2bfloat16(vB);
                g_corrh[row + posA + Ww] = hB2;
                g_corrl[row + posA + Ww] = __float2bfloat16(vB - __bfloat162float(hB2));
                accA[ko] = 0.f;
                accB[ko] = 0.f;
            }
        }
        __syncthreads();
        if (s < 31) {
#pragma unroll
            for (int e = 0; e < 4; e++) buf[(s + 1) & 1][je[e]][me[e]] = pf[e];
            x1Ac = x1An;
            x1Bc = x1Bn;
        }
        __syncthreads();
    }
}

// ---------------------------------------------------------------------------
// Kernel 3: decode — full-K resident + 2-phase staging (R9 version).
// ---------------------------------------------------------------------------
#define APITCH 272
#define ATILE (KPAD * APITCH)
#define BPITCH 432
#define BTILE (128 * BPITCH)
#define SA_H 0
#define SA_L ATILE
#define SB_H (2 * ATILE)
#define SB_L (2 * ATILE + BTILE)
#define SM_SCB (2 * ATILE + 2 * BTILE)
#define SMEM_DEC (SM_SCB + 1024)
#define SPLIT_R 112

__global__ void __launch_bounds__(512, 1) k_dec(
    const float* __restrict__ x,
    const float* __restrict__ gamma, const float* __restrict__ beta,
    const float* __restrict__ mean, const float* __restrict__ var,
    float* __restrict__ out) {
    extern __shared__ __align__(16) char sm[];
    const uint32_t sb = smem_u32(sm);
    float2* scb = reinterpret_cast<float2*>(sm + SM_SCB);
    const int tid  = threadIdx.x;
    const int wid  = tid >> 5;
    const int lane = tid & 31;
    const size_t P0 = (size_t)blockIdx.x * 128;
    const int o0 = blockIdx.y * 128;
    const int wm = wid & 3;
    const int wn = wid >> 2;

    for (int i = tid; i < 128 * 26; i += 512) {
        int r = i / 26, c = i % 26;
        uint32_t d = r * BPITCH + c * 16;
        size_t go = ((size_t)(o0 + r) * KPAD) * 2 + c * 16;
        cpasync16(sb + SB_H + d, (const char*)g_dwh + go);
        cpasync16(sb + SB_L + d, (const char*)g_dwl + go);
    }
    for (int i = tid; i < SPLIT_R * 16; i += 512) {
        int r = i >> 4, c = i & 15;
        uint32_t d = r * APITCH + c * 16;
        size_t go = ((size_t)r * NPOS + P0) * 2 + c * 16;
        cpasync16(sb + SA_H + d, (const char*)g_corrh + go);
        cpasync16(sb + SA_L + d, (const char*)g_corrl + go);
    }
    asm volatile("cp.async.commit_group;" ::: "memory");
    for (int i = tid + SPLIT_R * 16; i < KPAD * 16; i += 512) {
        int r = i >> 4, c = i & 15;
        uint32_t d = r * APITCH + c * 16;
        size_t go = ((size_t)r * NPOS + P0) * 2 + c * 16;
        cpasync16(sb + SA_H + d, (const char*)g_corrh + go);
        cpasync16(sb + SA_L + d, (const char*)g_corrl + go);
    }
    asm volatile("cp.async.commit_group;" ::: "memory");
    if (tid < 128) {
        int o = o0 + tid;
        float s = gamma[o] * rsqrtf(var[o] + EPS);
        scb[tid] = make_float2(s, beta[o] - mean[o] * s);
    }
    asm volatile("cp.async.wait_group 1;" ::: "memory");
    __syncthreads();

    float acc[2][4][4];
#pragma unroll
    for (int i = 0; i < 2; i++)
#pragma unroll
        for (int j = 0; j < 4; j++)
#pragma unroll
            for (int q = 0; q < 4; q++) acc[i][j][q] = 0.f;

    const uint32_t a_kr = (lane & 7) + ((lane >> 4) << 3);
    const uint32_t a_mr = ((lane >> 3) & 1) << 3;
    const uint32_t b_row0 = wn * 32 + ((lane >> 4) << 3) + (lane & 7);
    const uint32_t b_colb = (((lane >> 3) & 1) << 4);

#pragma unroll 1
    for (int ks = 0; ks < NKS; ks++) {
        if (ks == 7) {
            asm volatile("cp.async.wait_group 0;" ::: "memory");
            __syncthreads();
        }
        uint32_t ah[2][4], al[2][4];
#pragma unroll
        for (int mt = 0; mt < 2; mt++) {
            uint32_t ad = sb + SA_H + (ks * 16 + a_kr) * APITCH
                        + (wm * 32 + mt * 16 + a_mr) * 2;
            ldmat4t(ah[mt], ad);
            ldmat4t(al[mt], ad + ATILE);
        }
#pragma unroll
        for (int np = 0; np < 2; np++) {
            uint32_t bd = sb + SB_H + (b_row0 + np * 16) * BPITCH + ks * 32 + b_colb;
            uint32_t bh[4], bl[4];
            ldmat4(bh, bd);
            ldmat4(bl, bd + BTILE);
#pragma unroll
            for (int mt = 0; mt < 2; mt++) {
                float* c0 = acc[mt][2 * np];
                float* c1 = acc[mt][2 * np + 1];
                mma16816(c0, ah[mt], bh);
                mma16816(c0, al[mt], bh);
                mma16816(c0, ah[mt], bl);
                mma16816(c1, ah[mt], bh + 2);
                mma16816(c1, al[mt], bh + 2);
                mma16816(c1, ah[mt], bl + 2);
            }
        }
    }

    const int b   = (int)(P0 / THW);
    const int tp0 = (int)(P0 % THW);
    const int g = lane >> 2, tq = lane & 3;
#pragma unroll
    for (int mt = 0; mt < 2; mt++) {
        const int pl = wm * 32 + mt * 16 + g;
        const int tp = tp0 + pl;
#pragma unroll
        for (int nt = 0; nt < 4; nt++) {
            const float* c = acc[mt][nt];
            const int ol = wn * 32 + nt * 8 + 2 * tq;
            const float2 s0 = scb[ol];
            const float2 s1 = scb[ol + 1];
            const size_t base0 = ((size_t)b * Cc + (o0 + ol)) * THW + tp;
            const size_t base1 = base0 + THW;
            float r0 = fmaxf(c[0] * s0.x + s0.y + x[base0],     0.f);
            float r1 = fmaxf(c[1] * s1.x + s1.y + x[base1],     0.f);
            float r2 = fmaxf(c[2] * s0.x + s0.y + x[base0 + 8], 0.f);
            float r3 = fmaxf(c[3] * s1.x + s1.y + x[base1 + 8], 0.f);
            out[base0]     = r0;
            out[base1]     = r1;
            out[base0 + 8] = r2;
            out[base1 + 8] = r3;
        }
    }
}

// ---------------------------------------------------------------------------
extern "C" void kernel_launch(void* const* d_in, const int* in_sizes, int n_in,
                              void* d_out, int out_size) {
    const float* x         = (const float*)d_in[0];
    const float* enc_w     = (const float*)d_in[1];
    const float* enc_gamma = (const float*)d_in[2];
    const float* enc_beta  = (const float*)d_in[3];
    const float* enc_mean  = (const float*)d_in[4];
    const float* enc_var   = (const float*)d_in[5];
    const float* fw        = (const float*)d_in[6];
    const float* dec_w     = (const float*)d_in[7];
    const float* dec_gamma = (const float*)d_in[8];
    const float* dec_beta  = (const float*)d_in[9];
    const float* dec_mean  = (const float*)d_in[10];
    const float* dec_var   = (const float*)d_in[11];
    float* out = (float*)d_out;

    cudaFuncSetAttribute(k_encode, cudaFuncAttributeMaxDynamicSharedMemorySize, SMEM_ENC);
    cudaFuncSetAttribute(k_dec, cudaFuncAttributeMaxDynamicSharedMemorySize, SMEM_DEC);

    k_prep<<<KPAD, Cc>>>(dec_w);
    k_prep_enc<<<CE, Cc>>>(enc_w);
    k_encode<<<dim3(THW / 256, Bsz), 512, SMEM_ENC>>>(x, enc_gamma, enc_beta,
                                                      enc_mean, enc_var);
    k_corr<<<Bsz * Tt * 7, 224>>>(fw);
    k_dec<<<dim3(NPOS / 128, Cc / 128), 512, SMEM_DEC>>>(x, dec_gamma, dec_beta,
                                                         dec_mean, dec_var, out);
}

// round 11
// speedup vs baseline: 2.6793x; 1.0121x over previous
#include <cuda_runtime.h>
#include <cuda_bf16.h>
#include <cstdint>

// Problem constants
#define Bsz 4
#define Cc 256
#define CE 64
#define Tt 16
#define Hh 56
#define Ww 56
#define HW (Hh*Ww)            // 3136
#define THW (Tt*HW)           // 50176
#define NPOS (Bsz*THW)        // 200704
#define KK 49
#define K2G 196
#define KPAD 208              // 13 * 16
#define NKS 13
#define EPS 1e-5f

// Scratch. Zero-initialized at load; g_corr rows >= 196 never written -> K pad.
__device__ float g_xenc[(size_t)Bsz * 32 * THW * 2];       // [b][cpair][p][2]
__device__ __nv_bfloat16 g_corrh[(size_t)KPAD * NPOS];     // corr hi [k][pos]
__device__ __nv_bfloat16 g_corrl[(size_t)KPAD * NPOS];     // corr lo [k][pos]
__device__ __nv_bfloat16 g_dwh[Cc * KPAD];                 // dec_w hi [o][208]
__device__ __nv_bfloat16 g_dwl[Cc * KPAD];                 // dec_w lo [o][208]
__device__ __nv_bfloat16 g_ewh[CE * Cc];                   // enc_w hi [ce][256]
__device__ __nv_bfloat16 g_ewl[CE * Cc];                   // enc_w lo [ce][256]

__device__ __forceinline__ uint32_t smem_u32(const void* p) {
    uint32_t a;
    asm("{ .reg .u64 t; cvta.to.shared.u64 t, %1; cvt.u32.u64 %0, t; }"
        : "=r"(a) : "l"(p));
    return a;
}
__device__ __forceinline__ void cpasync16(uint32_t saddr, const void* g) {
    asm volatile("cp.async.cg.shared.global [%0], [%1], 16;"
                 :: "r"(saddr), "l"(g) : "memory");
}
__device__ __forceinline__ void sts8(uint32_t saddr, uint32_t a, uint32_t b) {
    asm volatile("st.shared.v2.b32 [%0], {%1, %2};" :: "r"(saddr), "r"(a), "r"(b)
                 : "memory");
}
__device__ __forceinline__ void ldmat4(uint32_t* d, uint32_t addr) {
    asm volatile("ldmatrix.sync.aligned.m8n8.x4.shared.b16 {%0,%1,%2,%3}, [%4];"
                 : "=r"(d[0]), "=r"(d[1]), "=r"(d[2]), "=r"(d[3]) : "r"(addr));
}
__device__ __forceinline__ void ldmat4t(uint32_t* d, uint32_t addr) {
    asm volatile("ldmatrix.sync.aligned.m8n8.x4.trans.shared.b16 {%0,%1,%2,%3}, [%4];"
                 : "=r"(d[0]), "=r"(d[1]), "=r"(d[2]), "=r"(d[3]) : "r"(addr));
}
__device__ __forceinline__ void mma16816(float* c, const uint32_t* a, const uint32_t* b) {
    asm volatile(
        "mma.sync.aligned.m16n8k16.row.col.f32.bf16.bf16.f32 "
        "{%0,%1,%2,%3}, {%4,%5,%6,%7}, {%8,%9}, {%0,%1,%2,%3};"
        : "+f"(c[0]), "+f"(c[1]), "+f"(c[2]), "+f"(c[3])
        : "r"(a[0]), "r"(a[1]), "r"(a[2]), "r"(a[3]), "r"(b[0]), "r"(b[1]));
}
__device__ __forceinline__ uint32_t packhi(float a, float b, float& ra, float& rb) {
    __nv_bfloat16 ha = __float2bfloat16(a), hb = __float2bfloat16(b);
    ra = a - __bfloat162float(ha);
    rb = b - __bfloat162float(hb);
    return (uint32_t)__bfloat16_as_ushort(ha) |
           ((uint32_t)__bfloat16_as_ushort(hb) << 16);
}
__device__ __forceinline__ uint32_t packbf(float a, float b) {
    return (uint32_t)__bfloat16_as_ushort(__float2bfloat16(a)) |
           ((uint32_t)__bfloat16_as_ushort(__float2bfloat16(b)) << 16);
}

// ---------------------------------------------------------------------------
// Kernel 0a: split dec_w [o][196] -> [o][208] bf16 hi/lo (zero-pad)
// ---------------------------------------------------------------------------
__global__ void k_prep(const float* __restrict__ dw) {
    int k = blockIdx.x;
    int o = threadIdx.x;
    float v = (k < K2G) ? dw[o * K2G + k] : 0.f;
    __nv_bfloat16 h = __float2bfloat16(v);
    float r = v - __bfloat162float(h);
    g_dwh[o * KPAD + k] = h;
    g_dwl[o * KPAD + k] = __float2bfloat16(r);
}
// Kernel 0b: split enc_w [ce][256] -> bf16 hi/lo
__global__ void k_prep_enc(const float* __restrict__ ew) {
    int ce = blockIdx.x;
    int c  = threadIdx.x;
    float v = ew[ce * Cc + c];
    __nv_bfloat16 h = __float2bfloat16(v);
    g_ewh[ce * Cc + c] = h;
    g_ewl[ce * Cc + c] = __float2bfloat16(v - __bfloat162float(h));
}

// ---------------------------------------------------------------------------
// Kernel 1: encode via bf16 hi/lo HMMA (R9 version, proven).
// ---------------------------------------------------------------------------
#define E_PITCH 528
#define E_ATILE (32 * E_PITCH)
#define E_BTILE (64 * E_PITCH)
#define E_OFFB (4 * E_ATILE)
#define E_SCB (E_OFFB + 2 * E_BTILE)
#define SMEM_ENC (E_SCB + 512)

__global__ void __launch_bounds__(512, 1) k_encode(
    const float* __restrict__ x,
    const float* __restrict__ gamma, const float* __restrict__ beta,
    const float* __restrict__ mean, const float* __restrict__ var) {
    extern __shared__ __align__(16) char sm[];
    const uint32_t sb = smem_u32(sm);
    float2* scb = reinterpret_cast<float2*>(sm + E_SCB);
    const int tid  = threadIdx.x;
    const int wid  = tid >> 5;
    const int lane = tid & 31;
    const int b  = blockIdx.y;
    const int P0 = blockIdx.x * 256;
    const int wm = wid & 7;
    const int wn = wid >> 3;

    for (int i = tid; i < 64 * 32; i += 512) {
        int r = i >> 5, c = i & 31;
        uint32_t d = sb + E_OFFB + r * E_PITCH + c * 16;
        size_t go = (size_t)r * 512 + c * 16;
        cpasync16(d,           (const char*)g_ewh + go);
        cpasync16(d + E_BTILE, (const char*)g_ewl + go);
    }
    asm volatile("cp.async.commit_group;" ::: "memory");
    if (tid < 64) {
        float s = gamma[tid] * rsqrtf(var[tid] + EPS);
        scb[tid] = make_float2(s, beta[tid] - mean[tid] * s);
    }

    const float* xb = x + (size_t)b * Cc * THW + P0;
    const int st_r  = tid >> 6;
    const int st_c4 = (tid & 63) * 4;

#pragma unroll
    for (int e = 0; e < 4; e++) {
        int r = st_r + 8 * e;
        float4 v = *reinterpret_cast<const float4*>(xb + (size_t)r * THW + st_c4);
        float rx, ry, rz, rw;
        uint32_t h0 = packhi(v.x, v.y, rx, ry);
        uint32_t h1 = packhi(v.z, v.w, rz, rw);
        uint32_t d = sb + r * E_PITCH + st_c4 * 2;
        sts8(d, h0, h1);
        sts8(d + E_ATILE, packbf(rx, ry), packbf(rz, rw));
    }
    asm volatile("cp.async.wait_group 0;" ::: "memory");
    __syncthreads();

    float acc[2][4][4];
#pragma unroll
    for (int i = 0; i < 2; i++)
#pragma unroll
        for (int j = 0; j < 4; j++)
#pragma unroll
            for (int q = 0; q < 4; q++) acc[i][j][q] = 0.f;

    const uint32_t a_kr = (lane & 7) + ((lane >> 4) << 3);
    const uint32_t a_mr = ((lane >> 3) & 1) << 3;
    const uint32_t b_row0 = wn * 32 + ((lane >> 4) << 3) + (lane & 7);
    const uint32_t b_colb = (((lane >> 3) & 1) << 4);

#pragma unroll 1
    for (int kc = 0; kc < 8; kc++) {
        float4 v[4];
        if (kc < 7) {
            const float* xk = xb + (size_t)(kc + 1) * 32 * THW;
#pragma unroll
            for (int e = 0; e < 4; e++)
                v[e] = *reinterpret_cast<const float4*>(
                    xk + (size_t)(st_r + 8 * e) * THW + st_c4);
        }
        const uint32_t ab = sb + (kc & 1) * (2 * E_ATILE);
#pragma unroll
        for (int ks2 = 0; ks2 < 2; ks2++) {
            uint32_t ah[2][4], al[2][4];
#pragma unroll
            for (int mt = 0; mt < 2; mt++) {
                uint32_t ad = ab + (ks2 * 16 + a_kr) * E_PITCH
                            + (wm * 32 + mt * 16 + a_mr) * 2;
                ldmat4t(ah[mt], ad);
                ldmat4t(al[mt], ad + E_ATILE);
            }
#pragma unroll
            for (int np = 0; np < 2; np++) {
                uint32_t bd = sb + E_OFFB + (b_row0 + np * 16) * E_PITCH
                            + (kc * 32 + ks2 * 16) * 2 + b_colb;
                uint32_t bh[4], bl[4];
                ldmat4(bh, bd);
                ldmat4(bl, bd + E_BTILE);
#pragma unroll
                for (int mt = 0; mt < 2; mt++) {
                    float* c0 = acc[mt][2 * np];
                    float* c1 = acc[mt][2 * np + 1];
                    mma16816(c0, ah[mt], bh);
                    mma16816(c0, al[mt], bh);
                    mma16816(c0, ah[mt], bl);
                    mma16816(c1, ah[mt], bh + 2);
                    mma16816(c1, al[mt], bh + 2);
                    mma16816(c1, ah[mt], bl + 2);
                }
            }
        }
        __syncthreads();
        if (kc < 7) {
            const uint32_t nb = sb + ((kc + 1) & 1) * (2 * E_ATILE);
#pragma unroll
            for (int e = 0; e < 4; e++) {
                int r = st_r + 8 * e;
                float rx, ry, rz, rw;
                uint32_t h0 = packhi(v[e].x, v[e].y, rx, ry);
                uint32_t h1 = packhi(v[e].z, v[e].w, rz, rw);
                uint32_t d = nb + r * E_PITCH + st_c4 * 2;
                sts8(d, h0, h1);
                sts8(d + E_ATILE, packbf(rx, ry), packbf(rz, rw));
            }
            __syncthreads();
        }
    }

    const int g = lane >> 2, tq = lane & 3;
#pragma unroll
    for (int mt = 0; mt < 2; mt++) {
        const int p = P0 + wm * 32 + mt * 16 + g;
#pragma unroll
        for (int nt = 0; nt < 4; nt++) {
            const float* c = acc[mt][nt];
            const int ol = wn * 32 + nt * 8 + 2 * tq;
            const float2 s0 = scb[ol];
            const float2 s1 = scb[ol + 1];
            const int cp = ol >> 1;
            float* base = &g_xenc[(((size_t)b * 32 + cp) * THW + p) * 2];
            float2 v0, v1;
            v0.x = fmaxf(c[0] * s0.x + s0.y, 0.f);
            v0.y = fmaxf(c[1] * s1.x + s1.y, 0.f);
            v1.x = fmaxf(c[2] * s0.x + s0.y, 0.f);
            v1.y = fmaxf(c[3] * s1.x + s1.y, 0.f);
            *reinterpret_cast<float2*>(base)      = v0;
            *reinterpret_cast<float2*>(base + 16) = v1;
        }
    }
}

// ---------------------------------------------------------------------------
// Kernel 2: correlation v4 — 2 vertical positions/thread, ONE barrier/stage.
// Stage s: prefetch s+1 (LDG) -> compute from buf[s&1] -> store s+1 into
// buf[(s+1)&1] -> barrier. Writes to buf[(s+1)&1] are safe: its readers ran
// in stage s-1, which ended with a barrier.
// ---------------------------------------------------------------------------
__global__ void __launch_bounds__(224, 2) k_corr(const float* __restrict__ fw) {
    __shared__ __align__(16) float2 fws2[32 * KK];     // [cpair][ko]
    __shared__ __align__(16) float2 buf[2][14][64];    // double-buffered window
    const int tid = threadIdx.x;
    const int bx = blockIdx.x;
    const int h0 = (bx % 7) * 8;
    const int t  = (bx / 7) % Tt;
    const int b  = bx / (7 * Tt);
    const int a  = tid / 56;          // 0..3 -> row pair
    const int w  = tid % 56;
    const int jA = 2 * a;             // buf-local row of posA
    const int hA = h0 + jA;           // global h of posA; posB = hA+1
    const int t1 = (t == 0) ? 0 : t - 1;

    for (int idx = tid; idx < 32 * KK; idx += 224) {
        int cp = idx / KK, ko = idx % KK;
        int c = cp * 2;
        fws2[idx] = make_float2(fw[(c * Tt + t) * KK + ko],
                                fw[((c + 1) * Tt + t) * KK + ko]);
    }

    const float2* xe = reinterpret_cast<const float2*>(g_xenc);
    const size_t cstride = THW;
    const size_t cb0 = (size_t)(b * 32) * cstride;

    // staging: 14*64 = 896 entries, 4 per thread
    int je[4], me[4];
    bool in[4];
    size_t off[4];
#pragma unroll
    for (int e = 0; e < 4; e++) {
        int idx = tid + 224 * e;
        int j = idx >> 6, m = idx & 63;
        je[e] = j; me[e] = m;
        int gh = h0 + j - 3, gx = m - 3;
        in[e] = (unsigned)gh < (unsigned)Hh && (unsigned)gx < (unsigned)Ww;
        off[e] = (size_t)t * HW + (size_t)gh * Ww + gx;
    }
    const size_t x1offA = (size_t)t1 * HW + (size_t)hA * Ww + w;
    const size_t posA   = ((size_t)(b * Tt + t) * Hh + hA) * Ww + w;

    float accA[KK], accB[KK];
#pragma unroll
    for (int i = 0; i < KK; i++) { accA[i] = 0.f; accB[i] = 0.f; }

    // prologue: stage 0
    float2 pf[4], x1Ac, x1Bc, x1An, x1Bn;
#pragma unroll
    for (int e = 0; e < 4; e++)
        pf[e] = in[e] ? xe[cb0 + off[e]] : make_float2(0.f, 0.f);
    x1Ac = xe[cb0 + x1offA];
    x1Bc = xe[cb0 + x1offA + Ww];
#pragma unroll
    for (int e = 0; e < 4; e++) buf[0][je[e]][me[e]] = pf[e];
    __syncthreads();

#pragma unroll 1
    for (int s = 0; s < 32; s++) {
        const size_t cbn = cb0 + (size_t)(s + 1) * cstride;
        if (s < 31) {
#pragma unroll
            for (int e = 0; e < 4; e++)
                pf[e] = in[e] ? xe[cbn + off[e]] : make_float2(0.f, 0.f);
            x1An = xe[cbn + x1offA];
            x1Bn = xe[cbn + x1offA + Ww];
        }
        const float2* fp = &fws2[s * KK];
        const float2 (*bw)[64] = buf[s & 1];
#pragma unroll
        for (int kx = 0; kx < 7; kx++) {
            float2 fcol[7];
#pragma unroll
            for (int r = 0; r < 7; r++) fcol[r] = fp[r * 7 + kx];
#pragma unroll
            for (int r = 0; r < 8; r++) {
                float2 v = bw[jA + r][w + kx];
                if (r < 7)
                    accA[r * 7 + kx] += fcol[r].x * x1Ac.x * v.x
                                      + fcol[r].y * x1Ac.y * v.y;
                if (r >= 1)
                    accB[(r - 1) * 7 + kx] += fcol[r - 1].x * x1Bc.x * v.x
                                            + fcol[r - 1].y * x1Bc.y * v.y;
            }
        }
        if ((s & 7) == 7) {   // flush 16-channel group
            const int g4 = s >> 3;
#pragma unroll
            for (int ko = 0; ko < KK; ko++) {
                size_t row = (size_t)(ko * 4 + g4) * NPOS;
                float vA = accA[ko] * 0.0625f;
                __nv_bfloat16 hA2 = __float2bfloat16(vA);
                g_corrh[row + posA] = hA2;
                g_corrl[row + posA] = __float2bfloat16(vA - __bfloat162float(hA2));
                float vB = accB[ko] * 0.0625f;
                __nv_bfloat16 hB2 = __float2bfloat16(vB);
                g_corrh[row + posA + Ww] = hB2;
                g_corrl[row + posA + Ww] = __float2bfloat16(vB - __bfloat162float(hB2));
                accA[ko] = 0.f;
                accB[ko] = 0.f;
            }
        }
        if (s < 31) {
#pragma unroll
            for (int e = 0; e < 4; e++) buf[(s + 1) & 1][je[e]][me[e]] = pf[e];
            x1Ac = x1An;
            x1Bc = x1Bn;
        }
        __syncthreads();      // single barrier per stage
    }
}

// ---------------------------------------------------------------------------
// Kernel 3: decode — full-K resident + 2-phase staging. Grid (2, NPOS/128):
// the two o-tiles of the same p-tile are ADJACENT in launch order so the
// second A read hits L2 instead of DRAM.
// ---------------------------------------------------------------------------
#define APITCH 272
#define ATILE (KPAD * APITCH)
#define BPITCH 432
#define BTILE (128 * BPITCH)
#define SA_H 0
#define SA_L ATILE
#define SB_H (2 * ATILE)
#define SB_L (2 * ATILE + BTILE)
#define SM_SCB (2 * ATILE + 2 * BTILE)
#define SMEM_DEC (SM_SCB + 1024)
#define SPLIT_R 112

__global__ void __launch_bounds__(512, 1) k_dec(
    const float* __restrict__ x,
    const float* __restrict__ gamma, const float* __restrict__ beta,
    const float* __restrict__ mean, const float* __restrict__ var,
    float* __restrict__ out) {
    extern __shared__ __align__(16) char sm[];
    const uint32_t sb = smem_u32(sm);
    float2* scb = reinterpret_cast<float2*>(sm + SM_SCB);
    const int tid  = threadIdx.x;
    const int wid  = tid >> 5;
    const int lane = tid & 31;
    const size_t P0 = (size_t)blockIdx.y * 128;     // p-tile (slow dim)
    const int o0 = blockIdx.x * 128;                // o-tile (fast dim)
    const int wm = wid & 3;
    const int wn = wid >> 2;

    for (int i = tid; i < 128 * 26; i += 512) {
        int r = i / 26, c = i % 26;
        uint32_t d = r * BPITCH + c * 16;
        size_t go = ((size_t)(o0 + r) * KPAD) * 2 + c * 16;
        cpasync16(sb + SB_H + d, (const char*)g_dwh + go);
        cpasync16(sb + SB_L + d, (const char*)g_dwl + go);
    }
    for (int i = tid; i < SPLIT_R * 16; i += 512) {
        int r = i >> 4, c = i & 15;
        uint32_t d = r * APITCH + c * 16;
        size_t go = ((size_t)r * NPOS + P0) * 2 + c * 16;
        cpasync16(sb + SA_H + d, (const char*)g_corrh + go);
        cpasync16(sb + SA_L + d, (const char*)g_corrl + go);
    }
    asm volatile("cp.async.commit_group;" ::: "memory");
    for (int i = tid + SPLIT_R * 16; i < KPAD * 16; i += 512) {
        int r = i >> 4, c = i & 15;
        uint32_t d = r * APITCH + c * 16;
        size_t go = ((size_t)r * NPOS + P0) * 2 + c * 16;
        cpasync16(sb + SA_H + d, (const char*)g_corrh + go);
        cpasync16(sb + SA_L + d, (const char*)g_corrl + go);
    }
    asm volatile("cp.async.commit_group;" ::: "memory");
    if (tid < 128) {
        int o = o0 + tid;
        float s = gamma[o] * rsqrtf(var[o] + EPS);
        scb[tid] = make_float2(s, beta[o] - mean[o] * s);
    }
    asm volatile("cp.async.wait_group 1;" ::: "memory");
    __syncthreads();

    float acc[2][4][4];
#pragma unroll
    for (int i = 0; i < 2; i++)
#pragma unroll
        for (int j = 0; j < 4; j++)
#pragma unroll
            for (int q = 0; q < 4; q++) acc[i][j][q] = 0.f;

    const uint32_t a_kr = (lane & 7) + ((lane >> 4) << 3);
    const uint32_t a_mr = ((lane >> 3) & 1) << 3;
    const uint32_t b_row0 = wn * 32 + ((lane >> 4) << 3) + (lane & 7);
    const uint32_t b_colb = (((lane >> 3) & 1) << 4);

#pragma unroll 1
    for (int ks = 0; ks < NKS; ks++) {
        if (ks == 7) {
            asm volatile("cp.async.wait_group 0;" ::: "memory");
            __syncthreads();
        }
        uint32_t ah[2][4], al[2][4];
#pragma unroll
        for (int mt = 0; mt < 2; mt++) {
            uint32_t ad = sb + SA_H + (ks * 16 + a_kr) * APITCH
                        + (wm * 32 + mt * 16 + a_mr) * 2;
            ldmat4t(ah[mt], ad);
            ldmat4t(al[mt], ad + ATILE);
        }
#pragma unroll
        for (int np = 0; np < 2; np++) {
            uint32_t bd = sb + SB_H + (b_row0 + np * 16) * BPITCH + ks * 32 + b_colb;
            uint32_t bh[4], bl[4];
            ldmat4(bh, bd);
            ldmat4(bl, bd + BTILE);
#pragma unroll
            for (int mt = 0; mt < 2; mt++) {
                float* c0 = acc[mt][2 * np];
                float* c1 = acc[mt][2 * np + 1];
                mma16816(c0, ah[mt], bh);
                mma16816(c0, al[mt], bh);
                mma16816(c0, ah[mt], bl);
                mma16816(c1, ah[mt], bh + 2);
                mma16816(c1, al[mt], bh + 2);
                mma16816(c1, ah[mt], bl + 2);
            }
        }
    }

    const int b   = (int)(P0 / THW);
    const int tp0 = (int)(P0 % THW);
    const int g = lane >> 2, tq = lane & 3;
#pragma unroll
    for (int mt = 0; mt < 2; mt++) {
        const int pl = wm * 32 + mt * 16 + g;
        const int tp = tp0 + pl;
#pragma unroll
        for (int nt = 0; nt < 4; nt++) {
            const float* c = acc[mt][nt];
            const int ol = wn * 32 + nt * 8 + 2 * tq;
            const float2 s0 = scb[ol];
            const float2 s1 = scb[ol + 1];
            const size_t base0 = ((size_t)b * Cc + (o0 + ol)) * THW + tp;
            const size_t base1 = base0 + THW;
            float r0 = fmaxf(c[0] * s0.x + s0.y + x[base0],     0.f);
            float r1 = fmaxf(c[1] * s1.x + s1.y + x[base1],     0.f);
            float r2 = fmaxf(c[2] * s0.x + s0.y + x[base0 + 8], 0.f);
            float r3 = fmaxf(c[3] * s1.x + s1.y + x[base1 + 8], 0.f);
            out[base0]     = r0;
            out[base1]     = r1;
            out[base0 + 8] = r2;
            out[base1 + 8] = r3;
        }
    }
}

// ---------------------------------------------------------------------------
extern "C" void kernel_launch(void* const* d_in, const int* in_sizes, int n_in,
                              void* d_out, int out_size) {
    const float* x         = (const float*)d_in[0];
    const float* enc_w     = (const float*)d_in[1];
    const float* enc_gamma = (const float*)d_in[2];
    const float* enc_beta  = (const float*)d_in[3];
    const float* enc_mean  = (const float*)d_in[4];
    const float* enc_var   = (const float*)d_in[5];
    const float* fw        = (const float*)d_in[6];
    const float* dec_w     = (const float*)d_in[7];
    const float* dec_gamma = (const float*)d_in[8];
    const float* dec_beta  = (const float*)d_in[9];
    const float* dec_mean  = (const float*)d_in[10];
    const float* dec_var   = (const float*)d_in[11];
    float* out = (float*)d_out;

    cudaFuncSetAttribute(k_encode, cudaFuncAttributeMaxDynamicSharedMemorySize, SMEM_ENC);
    cudaFuncSetAttribute(k_dec, cudaFuncAttributeMaxDynamicSharedMemorySize, SMEM_DEC);

    k_prep<<<KPAD, Cc>>>(dec_w);
    k_prep_enc<<<CE, Cc>>>(enc_w);
    k_encode<<<dim3(THW / 256, Bsz), 512, SMEM_ENC>>>(x, enc_gamma, enc_beta,
                                                      enc_mean, enc_var);
    k_corr<<<Bsz * Tt * 7, 224>>>(fw);
    k_dec<<<dim3(Cc / 128, NPOS / 128), 512, SMEM_DEC>>>(x, dec_gamma, dec_beta,
                                                         dec_mean, dec_var, out);
}

// round 12
// speedup vs baseline: 2.6887x; 1.0035x over previous
#include <cuda_runtime.h>
#include <cuda_bf16.h>
#include <cstdint>

// Problem constants
#define Bsz 4
#define Cc 256
#define CE 64
#define Tt 16
#define Hh 56
#define Ww 56
#define HW (Hh*Ww)            // 3136
#define THW (Tt*HW)           // 50176
#define NPOS (Bsz*THW)        // 200704
#define KK 49
#define K2G 196
#define KPAD 208              // 13 * 16
#define NKS 13
#define EPS 1e-5f

// Scratch. Zero-initialized at load; g_corr rows >= 196 never written -> K pad.
__device__ float g_xenc[(size_t)Bsz * 32 * THW * 2];       // [b][cpair][p][2]
__device__ __nv_bfloat16 g_corrh[(size_t)KPAD * NPOS];     // corr hi [k][pos]
__device__ __nv_bfloat16 g_corrl[(size_t)KPAD * NPOS];     // corr lo [k][pos]
__device__ __nv_bfloat16 g_dwh[Cc * KPAD];                 // dec_w hi [o][208]
__device__ __nv_bfloat16 g_dwl[Cc * KPAD];                 // dec_w lo [o][208]
__device__ __nv_bfloat16 g_ewh[CE * Cc];                   // enc_w hi [ce][256]
__device__ __nv_bfloat16 g_ewl[CE * Cc];                   // enc_w lo [ce][256]

__device__ __forceinline__ uint32_t smem_u32(const void* p) {
    uint32_t a;
    asm("{ .reg .u64 t; cvta.to.shared.u64 t, %1; cvt.u32.u64 %0, t; }"
        : "=r"(a) : "l"(p));
    return a;
}
__device__ __forceinline__ void cpasync16(uint32_t saddr, const void* g) {
    asm volatile("cp.async.cg.shared.global [%0], [%1], 16;"
                 :: "r"(saddr), "l"(g) : "memory");
}
__device__ __forceinline__ void sts8(uint32_t saddr, uint32_t a, uint32_t b) {
    asm volatile("st.shared.v2.b32 [%0], {%1, %2};" :: "r"(saddr), "r"(a), "r"(b)
                 : "memory");
}
__device__ __forceinline__ void ldmat4(uint32_t* d, uint32_t addr) {
    asm volatile("ldmatrix.sync.aligned.m8n8.x4.shared.b16 {%0,%1,%2,%3}, [%4];"
                 : "=r"(d[0]), "=r"(d[1]), "=r"(d[2]), "=r"(d[3]) : "r"(addr));
}
__device__ __forceinline__ void ldmat4t(uint32_t* d, uint32_t addr) {
    asm volatile("ldmatrix.sync.aligned.m8n8.x4.trans.shared.b16 {%0,%1,%2,%3}, [%4];"
                 : "=r"(d[0]), "=r"(d[1]), "=r"(d[2]), "=r"(d[3]) : "r"(addr));
}
__device__ __forceinline__ void mma16816(float* c, const uint32_t* a, const uint32_t* b) {
    asm volatile(
        "mma.sync.aligned.m16n8k16.row.col.f32.bf16.bf16.f32 "
        "{%0,%1,%2,%3}, {%4,%5,%6,%7}, {%8,%9}, {%0,%1,%2,%3};"
        : "+f"(c[0]), "+f"(c[1]), "+f"(c[2]), "+f"(c[3])
        : "r"(a[0]), "r"(a[1]), "r"(a[2]), "r"(a[3]), "r"(b[0]), "r"(b[1]));
}
__device__ __forceinline__ uint32_t packhi(float a, float b, float& ra, float& rb) {
    __nv_bfloat16 ha = __float2bfloat16(a), hb = __float2bfloat16(b);
    ra = a - __bfloat162float(ha);
    rb = b - __bfloat162float(hb);
    return (uint32_t)__bfloat16_as_ushort(ha) |
           ((uint32_t)__bfloat16_as_ushort(hb) << 16);
}
__device__ __forceinline__ uint32_t packbf(float a, float b) {
    return (uint32_t)__bfloat16_as_ushort(__float2bfloat16(a)) |
           ((uint32_t)__bfloat16_as_ushort(__float2bfloat16(b)) << 16);
}

// ---------------------------------------------------------------------------
// Kernel 0a: split dec_w [o][196] -> [o][208] bf16 hi/lo (zero-pad)
// ---------------------------------------------------------------------------
__global__ void k_prep(const float* __restrict__ dw) {
    int k = blockIdx.x;
    int o = threadIdx.x;
    float v = (k < K2G) ? dw[o * K2G + k] : 0.f;
    __nv_bfloat16 h = __float2bfloat16(v);
    float r = v - __bfloat162float(h);
    g_dwh[o * KPAD + k] = h;
    g_dwl[o * KPAD + k] = __float2bfloat16(r);
}
// Kernel 0b: split enc_w [ce][256] -> bf16 hi/lo
__global__ void k_prep_enc(const float* __restrict__ ew) {
    int ce = blockIdx.x;
    int c  = threadIdx.x;
    float v = ew[ce * Cc + c];
    __nv_bfloat16 h = __float2bfloat16(v);
    g_ewh[ce * Cc + c] = h;
    g_ewl[ce * Cc + c] = __float2bfloat16(v - __bfloat162float(h));
}

// ---------------------------------------------------------------------------
// Kernel 1: encode via bf16 hi/lo HMMA (R9 version, proven).
// ---------------------------------------------------------------------------
#define E_PITCH 528
#define E_ATILE (32 * E_PITCH)
#define E_BTILE (64 * E_PITCH)
#define E_OFFB (4 * E_ATILE)
#define E_SCB (E_OFFB + 2 * E_BTILE)
#define SMEM_ENC (E_SCB + 512)

__global__ void __launch_bounds__(512, 1) k_encode(
    const float* __restrict__ x,
    const float* __restrict__ gamma, const float* __restrict__ beta,
    const float* __restrict__ mean, const float* __restrict__ var) {
    extern __shared__ __align__(16) char sm[];
    const uint32_t sb = smem_u32(sm);
    float2* scb = reinterpret_cast<float2*>(sm + E_SCB);
    const int tid  = threadIdx.x;
    const int wid  = tid >> 5;
    const int lane = tid & 31;
    const int b  = blockIdx.y;
    const int P0 = blockIdx.x * 256;
    const int wm = wid & 7;
    const int wn = wid >> 3;

    for (int i = tid; i < 64 * 32; i += 512) {
        int r = i >> 5, c = i & 31;
        uint32_t d = sb + E_OFFB + r * E_PITCH + c * 16;
        size_t go = (size_t)r * 512 + c * 16;
        cpasync16(d,           (const char*)g_ewh + go);
        cpasync16(d + E_BTILE, (const char*)g_ewl + go);
    }
    asm volatile("cp.async.commit_group;" ::: "memory");
    if (tid < 64) {
        float s = gamma[tid] * rsqrtf(var[tid] + EPS);
        scb[tid] = make_float2(s, beta[tid] - mean[tid] * s);
    }

    const float* xb = x + (size_t)b * Cc * THW + P0;
    const int st_r  = tid >> 6;
    const int st_c4 = (tid & 63) * 4;

#pragma unroll
    for (int e = 0; e < 4; e++) {
        int r = st_r + 8 * e;
        float4 v = *reinterpret_cast<const float4*>(xb + (size_t)r * THW + st_c4);
        float rx, ry, rz, rw;
        uint32_t h0 = packhi(v.x, v.y, rx, ry);
        uint32_t h1 = packhi(v.z, v.w, rz, rw);
        uint32_t d = sb + r * E_PITCH + st_c4 * 2;
        sts8(d, h0, h1);
        sts8(d + E_ATILE, packbf(rx, ry), packbf(rz, rw));
    }
    asm volatile("cp.async.wait_group 0;" ::: "memory");
    __syncthreads();

    float acc[2][4][4];
#pragma unroll
    for (int i = 0; i < 2; i++)
#pragma unroll
        for (int j = 0; j < 4; j++)
#pragma unroll
            for (int q = 0; q < 4; q++) acc[i][j][q] = 0.f;

    const uint32_t a_kr = (lane & 7) + ((lane >> 4) << 3);
    const uint32_t a_mr = ((lane >> 3) & 1) << 3;
    const uint32_t b_row0 = wn * 32 + ((lane >> 4) << 3) + (lane & 7);
    const uint32_t b_colb = (((lane >> 3) & 1) << 4);

#pragma unroll 1
    for (int kc = 0; kc < 8; kc++) {
        float4 v[4];
        if (kc < 7) {
            const float* xk = xb + (size_t)(kc + 1) * 32 * THW;
#pragma unroll
            for (int e = 0; e < 4; e++)
                v[e] = *reinterpret_cast<const float4*>(
                    xk + (size_t)(st_r + 8 * e) * THW + st_c4);
        }
        const uint32_t ab = sb + (kc & 1) * (2 * E_ATILE);
#pragma unroll
        for (int ks2 = 0; ks2 < 2; ks2++) {
            uint32_t ah[2][4], al[2][4];
#pragma unroll
            for (int mt = 0; mt < 2; mt++) {
                uint32_t ad = ab + (ks2 * 16 + a_kr) * E_PITCH
                            + (wm * 32 + mt * 16 + a_mr) * 2;
                ldmat4t(ah[mt], ad);
                ldmat4t(al[mt], ad + E_ATILE);
            }
#pragma unroll
            for (int np = 0; np < 2; np++) {
                uint32_t bd = sb + E_OFFB + (b_row0 + np * 16) * E_PITCH
                            + (kc * 32 + ks2 * 16) * 2 + b_colb;
                uint32_t bh[4], bl[4];
                ldmat4(bh, bd);
                ldmat4(bl, bd + E_BTILE);
#pragma unroll
                for (int mt = 0; mt < 2; mt++) {
                    float* c0 = acc[mt][2 * np];
                    float* c1 = acc[mt][2 * np + 1];
                    mma16816(c0, ah[mt], bh);
                    mma16816(c0, al[mt], bh);
                    mma16816(c0, ah[mt], bl);
                    mma16816(c1, ah[mt], bh + 2);
                    mma16816(c1, al[mt], bh + 2);
                    mma16816(c1, ah[mt], bl + 2);
                }
            }
        }
        __syncthreads();
        if (kc < 7) {
            const uint32_t nb = sb + ((kc + 1) & 1) * (2 * E_ATILE);
#pragma unroll
            for (int e = 0; e < 4; e++) {
                int r = st_r + 8 * e;
                float rx, ry, rz, rw;
                uint32_t h0 = packhi(v[e].x, v[e].y, rx, ry);
                uint32_t h1 = packhi(v[e].z, v[e].w, rz, rw);
                uint32_t d = nb + r * E_PITCH + st_c4 * 2;
                sts8(d, h0, h1);
                sts8(d + E_ATILE, packbf(rx, ry), packbf(rz, rw));
            }
            __syncthreads();
        }
    }

    const int g = lane >> 2, tq = lane & 3;
#pragma unroll
    for (int mt = 0; mt < 2; mt++) {
        const int p = P0 + wm * 32 + mt * 16 + g;
#pragma unroll
        for (int nt = 0; nt < 4; nt++) {
            const float* c = acc[mt][nt];
            const int ol = wn * 32 + nt * 8 + 2 * tq;
            const float2 s0 = scb[ol];
            const float2 s1 = scb[ol + 1];
            const int cp = ol >> 1;
            float* base = &g_xenc[(((size_t)b * 32 + cp) * THW + p) * 2];
            float2 v0, v1;
            v0.x = fmaxf(c[0] * s0.x + s0.y, 0.f);
            v0.y = fmaxf(c[1] * s1.x + s1.y, 0.f);
            v1.x = fmaxf(c[2] * s0.x + s0.y, 0.f);
            v1.y = fmaxf(c[3] * s1.x + s1.y, 0.f);
            *reinterpret_cast<float2*>(base)      = v0;
            *reinterpret_cast<float2*>(base + 16) = v1;
        }
    }
}

// ---------------------------------------------------------------------------
// Kernel 2: correlation (R11 version, 170us).
// ---------------------------------------------------------------------------
__global__ void __launch_bounds__(224, 2) k_corr(const float* __restrict__ fw) {
    __shared__ __align__(16) float2 fws2[32 * KK];
    __shared__ __align__(16) float2 buf[2][14][64];
    const int tid = threadIdx.x;
    const int bx = blockIdx.x;
    const int h0 = (bx % 7) * 8;
    const int t  = (bx / 7) % Tt;
    const int b  = bx / (7 * Tt);
    const int a  = tid / 56;
    const int w  = tid % 56;
    const int jA = 2 * a;
    const int hA = h0 + jA;
    const int t1 = (t == 0) ? 0 : t - 1;

    for (int idx = tid; idx < 32 * KK; idx += 224) {
        int cp = idx / KK, ko = idx % KK;
        int c = cp * 2;
        fws2[idx] = make_float2(fw[(c * Tt + t) * KK + ko],
                                fw[((c + 1) * Tt + t) * KK + ko]);
    }

    const float2* xe = reinterpret_cast<const float2*>(g_xenc);
    const size_t cstride = THW;
    const size_t cb0 = (size_t)(b * 32) * cstride;

    int je[4], me[4];
    bool in[4];
    size_t off[4];
#pragma unroll
    for (int e = 0; e < 4; e++) {
        int idx = tid + 224 * e;
        int j = idx >> 6, m = idx & 63;
        je[e] = j; me[e] = m;
        int gh = h0 + j - 3, gx = m - 3;
        in[e] = (unsigned)gh < (unsigned)Hh && (unsigned)gx < (unsigned)Ww;
        off[e] = (size_t)t * HW + (size_t)gh * Ww + gx;
    }
    const size_t x1offA = (size_t)t1 * HW + (size_t)hA * Ww + w;
    const size_t posA   = ((size_t)(b * Tt + t) * Hh + hA) * Ww + w;

    float accA[KK], accB[KK];
#pragma unroll
    for (int i = 0; i < KK; i++) { accA[i] = 0.f; accB[i] = 0.f; }

    float2 pf[4], x1Ac, x1Bc, x1An, x1Bn;
#pragma unroll
    for (int e = 0; e < 4; e++)
        pf[e] = in[e] ? xe[cb0 + off[e]] : make_float2(0.f, 0.f);
    x1Ac = xe[cb0 + x1offA];
    x1Bc = xe[cb0 + x1offA + Ww];
#pragma unroll
    for (int e = 0; e < 4; e++) buf[0][je[e]][me[e]] = pf[e];
    __syncthreads();

#pragma unroll 1
    for (int s = 0; s < 32; s++) {
        const size_t cbn = cb0 + (size_t)(s + 1) * cstride;
        if (s < 31) {
#pragma unroll
            for (int e = 0; e < 4; e++)
                pf[e] = in[e] ? xe[cbn + off[e]] : make_float2(0.f, 0.f);
            x1An = xe[cbn + x1offA];
            x1Bn = xe[cbn + x1offA + Ww];
        }
        const float2* fp = &fws2[s * KK];
        const float2 (*bw)[64] = buf[s & 1];
#pragma unroll
        for (int kx = 0; kx < 7; kx++) {
            float2 fcol[7];
#pragma unroll
            for (int r = 0; r < 7; r++) fcol[r] = fp[r * 7 + kx];
#pragma unroll
            for (int r = 0; r < 8; r++) {
                float2 v = bw[jA + r][w + kx];
                if (r < 7)
                    accA[r * 7 + kx] += fcol[r].x * x1Ac.x * v.x
                                      + fcol[r].y * x1Ac.y * v.y;
                if (r >= 1)
                    accB[(r - 1) * 7 + kx] += fcol[r - 1].x * x1Bc.x * v.x
                                            + fcol[r - 1].y * x1Bc.y * v.y;
            }
        }
        if ((s & 7) == 7) {
            const int g4 = s >> 3;
#pragma unroll
            for (int ko = 0; ko < KK; ko++) {
                size_t row = (size_t)(ko * 4 + g4) * NPOS;
                float vA = accA[ko] * 0.0625f;
                __nv_bfloat16 hA2 = __float2bfloat16(vA);
                g_corrh[row + posA] = hA2;
                g_corrl[row + posA] = __float2bfloat16(vA - __bfloat162float(hA2));
                float vB = accB[ko] * 0.0625f;
                __nv_bfloat16 hB2 = __float2bfloat16(vB);
                g_corrh[row + posA + Ww] = hB2;
                g_corrl[row + posA + Ww] = __float2bfloat16(vB - __bfloat162float(hB2));
                accA[ko] = 0.f;
                accB[ko] = 0.f;
            }
        }
        if (s < 31) {
#pragma unroll
            for (int e = 0; e < 4; e++) buf[(s + 1) & 1][je[e]][me[e]] = pf[e];
            x1Ac = x1An;
            x1Bc = x1Bn;
        }
        __syncthreads();
    }
}

// ---------------------------------------------------------------------------
// Kernel 3: decode v5 — CTA 64p x 64o, BOTH operands full-K resident,
// 115,200B smem -> 2 CTAs/SM so staging/epilogue of one CTA overlaps MMA of
// the other. 256 threads, warp tile 32p x 16o, zero mainloop barriers.
// Grid (4 o-tiles fastest, 3136 p-tiles) -> A reused x4 via L2.
// ---------------------------------------------------------------------------
#define D_APITCH 144                     // 64p*2B + 16 pad
#define D_ATILE (KPAD * D_APITCH)        // 29952
#define D_BPITCH 432                     // 208k*2B + 16 pad
#define D_BTILE (64 * D_BPITCH)          // 27648
#define D_SA_H 0
#define D_SA_L D_ATILE
#define D_SB_H (2 * D_ATILE)             // 59904
#define D_SB_L (2 * D_ATILE + D_BTILE)   // 87552
#define SMEM_DEC (2 * D_ATILE + 2 * D_BTILE)  // 115200
#define D_SPLIT 112                      // A rows in phase 1 (7 k-chunks)

__global__ void __launch_bounds__(256, 2) k_dec(
    const float* __restrict__ x,
    const float* __restrict__ gamma, const float* __restrict__ beta,
    const float* __restrict__ mean, const float* __restrict__ var,
    float* __restrict__ out) {
    extern __shared__ __align__(16) char sm[];
    const uint32_t sb = smem_u32(sm);
    const int tid  = threadIdx.x;
    const int wid  = tid >> 5;
    const int lane = tid & 31;
    const size_t P0 = (size_t)blockIdx.y * 64;   // p-tile (slow)
    const int o0 = blockIdx.x * 64;              // o-tile (fast)
    const int wm = wid & 1;            // p: 2 x 32
    const int wn = wid >> 1;           // o: 4 x 16

    // Phase 1: B (all 64 rows x 26 uint4) + A rows [0, 112)
    for (int i = tid; i < 64 * 26; i += 256) {
        int r = i / 26, c = i % 26;
        uint32_t d = r * D_BPITCH + c * 16;
        size_t go = ((size_t)(o0 + r) * KPAD) * 2 + c * 16;
        cpasync16(sb + D_SB_H + d, (const char*)g_dwh + go);
        cpasync16(sb + D_SB_L + d, (const char*)g_dwl + go);
    }
    for (int i = tid; i < D_SPLIT * 8; i += 256) {
        int r = i >> 3, c = i & 7;
        uint32_t d = r * D_APITCH + c * 16;
        size_t go = ((size_t)r * NPOS + P0) * 2 + c * 16;
        cpasync16(sb + D_SA_H + d, (const char*)g_corrh + go);
        cpasync16(sb + D_SA_L + d, (const char*)g_corrl + go);
    }
    asm volatile("cp.async.commit_group;" ::: "memory");
    // Phase 2: A rows [112, 208)
    for (int i = tid + D_SPLIT * 8; i < KPAD * 8; i += 256) {
        int r = i >> 3, c = i & 7;
        uint32_t d = r * D_APITCH + c * 16;
        size_t go = ((size_t)r * NPOS + P0) * 2 + c * 16;
        cpasync16(sb + D_SA_H + d, (const char*)g_corrh + go);
        cpasync16(sb + D_SA_L + d, (const char*)g_corrl + go);
    }
    asm volatile("cp.async.commit_group;" ::: "memory");
    asm volatile("cp.async.wait_group 1;" ::: "memory");
    __syncthreads();

    float acc[2][2][4];   // [mt][oct][frag]
#pragma unroll
    for (int i = 0; i < 2; i++)
#pragma unroll
        for (int j = 0; j < 2; j++)
#pragma unroll
            for (int q = 0; q < 4; q++) acc[i][j][q] = 0.f;

    const uint32_t a_kr = (lane & 7) + ((lane >> 4) << 3);
    const uint32_t a_mr = ((lane >> 3) & 1) << 3;
    const uint32_t b_row0 = wn * 16 + ((lane >> 4) << 3) + (lane & 7);
    const uint32_t b_colb = (((lane >> 3) & 1) << 4);

#pragma unroll 1
    for (int ks = 0; ks < NKS; ks++) {
        if (ks == 7) {
            asm volatile("cp.async.wait_group 0;" ::: "memory");
            __syncthreads();
        }
        uint32_t ah[2][4], al[2][4];
#pragma unroll
        for (int mt = 0; mt < 2; mt++) {
            uint32_t ad = sb + D_SA_H + (ks * 16 + a_kr) * D_APITCH
                        + (wm * 32 + mt * 16 + a_mr) * 2;
            ldmat4t(ah[mt], ad);
            ldmat4t(al[mt], ad + D_ATILE);
        }
        uint32_t bh[4], bl[4];
        {
            uint32_t bd = sb + D_SB_H + b_row0 * D_BPITCH + ks * 32 + b_colb;
            ldmat4(bh, bd);
            ldmat4(bl, bd + D_BTILE);
        }
#pragma unroll
        for (int mt = 0; mt < 2; mt++)
#pragma unroll
            for (int oct = 0; oct < 2; oct++) {
                float* c = acc[mt][oct];
                mma16816(c, ah[mt], bh + 2 * oct);
                mma16816(c, al[mt], bh + 2 * oct);
                mma16816(c, ah[mt], bl + 2 * oct);
            }
    }

    // Epilogue: bn + residual + relu, out[b][o][tp].
    const int bb  = (int)(P0 / THW);
    const int tp0 = (int)(P0 % THW);
    const int g = lane >> 2, tq = lane & 3;
#pragma unroll
    for (int oct = 0; oct < 2; oct++) {
        const int ol = wn * 16 + oct * 8 + 2 * tq;
        const int o = o0 + ol;
        const float s0 = gamma[o] * rsqrtf(var[o] + EPS);
        const float bi0 = beta[o] - mean[o] * s0;
        const float s1 = gamma[o + 1] * rsqrtf(var[o + 1] + EPS);
        const float bi1 = beta[o + 1] - mean[o + 1] * s1;
#pragma unroll
        for (int mt = 0; mt < 2; mt++) {
            const float* c = acc[mt][oct];
            const int tp = tp0 + wm * 32 + mt * 16 + g;
            const size_t base0 = ((size_t)bb * Cc + o) * THW + tp;
            const size_t base1 = base0 + THW;
            float r0 = fmaxf(c[0] * s0 + bi0 + x[base0],     0.f);
            float r1 = fmaxf(c[1] * s1 + bi1 + x[base1],     0.f);
            float r2 = fmaxf(c[2] * s0 + bi0 + x[base0 + 8], 0.f);
            float r3 = fmaxf(c[3] * s1 + bi1 + x[base1 + 8], 0.f);
            out[base0]     = r0;
            out[base1]     = r1;
            out[base0 + 8] = r2;
            out[base1 + 8] = r3;
        }
    }
}

// ---------------------------------------------------------------------------
extern "C" void kernel_launch(void* const* d_in, const int* in_sizes, int n_in,
                              void* d_out, int out_size) {
    const float* x         = (const float*)d_in[0];
    const float* enc_w     = (const float*)d_in[1];
    const float* enc_gamma = (const float*)d_in[2];
    const float* enc_beta  = (const float*)d_in[3];
    const float* enc_mean  = (const float*)d_in[4];
    const float* enc_var   = (const float*)d_in[5];
    const float* fw        = (const float*)d_in[6];
    const float* dec_w     = (const float*)d_in[7];
    const float* dec_gamma = (const float*)d_in[8];
    const float* dec_beta  = (const float*)d_in[9];
    const float* dec_mean  = (const float*)d_in[10];
    const float* dec_var   = (const float*)d_in[11];
    float* out = (float*)d_out;

    cudaFuncSetAttribute(k_encode, cudaFuncAttributeMaxDynamicSharedMemorySize, SMEM_ENC);
    cudaFuncSetAttribute(k_dec, cudaFuncAttributeMaxDynamicSharedMemorySize, SMEM_DEC);

    k_prep<<<KPAD, Cc>>>(dec_w);
    k_prep_enc<<<CE, Cc>>>(enc_w);
    k_encode<<<dim3(THW / 256, Bsz), 512, SMEM_ENC>>>(x, enc_gamma, enc_beta,
                                                      enc_mean, enc_var);
    k_corr<<<Bsz * Tt * 7, 224>>>(fw);
    k_dec<<<dim3(Cc / 64, NPOS / 64), 256, SMEM_DEC>>>(x, dec_gamma, dec_beta,
                                                       dec_mean, dec_var, out);
}

// round 13
// speedup vs baseline: 2.7969x; 1.0402x over previous
#include <cuda_runtime.h>
#include <cuda_bf16.h>
#include <cstdint>

// Problem constants
#define Bsz 4
#define Cc 256
#define CE 64
#define Tt 16
#define Hh 56
#define Ww 56
#define HW (Hh*Ww)            // 3136
#define THW (Tt*HW)           // 50176
#define NPOS (Bsz*THW)        // 200704
#define KK 49
#define K2G 196
#define KPAD 224              // 7 chunks of 32
#define EPS 1e-5f

// Scratch. Zero-initialized at load; g_corr rows >= 196 never written -> K pad.
__device__ float g_xenc[(size_t)Bsz * 32 * THW * 2];       // [b][cpair][p][2]
__device__ __nv_bfloat16 g_corrh[(size_t)KPAD * NPOS];     // corr hi [k][pos]
__device__ __nv_bfloat16 g_corrl[(size_t)KPAD * NPOS];     // corr lo [k][pos]
__device__ __nv_bfloat16 g_dwh[Cc * KPAD];                 // dec_w hi [o][224]
__device__ __nv_bfloat16 g_dwl[Cc * KPAD];                 // dec_w lo [o][224]
__device__ __nv_bfloat16 g_ewh[CE * Cc];                   // enc_w hi [ce][256]
__device__ __nv_bfloat16 g_ewl[CE * Cc];                   // enc_w lo [ce][256]

__device__ __forceinline__ uint32_t smem_u32(const void* p) {
    uint32_t a;
    asm("{ .reg .u64 t; cvta.to.shared.u64 t, %1; cvt.u32.u64 %0, t; }"
        : "=r"(a) : "l"(p));
    return a;
}
__device__ __forceinline__ void cpasync16(uint32_t saddr, const void* g) {
    asm volatile("cp.async.cg.shared.global [%0], [%1], 16;"
                 :: "r"(saddr), "l"(g) : "memory");
}
__device__ __forceinline__ void sts8(uint32_t saddr, uint32_t a, uint32_t b) {
    asm volatile("st.shared.v2.b32 [%0], {%1, %2};" :: "r"(saddr), "r"(a), "r"(b)
                 : "memory");
}
__device__ __forceinline__ void ldmat4(uint32_t* d, uint32_t addr) {
    asm volatile("ldmatrix.sync.aligned.m8n8.x4.shared.b16 {%0,%1,%2,%3}, [%4];"
                 : "=r"(d[0]), "=r"(d[1]), "=r"(d[2]), "=r"(d[3]) : "r"(addr));
}
__device__ __forceinline__ void ldmat4t(uint32_t* d, uint32_t addr) {
    asm volatile("ldmatrix.sync.aligned.m8n8.x4.trans.shared.b16 {%0,%1,%2,%3}, [%4];"
                 : "=r"(d[0]), "=r"(d[1]), "=r"(d[2]), "=r"(d[3]) : "r"(addr));
}
__device__ __forceinline__ void mma16816(float* c, const uint32_t* a, const uint32_t* b) {
    asm volatile(
        "mma.sync.aligned.m16n8k16.row.col.f32.bf16.bf16.f32 "
        "{%0,%1,%2,%3}, {%4,%5,%6,%7}, {%8,%9}, {%0,%1,%2,%3};"
        : "+f"(c[0]), "+f"(c[1]), "+f"(c[2]), "+f"(c[3])
        : "r"(a[0]), "r"(a[1]), "r"(a[2]), "r"(a[3]), "r"(b[0]), "r"(b[1]));
}
__device__ __forceinline__ uint32_t packhi(float a, float b, float& ra, float& rb) {
    __nv_bfloat16 ha = __float2bfloat16(a), hb = __float2bfloat16(b);
    ra = a - __bfloat162float(ha);
    rb = b - __bfloat162float(hb);
    return (uint32_t)__bfloat16_as_ushort(ha) |
           ((uint32_t)__bfloat16_as_ushort(hb) << 16);
}
__device__ __forceinline__ uint32_t packbf(float a, float b) {
    return (uint32_t)__bfloat16_as_ushort(__float2bfloat16(a)) |
           ((uint32_t)__bfloat16_as_ushort(__float2bfloat16(b)) << 16);
}

// ---------------------------------------------------------------------------
// Kernel 0a: split dec_w [o][196] -> [o][224] bf16 hi/lo (zero-pad)
// ---------------------------------------------------------------------------
__global__ void k_prep(const float* __restrict__ dw) {
    int k = blockIdx.x;   // 0..223
    int o = threadIdx.x;
    float v = (k < K2G) ? dw[o * K2G + k] : 0.f;
    __nv_bfloat16 h = __float2bfloat16(v);
    float r = v - __bfloat162float(h);
    g_dwh[o * KPAD + k] = h;
    g_dwl[o * KPAD + k] = __float2bfloat16(r);
}
// Kernel 0b: split enc_w [ce][256] -> bf16 hi/lo
__global__ void k_prep_enc(const float* __restrict__ ew) {
    int ce = blockIdx.x;
    int c  = threadIdx.x;
    float v = ew[ce * Cc + c];
    __nv_bfloat16 h = __float2bfloat16(v);
    g_ewh[ce * Cc + c] = h;
    g_ewl[ce * Cc + c] = __float2bfloat16(v - __bfloat162float(h));
}

// ---------------------------------------------------------------------------
// Kernel 1: encode via bf16 hi/lo HMMA (R9 version, proven).
// ---------------------------------------------------------------------------
#define E_PITCH 528
#define E_ATILE (32 * E_PITCH)
#define E_BTILE (64 * E_PITCH)
#define E_OFFB (4 * E_ATILE)
#define E_SCB (E_OFFB + 2 * E_BTILE)
#define SMEM_ENC (E_SCB + 512)

__global__ void __launch_bounds__(512, 1) k_encode(
    const float* __restrict__ x,
    const float* __restrict__ gamma, const float* __restrict__ beta,
    const float* __restrict__ mean, const float* __restrict__ var) {
    extern __shared__ __align__(16) char sm[];
    const uint32_t sb = smem_u32(sm);
    float2* scb = reinterpret_cast<float2*>(sm + E_SCB);
    const int tid  = threadIdx.x;
    const int wid  = tid >> 5;
    const int lane = tid & 31;
    const int b  = blockIdx.y;
    const int P0 = blockIdx.x * 256;
    const int wm = wid & 7;
    const int wn = wid >> 3;

    for (int i = tid; i < 64 * 32; i += 512) {
        int r = i >> 5, c = i & 31;
        uint32_t d = sb + E_OFFB + r * E_PITCH + c * 16;
        size_t go = (size_t)r * 512 + c * 16;
        cpasync16(d,           (const char*)g_ewh + go);
        cpasync16(d + E_BTILE, (const char*)g_ewl + go);
    }
    asm volatile("cp.async.commit_group;" ::: "memory");
    if (tid < 64) {
        float s = gamma[tid] * rsqrtf(var[tid] + EPS);
        scb[tid] = make_float2(s, beta[tid] - mean[tid] * s);
    }

    const float* xb = x + (size_t)b * Cc * THW + P0;
    const int st_r  = tid >> 6;
    const int st_c4 = (tid & 63) * 4;

#pragma unroll
    for (int e = 0; e < 4; e++) {
        int r = st_r + 8 * e;
        float4 v = *reinterpret_cast<const float4*>(xb + (size_t)r * THW + st_c4);
        float rx, ry, rz, rw;
        uint32_t h0 = packhi(v.x, v.y, rx, ry);
        uint32_t h1 = packhi(v.z, v.w, rz, rw);
        uint32_t d = sb + r * E_PITCH + st_c4 * 2;
        sts8(d, h0, h1);
        sts8(d + E_ATILE, packbf(rx, ry), packbf(rz, rw));
    }
    asm volatile("cp.async.wait_group 0;" ::: "memory");
    __syncthreads();

    float acc[2][4][4];
#pragma unroll
    for (int i = 0; i < 2; i++)
#pragma unroll
        for (int j = 0; j < 4; j++)
#pragma unroll
            for (int q = 0; q < 4; q++) acc[i][j][q] = 0.f;

    const uint32_t a_kr = (lane & 7) + ((lane >> 4) << 3);
    const uint32_t a_mr = ((lane >> 3) & 1) << 3;
    const uint32_t b_row0 = wn * 32 + ((lane >> 4) << 3) + (lane & 7);
    const uint32_t b_colb = (((lane >> 3) & 1) << 4);

#pragma unroll 1
    for (int kc = 0; kc < 8; kc++) {
        float4 v[4];
        if (kc < 7) {
            const float* xk = xb + (size_t)(kc + 1) * 32 * THW;
#pragma unroll
            for (int e = 0; e < 4; e++)
                v[e] = *reinterpret_cast<const float4*>(
                    xk + (size_t)(st_r + 8 * e) * THW + st_c4);
        }
        const uint32_t ab = sb + (kc & 1) * (2 * E_ATILE);
#pragma unroll
        for (int ks2 = 0; ks2 < 2; ks2++) {
            uint32_t ah[2][4], al[2][4];
#pragma unroll
            for (int mt = 0; mt < 2; mt++) {
                uint32_t ad = ab + (ks2 * 16 + a_kr) * E_PITCH
                            + (wm * 32 + mt * 16 + a_mr) * 2;
                ldmat4t(ah[mt], ad);
                ldmat4t(al[mt], ad + E_ATILE);
            }
#pragma unroll
            for (int np = 0; np < 2; np++) {
                uint32_t bd = sb + E_OFFB + (b_row0 + np * 16) * E_PITCH
                            + (kc * 32 + ks2 * 16) * 2 + b_colb;
                uint32_t bh[4], bl[4];
                ldmat4(bh, bd);
                ldmat4(bl, bd + E_BTILE);
#pragma unroll
                for (int mt = 0; mt < 2; mt++) {
                    float* c0 = acc[mt][2 * np];
                    float* c1 = acc[mt][2 * np + 1];
                    mma16816(c0, ah[mt], bh);
                    mma16816(c0, al[mt], bh);
                    mma16816(c0, ah[mt], bl);
                    mma16816(c1, ah[mt], bh + 2);
                    mma16816(c1, al[mt], bh + 2);
                    mma16816(c1, ah[mt], bl + 2);
                }
            }
        }
        __syncthreads();
        if (kc < 7) {
            const uint32_t nb = sb + ((kc + 1) & 1) * (2 * E_ATILE);
#pragma unroll
            for (int e = 0; e < 4; e++) {
                int r = st_r + 8 * e;
                float rx, ry, rz, rw;
                uint32_t h0 = packhi(v[e].x, v[e].y, rx, ry);
                uint32_t h1 = packhi(v[e].z, v[e].w, rz, rw);
                uint32_t d = nb + r * E_PITCH + st_c4 * 2;
                sts8(d, h0, h1);
                sts8(d + E_ATILE, packbf(rx, ry), packbf(rz, rw));
            }
            __syncthreads();
        }
    }

    const int g = lane >> 2, tq = lane & 3;
#pragma unroll
    for (int mt = 0; mt < 2; mt++) {
        const int p = P0 + wm * 32 + mt * 16 + g;
#pragma unroll
        for (int nt = 0; nt < 4; nt++) {
            const float* c = acc[mt][nt];
            const int ol = wn * 32 + nt * 8 + 2 * tq;
            const float2 s0 = scb[ol];
            const float2 s1 = scb[ol + 1];
            const int cp = ol >> 1;
            float* base = &g_xenc[(((size_t)b * 32 + cp) * THW + p) * 2];
            float2 v0, v1;
            v0.x = fmaxf(c[0] * s0.x + s0.y, 0.f);
            v0.y = fmaxf(c[1] * s1.x + s1.y, 0.f);
            v1.x = fmaxf(c[2] * s0.x + s0.y, 0.f);
            v1.y = fmaxf(c[3] * s1.x + s1.y, 0.f);
            *reinterpret_cast<float2*>(base)      = v0;
            *reinterpret_cast<float2*>(base + 16) = v1;
        }
    }
}

// ---------------------------------------------------------------------------
// Kernel 2: correlation (R11 version, 170us).
// ---------------------------------------------------------------------------
__global__ void __launch_bounds__(224, 2) k_corr(const float* __restrict__ fw) {
    __shared__ __align__(16) float2 fws2[32 * KK];
    __shared__ __align__(16) float2 buf[2][14][64];
    const int tid = threadIdx.x;
    const int bx = blockIdx.x;
    const int h0 = (bx % 7) * 8;
    const int t  = (bx / 7) % Tt;
    const int b  = bx / (7 * Tt);
    const int a  = tid / 56;
    const int w  = tid % 56;
    const int jA = 2 * a;
    const int hA = h0 + jA;
    const int t1 = (t == 0) ? 0 : t - 1;

    for (int idx = tid; idx < 32 * KK; idx += 224) {
        int cp = idx / KK, ko = idx % KK;
        int c = cp * 2;
        fws2[idx] = make_float2(fw[(c * Tt + t) * KK + ko],
                                fw[((c + 1) * Tt + t) * KK + ko]);
    }

    const float2* xe = reinterpret_cast<const float2*>(g_xenc);
    const size_t cstride = THW;
    const size_t cb0 = (size_t)(b * 32) * cstride;

    int je[4], me[4];
    bool in[4];
    size_t off[4];
#pragma unroll
    for (int e = 0; e < 4; e++) {
        int idx = tid + 224 * e;
        int j = idx >> 6, m = idx & 63;
        je[e] = j; me[e] = m;
        int gh = h0 + j - 3, gx = m - 3;
        in[e] = (unsigned)gh < (unsigned)Hh && (unsigned)gx < (unsigned)Ww;
        off[e] = (size_t)t * HW + (size_t)gh * Ww + gx;
    }
    const size_t x1offA = (size_t)t1 * HW + (size_t)hA * Ww + w;
    const size_t posA   = ((size_t)(b * Tt + t) * Hh + hA) * Ww + w;

    float accA[KK], accB[KK];
#pragma unroll
    for (int i = 0; i < KK; i++) { accA[i] = 0.f; accB[i] = 0.f; }

    float2 pf[4], x1Ac, x1Bc, x1An, x1Bn;
#pragma unroll
    for (int e = 0; e < 4; e++)
        pf[e] = in[e] ? xe[cb0 + off[e]] : make_float2(0.f, 0.f);
    x1Ac = xe[cb0 + x1offA];
    x1Bc = xe[cb0 + x1offA + Ww];
#pragma unroll
    for (int e = 0; e < 4; e++) buf[0][je[e]][me[e]] = pf[e];
    __syncthreads();

#pragma unroll 1
    for (int s = 0; s < 32; s++) {
        const size_t cbn = cb0 + (size_t)(s + 1) * cstride;
        if (s < 31) {
#pragma unroll
            for (int e = 0; e < 4; e++)
                pf[e] = in[e] ? xe[cbn + off[e]] : make_float2(0.f, 0.f);
            x1An = xe[cbn + x1offA];
            x1Bn = xe[cbn + x1offA + Ww];
        }
        const float2* fp = &fws2[s * KK];
        const float2 (*bw)[64] = buf[s & 1];
#pragma unroll
        for (int kx = 0; kx < 7; kx++) {
            float2 fcol[7];
#pragma unroll
            for (int r = 0; r < 7; r++) fcol[r] = fp[r * 7 + kx];
#pragma unroll
            for (int r = 0; r < 8; r++) {
                float2 v = bw[jA + r][w + kx];
                if (r < 7)
                    accA[r * 7 + kx] += fcol[r].x * x1Ac.x * v.x
                                      + fcol[r].y * x1Ac.y * v.y;
                if (r >= 1)
                    accB[(r - 1) * 7 + kx] += fcol[r - 1].x * x1Bc.x * v.x
                                            + fcol[r - 1].y * x1Bc.y * v.y;
            }
        }
        if ((s & 7) == 7) {
            const int g4 = s >> 3;
#pragma unroll
            for (int ko = 0; ko < KK; ko++) {
                size_t row = (size_t)(ko * 4 + g4) * NPOS;
                float vA = accA[ko] * 0.0625f;
                __nv_bfloat16 hA2 = __float2bfloat16(vA);
                g_corrh[row + posA] = hA2;
                g_corrl[row + posA] = __float2bfloat16(vA - __bfloat162float(hA2));
                float vB = accB[ko] * 0.0625f;
                __nv_bfloat16 hB2 = __float2bfloat16(vB);
                g_corrh[row + posA + Ww] = hB2;
                g_corrl[row + posA + Ww] = __float2bfloat16(vB - __bfloat162float(hB2));
                accA[ko] = 0.f;
                accB[ko] = 0.f;
            }
        }
        if (s < 31) {
#pragma unroll
            for (int e = 0; e < 4; e++) buf[(s + 1) & 1][je[e]][me[e]] = pf[e];
            x1Ac = x1An;
            x1Bc = x1Bn;
        }
        __syncthreads();
    }
}

// ---------------------------------------------------------------------------
// Kernel 3: decode v6 — CTA 128p x 128o, 256 threads (8 warps, 32p x 64o),
// K=224 in 7 chunks of 32, 3-stage cp.async ring, ONE barrier per chunk,
// smem 114.7KB -> 2 CTAs/SM (cross-CTA overlap of waits with MMA).
// ---------------------------------------------------------------------------
#define D_NKC 7
#define D_AP 272                         // A stage pitch: 128p*2B + 16
#define D_ASTG (32 * D_AP)               // 8704  (one of hi/lo)
#define D_APAIR (2 * D_ASTG)             // 17408
#define D_BP 80                          // B stage pitch: 32k*2B + 16
#define D_BSTG (128 * D_BP)              // 10240
#define D_BPAIR (2 * D_BSTG)             // 20480
#define D_OFFB (3 * D_APAIR)             // 52224
#define D_SCB (D_OFFB + 3 * D_BPAIR)     // 113664
#define SMEM_DEC (D_SCB + 1024)          // 114688

__global__ void __launch_bounds__(256, 2) k_dec(
    const float* __restrict__ x,
    const float* __restrict__ gamma, const float* __restrict__ beta,
    const float* __restrict__ mean, const float* __restrict__ var,
    float* __restrict__ out) {
    extern __shared__ __align__(16) char sm[];
    const uint32_t sb = smem_u32(sm);
    float2* scb = reinterpret_cast<float2*>(sm + D_SCB);
    const int tid  = threadIdx.x;
    const int wid  = tid >> 5;
    const int lane = tid & 31;
    const size_t P0 = (size_t)blockIdx.y * 128;   // p-tile (slow)
    const int o0 = blockIdx.x * 128;              // o-tile (fast, adjacent pairs)
    const int wm = wid & 3;            // p: 4 x 32
    const int wn = wid >> 2;           // o: 2 x 64

    auto load_chunk = [&](int c, int st) {
        // A: 32 k-rows x 16 uint4 (hi+lo)
        for (int i = tid; i < 512; i += 256) {
            int r = i >> 4, col = i & 15;
            uint32_t d = sb + st * D_APAIR + r * D_AP + col * 16;
            size_t go = ((size_t)(c * 32 + r) * NPOS + P0) * 2 + col * 16;
            cpasync16(d,          (const char*)g_corrh + go);
            cpasync16(d + D_ASTG, (const char*)g_corrl + go);
        }
        // B: 128 o-rows x 4 uint4 (hi+lo)
        for (int i = tid; i < 512; i += 256) {
            int r = i >> 2, col = i & 3;
            uint32_t d = sb + D_OFFB + st * D_BPAIR + r * D_BP + col * 16;
            size_t go = (size_t)(o0 + r) * (KPAD * 2) + c * 64 + col * 16;
            cpasync16(d,          (const char*)g_dwh + go);
            cpasync16(d + D_BSTG, (const char*)g_dwl + go);
        }
        asm volatile("cp.async.commit_group;" ::: "memory");
    };

    load_chunk(0, 0);
    load_chunk(1, 1);
    if (tid < 128) {
        int o = o0 + tid;
        float s = gamma[o] * rsqrtf(var[o] + EPS);
        scb[tid] = make_float2(s, beta[o] - mean[o] * s);
    }

    float acc[2][8][4];
#pragma unroll
    for (int i = 0; i < 2; i++)
#pragma unroll
        for (int j = 0; j < 8; j++)
#pragma unroll
            for (int q = 0; q < 4; q++) acc[i][j][q] = 0.f;

    const uint32_t a_kr = (lane & 7) + ((lane >> 4) << 3);
    const uint32_t a_mrb = (wm * 32 + (((lane >> 3) & 1) << 3)) * 2;
    const uint32_t b_row0 = wn * 64 + ((lane >> 4) << 3) + (lane & 7);
    const uint32_t b_colb = (((lane >> 3) & 1) << 4);

#pragma unroll 1
    for (int c = 0; c < D_NKC; c++) {
        if (c >= D_NKC - 2)
            asm volatile("cp.async.wait_group 0;" ::: "memory");
        else
            asm volatile("cp.async.wait_group 1;" ::: "memory");
        __syncthreads();
        const int st = c % 3;
        const uint32_t sah = sb + st * D_APAIR;
        const uint32_t sbh = sb + D_OFFB + st * D_BPAIR;

#pragma unroll
        for (int ks2 = 0; ks2 < 2; ks2++) {
            uint32_t ah[2][4], al[2][4];
#pragma unroll
            for (int mt = 0; mt < 2; mt++) {
                uint32_t ad = sah + (ks2 * 16 + a_kr) * D_AP + a_mrb + mt * 32;
                ldmat4t(ah[mt], ad);
                ldmat4t(al[mt], ad + D_ASTG);
            }
#pragma unroll
            for (int np = 0; np < 4; np++) {
                uint32_t bd = sbh + (b_row0 + np * 16) * D_BP + ks2 * 32 + b_colb;
                uint32_t bh[4], bl[4];
                ldmat4(bh, bd);
                ldmat4(bl, bd + D_BSTG);
#pragma unroll
                for (int mt = 0; mt < 2; mt++) {
                    float* c0 = acc[mt][2 * np];
                    float* c1 = acc[mt][2 * np + 1];
                    mma16816(c0, ah[mt], bh);
                    mma16816(c0, al[mt], bh);
                    mma16816(c0, ah[mt], bl);
                    mma16816(c1, ah[mt], bh + 2);
                    mma16816(c1, al[mt], bh + 2);
                    mma16816(c1, ah[mt], bl + 2);
                }
            }
        }
        if (c + 2 < D_NKC) load_chunk(c + 2, (c + 2) % 3);
    }

    // Epilogue: bn + residual + relu, out[b][o][tp].
    const int bb  = (int)(P0 / THW);
    const int tp0 = (int)(P0 % THW);
    const int g = lane >> 2, tq = lane & 3;
#pragma unroll
    for (int mt = 0; mt < 2; mt++) {
        const int pl = wm * 32 + mt * 16 + g;
        const int tp = tp0 + pl;
#pragma unroll
        for (int nt = 0; nt < 8; nt++) {
            const float* c = acc[mt][nt];
            const int ol = wn * 64 + nt * 8 + 2 * tq;
            const float2 s0 = scb[ol];
            const float2 s1 = scb[ol + 1];
            const size_t base0 = ((size_t)bb * Cc + (o0 + ol)) * THW + tp;
            const size_t base1 = base0 + THW;
            float r0 = fmaxf(c[0] * s0.x + s0.y + x[base0],     0.f);
            float r1 = fmaxf(c[1] * s1.x + s1.y + x[base1],     0.f);
            float r2 = fmaxf(c[2] * s0.x + s0.y + x[base0 + 8], 0.f);
            float r3 = fmaxf(c[3] * s1.x + s1.y + x[base1 + 8], 0.f);
            out[base0]     = r0;
            out[base1]     = r1;
            out[base0 + 8] = r2;
            out[base1 + 8] = r3;
        }
    }
}

// ---------------------------------------------------------------------------
extern "C" void kernel_launch(void* const* d_in, const int* in_sizes, int n_in,
                              void* d_out, int out_size) {
    const float* x         = (const float*)d_in[0];
    const float* enc_w     = (const float*)d_in[1];
    const float* enc_gamma = (const float*)d_in[2];
    const float* enc_beta  = (const float*)d_in[3];
    const float* enc_mean  = (const float*)d_in[4];
    const float* enc_var   = (const float*)d_in[5];
    const float* fw        = (const float*)d_in[6];
    const float* dec_w     = (const float*)d_in[7];
    const float* dec_gamma = (const float*)d_in[8];
    const float* dec_beta  = (const float*)d_in[9];
    const float* dec_mean  = (const float*)d_in[10];
    const float* dec_var   = (const float*)d_in[11];
    float* out = (float*)d_out;

    cudaFuncSetAttribute(k_encode, cudaFuncAttributeMaxDynamicSharedMemorySize, SMEM_ENC);
    cudaFuncSetAttribute(k_dec, cudaFuncAttributeMaxDynamicSharedMemorySize, SMEM_DEC);

    k_prep<<<KPAD, Cc>>>(dec_w);
    k_prep_enc<<<CE, Cc>>>(enc_w);
    k_encode<<<dim3(THW / 256, Bsz), 512, SMEM_ENC>>>(x, enc_gamma, enc_beta,
                                                      enc_mean, enc_var);
    k_corr<<<Bsz * Tt * 7, 224>>>(fw);
    k_dec<<<dim3(Cc / 128, NPOS / 128), 256, SMEM_DEC>>>(x, dec_gamma, dec_beta,
                                                         dec_mean, dec_var, out);
}

// round 14
// speedup vs baseline: 2.8881x; 1.0326x over previous
#include <cuda_runtime.h>
#include <cuda_bf16.h>
#include <cstdint>

// Problem constants
#define Bsz 4
#define Cc 256
#define CE 64
#define Tt 16
#define Hh 56
#define Ww 56
#define HW (Hh*Ww)            // 3136
#define THW (Tt*HW)           // 50176
#define NPOS (Bsz*THW)        // 200704
#define KK 49
#define K2G 196
#define KPAD 224              // 7 chunks of 32
#define EPS 1e-5f

// Scratch. Zero-initialized at load; g_corr rows >= 196 never written -> K pad.
__device__ float g_xenc[(size_t)Bsz * 32 * THW * 2];       // [b][cpair][p][2]
__device__ __nv_bfloat16 g_corrh[(size_t)KPAD * NPOS];     // corr hi [k][pos]
__device__ __nv_bfloat16 g_corrl[(size_t)KPAD * NPOS];     // corr lo [k][pos]
__device__ __nv_bfloat16 g_dwh[Cc * KPAD];                 // dec_w hi [o][224]
__device__ __nv_bfloat16 g_dwl[Cc * KPAD];                 // dec_w lo [o][224]
__device__ __nv_bfloat16 g_ewh[CE * Cc];                   // enc_w hi [ce][256]
__device__ __nv_bfloat16 g_ewl[CE * Cc];                   // enc_w lo [ce][256]

__device__ __forceinline__ uint32_t smem_u32(const void* p) {
    uint32_t a;
    asm("{ .reg .u64 t; cvta.to.shared.u64 t, %1; cvt.u32.u64 %0, t; }"
        : "=r"(a) : "l"(p));
    return a;
}
__device__ __forceinline__ void cpasync16(uint32_t saddr, const void* g) {
    asm volatile("cp.async.cg.shared.global [%0], [%1], 16;"
                 :: "r"(saddr), "l"(g) : "memory");
}
__device__ __forceinline__ void sts8(uint32_t saddr, uint32_t a, uint32_t b) {
    asm volatile("st.shared.v2.b32 [%0], {%1, %2};" :: "r"(saddr), "r"(a), "r"(b)
                 : "memory");
}
__device__ __forceinline__ void ldmat4(uint32_t* d, uint32_t addr) {
    asm volatile("ldmatrix.sync.aligned.m8n8.x4.shared.b16 {%0,%1,%2,%3}, [%4];"
                 : "=r"(d[0]), "=r"(d[1]), "=r"(d[2]), "=r"(d[3]) : "r"(addr));
}
__device__ __forceinline__ void ldmat4t(uint32_t* d, uint32_t addr) {
    asm volatile("ldmatrix.sync.aligned.m8n8.x4.trans.shared.b16 {%0,%1,%2,%3}, [%4];"
                 : "=r"(d[0]), "=r"(d[1]), "=r"(d[2]), "=r"(d[3]) : "r"(addr));
}
__device__ __forceinline__ void mma16816(float* c, const uint32_t* a, const uint32_t* b) {
    asm volatile(
        "mma.sync.aligned.m16n8k16.row.col.f32.bf16.bf16.f32 "
        "{%0,%1,%2,%3}, {%4,%5,%6,%7}, {%8,%9}, {%0,%1,%2,%3};"
        : "+f"(c[0]), "+f"(c[1]), "+f"(c[2]), "+f"(c[3])
        : "r"(a[0]), "r"(a[1]), "r"(a[2]), "r"(a[3]), "r"(b[0]), "r"(b[1]));
}
__device__ __forceinline__ uint32_t packhi(float a, float b, float& ra, float& rb) {
    __nv_bfloat16 ha = __float2bfloat16(a), hb = __float2bfloat16(b);
    ra = a - __bfloat162float(ha);
    rb = b - __bfloat162float(hb);
    return (uint32_t)__bfloat16_as_ushort(ha) |
           ((uint32_t)__bfloat16_as_ushort(hb) << 16);
}
__device__ __forceinline__ uint32_t packbf(float a, float b) {
    return (uint32_t)__bfloat16_as_ushort(__float2bfloat16(a)) |
           ((uint32_t)__bfloat16_as_ushort(__float2bfloat16(b)) << 16);
}

// ---------------------------------------------------------------------------
// Kernel 0a: split dec_w [o][196] -> [o][224] bf16 hi/lo (zero-pad)
// ---------------------------------------------------------------------------
__global__ void k_prep(const float* __restrict__ dw) {
    int k = blockIdx.x;   // 0..223
    int o = threadIdx.x;
    float v = (k < K2G) ? dw[o * K2G + k] : 0.f;
    __nv_bfloat16 h = __float2bfloat16(v);
    float r = v - __bfloat162float(h);
    g_dwh[o * KPAD + k] = h;
    g_dwl[o * KPAD + k] = __float2bfloat16(r);
}
// Kernel 0b: split enc_w [ce][256] -> bf16 hi/lo
__global__ void k_prep_enc(const float* __restrict__ ew) {
    int ce = blockIdx.x;
    int c  = threadIdx.x;
    float v = ew[ce * Cc + c];
    __nv_bfloat16 h = __float2bfloat16(v);
    g_ewh[ce * Cc + c] = h;
    g_ewl[ce * Cc + c] = __float2bfloat16(v - __bfloat162float(h));
}

// ---------------------------------------------------------------------------
// Kernel 1: encode via bf16 hi/lo HMMA (R9 version, proven).
// ---------------------------------------------------------------------------
#define E_PITCH 528
#define E_ATILE (32 * E_PITCH)
#define E_BTILE (64 * E_PITCH)
#define E_OFFB (4 * E_ATILE)
#define E_SCB (E_OFFB + 2 * E_BTILE)
#define SMEM_ENC (E_SCB + 512)

__global__ void __launch_bounds__(512, 1) k_encode(
    const float* __restrict__ x,
    const float* __restrict__ gamma, const float* __restrict__ beta,
    const float* __restrict__ mean, const float* __restrict__ var) {
    extern __shared__ __align__(16) char sm[];
    const uint32_t sb = smem_u32(sm);
    float2* scb = reinterpret_cast<float2*>(sm + E_SCB);
    const int tid  = threadIdx.x;
    const int wid  = tid >> 5;
    const int lane = tid & 31;
    const int b  = blockIdx.y;
    const int P0 = blockIdx.x * 256;
    const int wm = wid & 7;
    const int wn = wid >> 3;

    for (int i = tid; i < 64 * 32; i += 512) {
        int r = i >> 5, c = i & 31;
        uint32_t d = sb + E_OFFB + r * E_PITCH + c * 16;
        size_t go = (size_t)r * 512 + c * 16;
        cpasync16(d,           (const char*)g_ewh + go);
        cpasync16(d + E_BTILE, (const char*)g_ewl + go);
    }
    asm volatile("cp.async.commit_group;" ::: "memory");
    if (tid < 64) {
        float s = gamma[tid] * rsqrtf(var[tid] + EPS);
        scb[tid] = make_float2(s, beta[tid] - mean[tid] * s);
    }

    const float* xb = x + (size_t)b * Cc * THW + P0;
    const int st_r  = tid >> 6;
    const int st_c4 = (tid & 63) * 4;

#pragma unroll
    for (int e = 0; e < 4; e++) {
        int r = st_r + 8 * e;
        float4 v = *reinterpret_cast<const float4*>(xb + (size_t)r * THW + st_c4);
        float rx, ry, rz, rw;
        uint32_t h0 = packhi(v.x, v.y, rx, ry);
        uint32_t h1 = packhi(v.z, v.w, rz, rw);
        uint32_t d = sb + r * E_PITCH + st_c4 * 2;
        sts8(d, h0, h1);
        sts8(d + E_ATILE, packbf(rx, ry), packbf(rz, rw));
    }
    asm volatile("cp.async.wait_group 0;" ::: "memory");
    __syncthreads();

    float acc[2][4][4];
#pragma unroll
    for (int i = 0; i < 2; i++)
#pragma unroll
        for (int j = 0; j < 4; j++)
#pragma unroll
            for (int q = 0; q < 4; q++) acc[i][j][q] = 0.f;

    const uint32_t a_kr = (lane & 7) + ((lane >> 4) << 3);
    const uint32_t a_mr = ((lane >> 3) & 1) << 3;
    const uint32_t b_row0 = wn * 32 + ((lane >> 4) << 3) + (lane & 7);
    const uint32_t b_colb = (((lane >> 3) & 1) << 4);

#pragma unroll 1
    for (int kc = 0; kc < 8; kc++) {
        float4 v[4];
        if (kc < 7) {
            const float* xk = xb + (size_t)(kc + 1) * 32 * THW;
#pragma unroll
            for (int e = 0; e < 4; e++)
                v[e] = *reinterpret_cast<const float4*>(
                    xk + (size_t)(st_r + 8 * e) * THW + st_c4);
        }
        const uint32_t ab = sb + (kc & 1) * (2 * E_ATILE);
#pragma unroll
        for (int ks2 = 0; ks2 < 2; ks2++) {
            uint32_t ah[2][4], al[2][4];
#pragma unroll
            for (int mt = 0; mt < 2; mt++) {
                uint32_t ad = ab + (ks2 * 16 + a_kr) * E_PITCH
                            + (wm * 32 + mt * 16 + a_mr) * 2;
                ldmat4t(ah[mt], ad);
                ldmat4t(al[mt], ad + E_ATILE);
            }
#pragma unroll
            for (int np = 0; np < 2; np++) {
                uint32_t bd = sb + E_OFFB + (b_row0 + np * 16) * E_PITCH
                            + (kc * 32 + ks2 * 16) * 2 + b_colb;
                uint32_t bh[4], bl[4];
                ldmat4(bh, bd);
                ldmat4(bl, bd + E_BTILE);
#pragma unroll
                for (int mt = 0; mt < 2; mt++) {
                    float* c0 = acc[mt][2 * np];
                    float* c1 = acc[mt][2 * np + 1];
                    mma16816(c0, ah[mt], bh);
                    mma16816(c0, al[mt], bh);
                    mma16816(c0, ah[mt], bl);
                    mma16816(c1, ah[mt], bh + 2);
                    mma16816(c1, al[mt], bh + 2);
                    mma16816(c1, ah[mt], bl + 2);
                }
            }
        }
        __syncthreads();
        if (kc < 7) {
            const uint32_t nb = sb + ((kc + 1) & 1) * (2 * E_ATILE);
#pragma unroll
            for (int e = 0; e < 4; e++) {
                int r = st_r + 8 * e;
                float rx, ry, rz, rw;
                uint32_t h0 = packhi(v[e].x, v[e].y, rx, ry);
                uint32_t h1 = packhi(v[e].z, v[e].w, rz, rw);
                uint32_t d = nb + r * E_PITCH + st_c4 * 2;
                sts8(d, h0, h1);
                sts8(d + E_ATILE, packbf(rx, ry), packbf(rz, rw));
            }
            __syncthreads();
        }
    }

    const int g = lane >> 2, tq = lane & 3;
#pragma unroll
    for (int mt = 0; mt < 2; mt++) {
        const int p = P0 + wm * 32 + mt * 16 + g;
#pragma unroll
        for (int nt = 0; nt < 4; nt++) {
            const float* c = acc[mt][nt];
            const int ol = wn * 32 + nt * 8 + 2 * tq;
            const float2 s0 = scb[ol];
            const float2 s1 = scb[ol + 1];
            const int cp = ol >> 1;
            float* base = &g_xenc[(((size_t)b * 32 + cp) * THW + p) * 2];
            float2 v0, v1;
            v0.x = fmaxf(c[0] * s0.x + s0.y, 0.f);
            v0.y = fmaxf(c[1] * s1.x + s1.y, 0.f);
            v1.x = fmaxf(c[2] * s0.x + s0.y, 0.f);
            v1.y = fmaxf(c[3] * s1.x + s1.y, 0.f);
            *reinterpret_cast<float2*>(base)      = v0;
            *reinterpret_cast<float2*>(base + 16) = v1;
        }
    }
}

// ---------------------------------------------------------------------------
// Kernel 2: correlation v5 — ko-split for occupancy. Two passes over the 32
// channel stages: pass 0 handles ky 0..3 (28 offsets), pass 1 ky 4..6 (21).
// Live accumulators 56 (was 98) -> ~90 regs -> 3 CTAs/SM; grid 448 vs
// capacity 444 -> ~1 wave (was 1.51).
// ---------------------------------------------------------------------------
__global__ void __launch_bounds__(224, 3) k_corr(const float* __restrict__ fw) {
    __shared__ __align__(16) float2 fws2[32 * KK];     // [cpair][ko]
    __shared__ __align__(16) float2 buf[2][14][64];    // double-buffered window
    const int tid = threadIdx.x;
    const int bx = blockIdx.x;
    const int h0 = (bx % 7) * 8;
    const int t  = (bx / 7) % Tt;
    const int b  = bx / (7 * Tt);
    const int a  = tid / 56;          // 0..3 -> row pair
    const int w  = tid % 56;
    const int jA = 2 * a;             // buf-local row of posA
    const int hA = h0 + jA;           // global h of posA; posB = hA+1
    const int t1 = (t == 0) ? 0 : t - 1;

    for (int idx = tid; idx < 32 * KK; idx += 224) {
        int cp = idx / KK, ko = idx % KK;
        int c = cp * 2;
        fws2[idx] = make_float2(fw[(c * Tt + t) * KK + ko],
                                fw[((c + 1) * Tt + t) * KK + ko]);
    }
    __syncthreads();

    const float2* xe = reinterpret_cast<const float2*>(g_xenc);
    const size_t cstride = THW;
    const size_t cb0 = (size_t)(b * 32) * cstride;

    // staging geometry: 14*64 = 896 entries, 4 per thread
    uint32_t sidx[4];   // packed j*64+m
    bool in[4];
    uint32_t off[4];    // float2-element offset within batch slab
#pragma unroll
    for (int e = 0; e < 4; e++) {
        int idx = tid + 224 * e;
        int j = idx >> 6, m = idx & 63;
        sidx[e] = (uint32_t)idx;
        int gh = h0 + j - 3, gx = m - 3;
        in[e] = (unsigned)gh < (unsigned)Hh && (unsigned)gx < (unsigned)Ww;
        off[e] = (uint32_t)(t * HW + gh * Ww + gx);
    }
    const uint32_t x1offA = (uint32_t)(t1 * HW + hA * Ww + w);
    const size_t posA = ((size_t)(b * Tt + t) * Hh + hA) * Ww + w;

#pragma unroll
    for (int half = 0; half < 2; half++) {
        const int kyLo = half ? 4 : 0;
        const int kyN  = half ? 3 : 4;   // accs used: kyN*7 (28 / 21)
        float accA[28], accB[28];
#pragma unroll
        for (int i = 0; i < 28; i++) { accA[i] = 0.f; accB[i] = 0.f; }

        // prologue: stage 0
        float2 pf[4], x1Ac, x1Bc, x1An, x1Bn;
#pragma unroll
        for (int e = 0; e < 4; e++)
            pf[e] = in[e] ? xe[cb0 + off[e]] : make_float2(0.f, 0.f);
        x1Ac = xe[cb0 + x1offA];
        x1Bc = xe[cb0 + x1offA + Ww];
#pragma unroll
        for (int e = 0; e < 4; e++)
            buf[0][sidx[e] >> 6][sidx[e] & 63] = pf[e];
        __syncthreads();

#pragma unroll 1
        for (int s = 0; s < 32; s++) {
            const size_t cbn = cb0 + (size_t)(s + 1) * cstride;
            if (s < 31) {
#pragma unroll
                for (int e = 0; e < 4; e++)
                    pf[e] = in[e] ? xe[cbn + off[e]] : make_float2(0.f, 0.f);
                x1An = xe[cbn + x1offA];
                x1Bn = xe[cbn + x1offA + Ww];
            }
            const float2* fp = &fws2[s * KK];
            const float2 (*bw)[64] = buf[s & 1];
#pragma unroll
            for (int kx = 0; kx < 7; kx++) {
                float2 fcol[4];
#pragma unroll
                for (int r = 0; r < 4; r++)
                    if (r < kyN) fcol[r] = fp[(kyLo + r) * 7 + kx];
#pragma unroll
                for (int r2 = 0; r2 < 5; r2++) {
                    if (r2 > kyN) break;
                    float2 v = bw[jA + kyLo + r2][w + kx];
                    if (r2 < kyN)
                        accA[r2 * 7 + kx] += fcol[r2].x * x1Ac.x * v.x
                                           + fcol[r2].y * x1Ac.y * v.y;
                    if (r2 >= 1)
                        accB[(r2 - 1) * 7 + kx] += fcol[r2 - 1].x * x1Bc.x * v.x
                                                 + fcol[r2 - 1].y * x1Bc.y * v.y;
                }
            }
            if ((s & 7) == 7) {   // flush 16-channel group
                const int g4 = s >> 3;
                const int nacc = kyN * 7;
#pragma unroll
                for (int i = 0; i < 28; i++) {
                    if (i >= nacc) break;
                    const int ko = kyLo * 7 + i;
                    size_t row = (size_t)(ko * 4 + g4) * NPOS;
                    float vA = accA[i] * 0.0625f;
                    __nv_bfloat16 hA2 = __float2bfloat16(vA);
                    g_corrh[row + posA] = hA2;
                    g_corrl[row + posA] = __float2bfloat16(vA - __bfloat162float(hA2));
                    float vB = accB[i] * 0.0625f;
                    __nv_bfloat16 hB2 = __float2bfloat16(vB);
                    g_corrh[row + posA + Ww] = hB2;
                    g_corrl[row + posA + Ww] = __float2bfloat16(vB - __bfloat162float(hB2));
                    accA[i] = 0.f;
                    accB[i] = 0.f;
                }
            }
            if (s < 31) {
#pragma unroll
                for (int e = 0; e < 4; e++)
                    buf[(s + 1) & 1][sidx[e] >> 6][sidx[e] & 63] = pf[e];
                x1Ac = x1An;
                x1Bc = x1Bn;
            }
            __syncthreads();      // single barrier per stage
        }
    }
}

// ---------------------------------------------------------------------------
// Kernel 3: decode v6 (R13, proven): CTA 128p x 128o, 256 threads, K=224 in
// 7 chunks of 32, 3-stage cp.async ring, one barrier/chunk, 2 CTAs/SM.
// ---------------------------------------------------------------------------
#define D_NKC 7
#define D_AP 272
#define D_ASTG (32 * D_AP)
#define D_APAIR (2 * D_ASTG)
#define D_BP 80
#define D_BSTG (128 * D_BP)
#define D_BPAIR (2 * D_BSTG)
#define D_OFFB (3 * D_APAIR)
#define D_SCB (D_OFFB + 3 * D_BPAIR)
#define SMEM_DEC (D_SCB + 1024)

__global__ void __launch_bounds__(256, 2) k_dec(
    const float* __restrict__ x,
    const float* __restrict__ gamma, const float* __restrict__ beta,
    const float* __restrict__ mean, const float* __restrict__ var,
    float* __restrict__ out) {
    extern __shared__ __align__(16) char sm[];
    const uint32_t sb = smem_u32(sm);
    float2* scb = reinterpret_cast<float2*>(sm + D_SCB);
    const int tid  = threadIdx.x;
    const int wid  = tid >> 5;
    const int lane = tid & 31;
    const size_t P0 = (size_t)blockIdx.y * 128;
    const int o0 = blockIdx.x * 128;
    const int wm = wid & 3;
    const int wn = wid >> 2;

    auto load_chunk = [&](int c, int st) {
        for (int i = tid; i < 512; i += 256) {
            int r = i >> 4, col = i & 15;
            uint32_t d = sb + st * D_APAIR + r * D_AP + col * 16;
            size_t go = ((size_t)(c * 32 + r) * NPOS + P0) * 2 + col * 16;
            cpasync16(d,          (const char*)g_corrh + go);
            cpasync16(d + D_ASTG, (const char*)g_corrl + go);
        }
        for (int i = tid; i < 512; i += 256) {
            int r = i >> 2, col = i & 3;
            uint32_t d = sb + D_OFFB + st * D_BPAIR + r * D_BP + col * 16;
            size_t go = (size_t)(o0 + r) * (KPAD * 2) + c * 64 + col * 16;
            cpasync16(d,          (const char*)g_dwh + go);
            cpasync16(d + D_BSTG, (const char*)g_dwl + go);
        }
        asm volatile("cp.async.commit_group;" ::: "memory");
    };

    load_chunk(0, 0);
    load_chunk(1, 1);
    if (tid < 128) {
        int o = o0 + tid;
        float s = gamma[o] * rsqrtf(var[o] + EPS);
        scb[tid] = make_float2(s, beta[o] - mean[o] * s);
    }

    float acc[2][8][4];
#pragma unroll
    for (int i = 0; i < 2; i++)
#pragma unroll
        for (int j = 0; j < 8; j++)
#pragma unroll
            for (int q = 0; q < 4; q++) acc[i][j][q] = 0.f;

    const uint32_t a_kr = (lane & 7) + ((lane >> 4) << 3);
    const uint32_t a_mrb = (wm * 32 + (((lane >> 3) & 1) << 3)) * 2;
    const uint32_t b_row0 = wn * 64 + ((lane >> 4) << 3) + (lane & 7);
    const uint32_t b_colb = (((lane >> 3) & 1) << 4);

#pragma unroll 1
    for (int c = 0; c < D_NKC; c++) {
        if (c >= D_NKC - 2)
            asm volatile("cp.async.wait_group 0;" ::: "memory");
        else
            asm volatile("cp.async.wait_group 1;" ::: "memory");
        __syncthreads();
        const int st = c % 3;
        const uint32_t sah = sb + st * D_APAIR;
        const uint32_t sbh = sb + D_OFFB + st * D_BPAIR;

#pragma unroll
        for (int ks2 = 0; ks2 < 2; ks2++) {
            uint32_t ah[2][4], al[2][4];
#pragma unroll
            for (int mt = 0; mt < 2; mt++) {
                uint32_t ad = sah + (ks2 * 16 + a_kr) * D_AP + a_mrb + mt * 32;
                ldmat4t(ah[mt], ad);
                ldmat4t(al[mt], ad + D_ASTG);
            }
#pragma unroll
            for (int np = 0; np < 4; np++) {
                uint32_t bd = sbh + (b_row0 + np * 16) * D_BP + ks2 * 32 + b_colb;
                uint32_t bh[4], bl[4];
                ldmat4(bh, bd);
                ldmat4(bl, bd + D_BSTG);
#pragma unroll
                for (int mt = 0; mt < 2; mt++) {
                    float* c0 = acc[mt][2 * np];
                    float* c1 = acc[mt][2 * np + 1];
                    mma16816(c0, ah[mt], bh);
                    mma16816(c0, al[mt], bh);
                    mma16816(c0, ah[mt], bl);
                    mma16816(c1, ah[mt], bh + 2);
                    mma16816(c1, al[mt], bh + 2);
                    mma16816(c1, ah[mt], bl + 2);
                }
            }
        }
        if (c + 2 < D_NKC) load_chunk(c + 2, (c + 2) % 3);
    }

    const int bb  = (int)(P0 / THW);
    const int tp0 = (int)(P0 % THW);
    const int g = lane >> 2, tq = lane & 3;
#pragma unroll
    for (int mt = 0; mt < 2; mt++) {
        const int pl = wm * 32 + mt * 16 + g;
        const int tp = tp0 + pl;
#pragma unroll
        for (int nt = 0; nt < 8; nt++) {
            const float* c = acc[mt][nt];
            const int ol = wn * 64 + nt * 8 + 2 * tq;
            const float2 s0 = scb[ol];
            const float2 s1 = scb[ol + 1];
            const size_t base0 = ((size_t)bb * Cc + (o0 + ol)) * THW + tp;
            const size_t base1 = base0 + THW;
            float r0 = fmaxf(c[0] * s0.x + s0.y + x[base0],     0.f);
            float r1 = fmaxf(c[1] * s1.x + s1.y + x[base1],     0.f);
            float r2 = fmaxf(c[2] * s0.x + s0.y + x[base0 + 8], 0.f);
            float r3 = fmaxf(c[3] * s1.x + s1.y + x[base1 + 8], 0.f);
            out[base0]     = r0;
            out[base1]     = r1;
            out[base0 + 8] = r2;
            out[base1 + 8] = r3;
        }
    }
}

// ---------------------------------------------------------------------------
extern "C" void kernel_launch(void* const* d_in, const int* in_sizes, int n_in,
                              void* d_out, int out_size) {
    const float* x         = (const float*)d_in[0];
    const float* enc_w     = (const float*)d_in[1];
    const float* enc_gamma = (const float*)d_in[2];
    const float* enc_beta  = (const float*)d_in[3];
    const float* enc_mean  = (const float*)d_in[4];
    const float* enc_var   = (const float*)d_in[5];
    const float* fw        = (const float*)d_in[6];
    const float* dec_w     = (const float*)d_in[7];
    const float* dec_gamma = (const float*)d_in[8];
    const float* dec_beta  = (const float*)d_in[9];
    const float* dec_mean  = (const float*)d_in[10];
    const float* dec_var   = (const float*)d_in[11];
    float* out = (float*)d_out;

    cudaFuncSetAttribute(k_encode, cudaFuncAttributeMaxDynamicSharedMemorySize, SMEM_ENC);
    cudaFuncSetAttribute(k_dec, cudaFuncAttributeMaxDynamicSharedMemorySize, SMEM_DEC);

    k_prep<<<KPAD, Cc>>>(dec_w);
    k_prep_enc<<<CE, Cc>>>(enc_w);
    k_encode<<<dim3(THW / 256, Bsz), 512, SMEM_ENC>>>(x, enc_gamma, enc_beta,
                                                      enc_mean, enc_var);
    k_corr<<<Bsz * Tt * 7, 224>>>(fw);
    k_dec<<<dim3(Cc / 128, NPOS / 128), 256, SMEM_DEC>>>(x, dec_gamma, dec_beta,
                                                         dec_mean, dec_var, out);
}

// round 16
// speedup vs baseline: 2.9011x; 1.0045x over previous
#include <cuda_runtime.h>
#include <cuda_bf16.h>
#include <cstdint>

// Problem constants
#define Bsz 4
#define Cc 256
#define CE 64
#define Tt 16
#define Hh 56
#define Ww 56
#define HW (Hh*Ww)            // 3136
#define THW (Tt*HW)           // 50176
#define NPOS (Bsz*THW)        // 200704
#define KK 49
#define K2G 196
#define KPAD 224              // 7 chunks of 32
#define EPS 1e-5f

// Scratch. Zero-initialized at load; g_corr rows >= 196 never written -> K pad.
__device__ float g_xenc[(size_t)Bsz * 32 * THW * 2];       // [b][cpair][p][2]
__device__ __nv_bfloat16 g_corrh[(size_t)KPAD * NPOS];     // corr hi [k][pos]
__device__ __nv_bfloat16 g_corrl[(size_t)KPAD * NPOS];     // corr lo [k][pos]
__device__ __nv_bfloat16 g_dwh[Cc * KPAD];                 // dec_w hi [o][224]
__device__ __nv_bfloat16 g_dwl[Cc * KPAD];                 // dec_w lo [o][224]
__device__ __nv_bfloat16 g_ewh[CE * Cc];                   // enc_w hi [ce][256]
__device__ __nv_bfloat16 g_ewl[CE * Cc];                   // enc_w lo [ce][256]

__device__ __forceinline__ uint32_t smem_u32(const void* p) {
    uint32_t a;
    asm("{ .reg .u64 t; cvta.to.shared.u64 t, %1; cvt.u32.u64 %0, t; }"
        : "=r"(a) : "l"(p));
    return a;
}
__device__ __forceinline__ void cpasync16(uint32_t saddr, const void* g) {
    asm volatile("cp.async.cg.shared.global [%0], [%1], 16;"
                 :: "r"(saddr), "l"(g) : "memory");
}
__device__ __forceinline__ void sts8(uint32_t saddr, uint32_t a, uint32_t b) {
    asm volatile("st.shared.v2.b32 [%0], {%1, %2};" :: "r"(saddr), "r"(a), "r"(b)
                 : "memory");
}
__device__ __forceinline__ void ldmat4(uint32_t* d, uint32_t addr) {
    asm volatile("ldmatrix.sync.aligned.m8n8.x4.shared.b16 {%0,%1,%2,%3}, [%4];"
                 : "=r"(d[0]), "=r"(d[1]), "=r"(d[2]), "=r"(d[3]) : "r"(addr));
}
__device__ __forceinline__ void ldmat4t(uint32_t* d, uint32_t addr) {
    asm volatile("ldmatrix.sync.aligned.m8n8.x4.trans.shared.b16 {%0,%1,%2,%3}, [%4];"
                 : "=r"(d[0]), "=r"(d[1]), "=r"(d[2]), "=r"(d[3]) : "r"(addr));
}
__device__ __forceinline__ void mma16816(float* c, const uint32_t* a, const uint32_t* b) {
    asm volatile(
        "mma.sync.aligned.m16n8k16.row.col.f32.bf16.bf16.f32 "
        "{%0,%1,%2,%3}, {%4,%5,%6,%7}, {%8,%9}, {%0,%1,%2,%3};"
        : "+f"(c[0]), "+f"(c[1]), "+f"(c[2]), "+f"(c[3])
        : "r"(a[0]), "r"(a[1]), "r"(a[2]), "r"(a[3]), "r"(b[0]), "r"(b[1]));
}
__device__ __forceinline__ uint32_t packhi(float a, float b, float& ra, float& rb) {
    __nv_bfloat16 ha = __float2bfloat16(a), hb = __float2bfloat16(b);
    ra = a - __bfloat162float(ha);
    rb = b - __bfloat162float(hb);
    return (uint32_t)__bfloat16_as_ushort(ha) |
           ((uint32_t)__bfloat16_as_ushort(hb) << 16);
}
__device__ __forceinline__ uint32_t packbf(float a, float b) {
    return (uint32_t)__bfloat16_as_ushort(__float2bfloat16(a)) |
           ((uint32_t)__bfloat16_as_ushort(__float2bfloat16(b)) << 16);
}

// ---------------------------------------------------------------------------
// Kernel 0a: split dec_w [o][196] -> [o][224] bf16 hi/lo (zero-pad)
// ---------------------------------------------------------------------------
__global__ void k_prep(const float* __restrict__ dw) {
    int k = blockIdx.x;
    int o = threadIdx.x;
    float v = (k < K2G) ? dw[o * K2G + k] : 0.f;
    __nv_bfloat16 h = __float2bfloat16(v);
    float r = v - __bfloat162float(h);
    g_dwh[o * KPAD + k] = h;
    g_dwl[o * KPAD + k] = __float2bfloat16(r);
}
// Kernel 0b: split enc_w [ce][256] -> bf16 hi/lo
__global__ void k_prep_enc(const float* __restrict__ ew) {
    int ce = blockIdx.x;
    int c  = threadIdx.x;
    float v = ew[ce * Cc + c];
    __nv_bfloat16 h = __float2bfloat16(v);
    g_ewh[ce * Cc + c] = h;
    g_ewl[ce * Cc + c] = __float2bfloat16(v - __bfloat162float(h));
}

// ---------------------------------------------------------------------------
// Kernel 1: encode v2 — CTA 128p x 64ce, 256 threads (8 warps, 32p x 32ce),
// K=256 in 8 chunks of 32, 2-stage A ring with ONE barrier/chunk, B resident.
// smem 103KB -> 2 CTAs/SM. fp32 -> bf16 hi/lo split in registers at staging.
// ---------------------------------------------------------------------------
#define E2_PITCH 272                     // A pitch: 128p*2B + 16
#define E2_ASTG (32 * E2_PITCH)          // 8704 (one of hi/lo)
#define E2_APAIR (2 * E2_ASTG)           // 17408
#define E2_OFFB (2 * E2_APAIR)           // 34816
#define E2_BPITCH 528                    // B pitch: 256k*2B + 16
#define E2_BTILE (64 * E2_BPITCH)        // 33792
#define E2_SCB (E2_OFFB + 2 * E2_BTILE)  // 102400
#define SMEM_ENC (E2_SCB + 512)          // 102912

__global__ void __launch_bounds__(256, 2) k_encode(
    const float* __restrict__ x,
    const float* __restrict__ gamma, const float* __restrict__ beta,
    const float* __restrict__ mean, const float* __restrict__ var) {
    extern __shared__ __align__(16) char sm[];
    const uint32_t sb = smem_u32(sm);
    float2* scb = reinterpret_cast<float2*>(sm + E2_SCB);
    const int tid  = threadIdx.x;
    const int wid  = tid >> 5;
    const int lane = tid & 31;
    const int b  = blockIdx.y;
    const int P0 = blockIdx.x * 128;
    const int wm = wid & 3;            // p: 4 x 32
    const int wn = wid >> 2;           // ce: 2 x 32

    // Stage B (enc_w hi/lo, 64 rows x 512B) via cp.async
    for (int i = tid; i < 64 * 32; i += 256) {
        int r = i >> 5, c = i & 31;
        uint32_t d = sb + E2_OFFB + r * E2_BPITCH + c * 16;
        size_t go = (size_t)r * 512 + c * 16;
        cpasync16(d,            (const char*)g_ewh + go);
        cpasync16(d + E2_BTILE, (const char*)g_ewl + go);
    }
    asm volatile("cp.async.commit_group;" ::: "memory");
    if (tid < 64) {
        float s = gamma[tid] * rsqrtf(var[tid] + EPS);
        scb[tid] = make_float2(s, beta[tid] - mean[tid] * s);
    }

    const float* xb = x + (size_t)b * Cc * THW + P0;
    // A staging geometry: 32 rows x 32 float4 = 1024 entries, 4 per thread
    const int st_r = tid >> 5;             // base row (0..7)
    const int st_q = (tid & 31) * 4;       // p offset (0..124)

    // prologue: stage chunk 0 into buffer 0
#pragma unroll
    for (int e = 0; e < 4; e++) {
        int r = st_r + 8 * e;
        float4 v = *reinterpret_cast<const float4*>(xb + (size_t)r * THW + st_q);
        float rx, ry, rz, rw;
        uint32_t h0 = packhi(v.x, v.y, rx, ry);
        uint32_t h1 = packhi(v.z, v.w, rz, rw);
        uint32_t d = sb + r * E2_PITCH + st_q * 2;
        sts8(d, h0, h1);
        sts8(d + E2_ASTG, packbf(rx, ry), packbf(rz, rw));
    }
    asm volatile("cp.async.wait_group 0;" ::: "memory");
    __syncthreads();

    float acc[2][4][4];
#pragma unroll
    for (int i = 0; i < 2; i++)
#pragma unroll
        for (int j = 0; j < 4; j++)
#pragma unroll
            for (int q = 0; q < 4; q++) acc[i][j][q] = 0.f;

    const uint32_t a_kr = (lane & 7) + ((lane >> 4) << 3);
    const uint32_t a_mrb = (wm * 32 + (((lane >> 3) & 1) << 3)) * 2;
    const uint32_t b_row0 = wn * 32 + ((lane >> 4) << 3) + (lane & 7);
    const uint32_t b_colb = (((lane >> 3) & 1) << 4);

#pragma unroll 1
    for (int kc = 0; kc < 8; kc++) {
        float4 v[4];
        if (kc < 7) {
            const float* xk = xb + (size_t)(kc + 1) * 32 * THW;
#pragma unroll
            for (int e = 0; e < 4; e++)
                v[e] = *reinterpret_cast<const float4*>(
                    xk + (size_t)(st_r + 8 * e) * THW + st_q);
        }
        // compute chunk kc from stage kc&1
        const uint32_t ab = sb + (kc & 1) * E2_APAIR;
#pragma unroll
        for (int ks2 = 0; ks2 < 2; ks2++) {
            uint32_t ah[2][4], al[2][4];
#pragma unroll
            for (int mt = 0; mt < 2; mt++) {
                uint32_t ad = ab + (ks2 * 16 + a_kr) * E2_PITCH + a_mrb + mt * 32;
                ldmat4t(ah[mt], ad);
                ldmat4t(al[mt], ad + E2_ASTG);
            }
#pragma unroll
            for (int np = 0; np < 2; np++) {
                uint32_t bd = sb + E2_OFFB + (b_row0 + np * 16) * E2_BPITCH
                            + (kc * 32 + ks2 * 16) * 2 + b_colb;
                uint32_t bh[4], bl[4];
                ldmat4(bh, bd);
                ldmat4(bl, bd + E2_BTILE);
#pragma unroll
                for (int mt = 0; mt < 2; mt++) {
                    float* c0 = acc[mt][2 * np];
                    float* c1 = acc[mt][2 * np + 1];
                    mma16816(c0, ah[mt], bh);
                    mma16816(c0, al[mt], bh);
                    mma16816(c0, ah[mt], bl);
                    mma16816(c1, ah[mt], bh + 2);
                    mma16816(c1, al[mt], bh + 2);
                    mma16816(c1, ah[mt], bl + 2);
                }
            }
        }
        // store chunk kc+1 into the other stage (its previous readers finished
        // before the barrier that ended chunk kc-1), then ONE barrier.
        if (kc < 7) {
            const uint32_t nb = sb + ((kc + 1) & 1) * E2_APAIR;
#pragma unroll
            for (int e = 0; e < 4; e++) {
                int r = st_r + 8 * e;
                float rx, ry, rz, rw;
                uint32_t h0 = packhi(v[e].x, v[e].y, rx, ry);
                uint32_t h1 = packhi(v[e].z, v[e].w, rz, rw);
                uint32_t d = nb + r * E2_PITCH + st_q * 2;
                sts8(d, h0, h1);
                sts8(d + E2_ASTG, packbf(rx, ry), packbf(rz, rw));
            }
        }
        __syncthreads();
    }

    // Epilogue: BN + ReLU, pair-interleaved float2 stores.
    const int g = lane >> 2, tq = lane & 3;
#pragma unroll
    for (int mt = 0; mt < 2; mt++) {
        const int p = P0 + wm * 32 + mt * 16 + g;
#pragma unroll
        for (int nt = 0; nt < 4; nt++) {
            const float* c = acc[mt][nt];
            const int ol = wn * 32 + nt * 8 + 2 * tq;
            const float2 s0 = scb[ol];
            const float2 s1 = scb[ol + 1];
            const int cp = ol >> 1;
            float* base = &g_xenc[(((size_t)b * 32 + cp) * THW + p) * 2];
            float2 v0, v1;
            v0.x = fmaxf(c[0] * s0.x + s0.y, 0.f);
            v0.y = fmaxf(c[1] * s1.x + s1.y, 0.f);
            v1.x = fmaxf(c[2] * s0.x + s0.y, 0.f);
            v1.y = fmaxf(c[3] * s1.x + s1.y, 0.f);
            *reinterpret_cast<float2*>(base)      = v0;   // row p
            *reinterpret_cast<float2*>(base + 16) = v1;   // row p+8
        }
    }
}

// ---------------------------------------------------------------------------
// Kernel 2: correlation v5 (R14, proven: 159us, 3 CTAs/SM, ko-split).
// ---------------------------------------------------------------------------
__global__ void __launch_bounds__(224, 3) k_corr(const float* __restrict__ fw) {
    __shared__ __align__(16) float2 fws2[32 * KK];
    __shared__ __align__(16) float2 buf[2][14][64];
    const int tid = threadIdx.x;
    const int bx = blockIdx.x;
    const int h0 = (bx % 7) * 8;
    const int t  = (bx / 7) % Tt;
    const int b  = bx / (7 * Tt);
    const int a  = tid / 56;
    const int w  = tid % 56;
    const int jA = 2 * a;
    const int hA = h0 + jA;
    const int t1 = (t == 0) ? 0 : t - 1;

    for (int idx = tid; idx < 32 * KK; idx += 224) {
        int cp = idx / KK, ko = idx % KK;
        int c = cp * 2;
        fws2[idx] = make_float2(fw[(c * Tt + t) * KK + ko],
                                fw[((c + 1) * Tt + t) * KK + ko]);
    }
    __syncthreads();

    const float2* xe = reinterpret_cast<const float2*>(g_xenc);
    const size_t cstride = THW;
    const size_t cb0 = (size_t)(b * 32) * cstride;

    uint32_t sidx[4];
    bool in[4];
    uint32_t off[4];
#pragma unroll
    for (int e = 0; e < 4; e++) {
        int idx = tid + 224 * e;
        int j = idx >> 6, m = idx & 63;
        sidx[e] = (uint32_t)idx;
        int gh = h0 + j - 3, gx = m - 3;
        in[e] = (unsigned)gh < (unsigned)Hh && (unsigned)gx < (unsigned)Ww;
        off[e] = (uint32_t)(t * HW + gh * Ww + gx);
    }
    const uint32_t x1offA = (uint32_t)(t1 * HW + hA * Ww + w);
    const size_t posA = ((size_t)(b * Tt + t) * Hh + hA) * Ww + w;

#pragma unroll
    for (int half = 0; half < 2; half++) {
        const int kyLo = half ? 4 : 0;
        const int kyN  = half ? 3 : 4;
        float accA[28], accB[28];
#pragma unroll
        for (int i = 0; i < 28; i++) { accA[i] = 0.f; accB[i] = 0.f; }

        float2 pf[4], x1Ac, x1Bc, x1An, x1Bn;
#pragma unroll
        for (int e = 0; e < 4; e++)
            pf[e] = in[e] ? xe[cb0 + off[e]] : make_float2(0.f, 0.f);
        x1Ac = xe[cb0 + x1offA];
        x1Bc = xe[cb0 + x1offA + Ww];
#pragma unroll
        for (int e = 0; e < 4; e++)
            buf[0][sidx[e] >> 6][sidx[e] & 63] = pf[e];
        __syncthreads();

#pragma unroll 1
        for (int s = 0; s < 32; s++) {
            const size_t cbn = cb0 + (size_t)(s + 1) * cstride;
            if (s < 31) {
#pragma unroll
                for (int e = 0; e < 4; e++)
                    pf[e] = in[e] ? xe[cbn + off[e]] : make_float2(0.f, 0.f);
                x1An = xe[cbn + x1offA];
                x1Bn = xe[cbn + x1offA + Ww];
            }
            const float2* fp = &fws2[s * KK];
            const float2 (*bw)[64] = buf[s & 1];
#pragma unroll
            for (int kx = 0; kx < 7; kx++) {
                float2 fcol[4];
#pragma unroll
                for (int r = 0; r < 4; r++)
                    if (r < kyN) fcol[r] = fp[(kyLo + r) * 7 + kx];
#pragma unroll
                for (int r2 = 0; r2 < 5; r2++) {
                    if (r2 > kyN) break;
                    float2 v = bw[jA + kyLo + r2][w + kx];
                    if (r2 < kyN)
                        accA[r2 * 7 + kx] += fcol[r2].x * x1Ac.x * v.x
                                           + fcol[r2].y * x1Ac.y * v.y;
                    if (r2 >= 1)
                        accB[(r2 - 1) * 7 + kx] += fcol[r2 - 1].x * x1Bc.x * v.x
                                                 + fcol[r2 - 1].y * x1Bc.y * v.y;
                }
            }
            if ((s & 7) == 7) {
                const int g4 = s >> 3;
                const int nacc = kyN * 7;
#pragma unroll
                for (int i = 0; i < 28; i++) {
                    if (i >= nacc) break;
                    const int ko = kyLo * 7 + i;
                    size_t row = (size_t)(ko * 4 + g4) * NPOS;
                    float vA = accA[i] * 0.0625f;
                    __nv_bfloat16 hA2 = __float2bfloat16(vA);
                    g_corrh[row + posA] = hA2;
                    g_corrl[row + posA] = __float2bfloat16(vA - __bfloat162float(hA2));
                    float vB = accB[i] * 0.0625f;
                    __nv_bfloat16 hB2 = __float2bfloat16(vB);
                    g_corrh[row + posA + Ww] = hB2;
                    g_corrl[row + posA + Ww] = __float2bfloat16(vB - __bfloat162float(hB2));
                    accA[i] = 0.f;
                    accB[i] = 0.f;
                }
            }
            if (s < 31) {
#pragma unroll
                for (int e = 0; e < 4; e++)
                    buf[(s + 1) & 1][sidx[e] >> 6][sidx[e] & 63] = pf[e];
                x1Ac = x1An;
                x1Bc = x1Bn;
            }
            __syncthreads();
        }
    }
}

// ---------------------------------------------------------------------------
// Kernel 3: decode v6.1 — R13 + earlier chunk-load issue (right after the
// top-of-chunk barrier; the target stage's readers all passed that barrier).
// ---------------------------------------------------------------------------
#define D_NKC 7
#define D_AP 272
#define D_ASTG (32 * D_AP)
#define D_APAIR (2 * D_ASTG)
#define D_BP 80
#define D_BSTG (128 * D_BP)
#define D_BPAIR (2 * D_BSTG)
#define D_OFFB (3 * D_APAIR)
#define D_SCB (D_OFFB + 3 * D_BPAIR)
#define SMEM_DEC (D_SCB + 1024)

__global__ void __launch_bounds__(256, 2) k_dec(
    const float* __restrict__ x,
    const float* __restrict__ gamma, const float* __restrict__ beta,
    const float* __restrict__ mean, const float* __restrict__ var,
    float* __restrict__ out) {
    extern __shared__ __align__(16) char sm[];
    const uint32_t sb = smem_u32(sm);
    float2* scb = reinterpret_cast<float2*>(sm + D_SCB);
    const int tid  = threadIdx.x;
    const int wid  = tid >> 5;
    const int lane = tid & 31;
    const size_t P0 = (size_t)blockIdx.y * 128;
    const int o0 = blockIdx.x * 128;
    const int wm = wid & 3;
    const int wn = wid >> 2;

    auto load_chunk = [&](int c, int st) {
        for (int i = tid; i < 512; i += 256) {
            int r = i >> 4, col = i & 15;
            uint32_t d = sb + st * D_APAIR + r * D_AP + col * 16;
            size_t go = ((size_t)(c * 32 + r) * NPOS + P0) * 2 + col * 16;
            cpasync16(d,          (const char*)g_corrh + go);
            cpasync16(d + D_ASTG, (const char*)g_corrl + go);
        }
        for (int i = tid; i < 512; i += 256) {
            int r = i >> 2, col = i & 3;
            uint32_t d = sb + D_OFFB + st * D_BPAIR + r * D_BP + col * 16;
            size_t go = (size_t)(o0 + r) * (KPAD * 2) + c * 64 + col * 16;
            cpasync16(d,          (const char*)g_dwh + go);
            cpasync16(d + D_BSTG, (const char*)g_dwl + go);
        }
        asm volatile("cp.async.commit_group;" ::: "memory");
    };

    load_chunk(0, 0);
    load_chunk(1, 1);
    if (tid < 128) {
        int o = o0 + tid;
        float s = gamma[o] * rsqrtf(var[o] + EPS);
        scb[tid] = make_float2(s, beta[o] - mean[o] * s);
    }

    float acc[2][8][4];
#pragma unroll
    for (int i = 0; i < 2; i++)
#pragma unroll
        for (int j = 0; j < 8; j++)
#pragma unroll
            for (int q = 0; q < 4; q++) acc[i][j][q] = 0.f;

    const uint32_t a_kr = (lane & 7) + ((lane >> 4) << 3);
    const uint32_t a_mrb = (wm * 32 + (((lane >> 3) & 1) << 3)) * 2;
    const uint32_t b_row0 = wn * 64 + ((lane >> 4) << 3) + (lane & 7);
    const uint32_t b_colb = (((lane >> 3) & 1) << 4);

#pragma unroll 1
    for (int c = 0; c < D_NKC; c++) {
        if (c >= D_NKC - 2)
            asm volatile("cp.async.wait_group 0;" ::: "memory");
        else
            asm volatile("cp.async.wait_group 1;" ::: "memory");
        __syncthreads();
        // issue the next-next chunk load NOW: its stage held chunk c-1,
        // whose readers all passed the barrier above.
        if (c + 2 < D_NKC) load_chunk(c + 2, (c + 2) % 3);

        const int st = c % 3;
        const uint32_t sah = sb + st * D_APAIR;
        const uint32_t sbh = sb + D_OFFB + st * D_BPAIR;

#pragma unroll
        for (int ks2 = 0; ks2 < 2; ks2++) {
            uint32_t ah[2][4], al[2][4];
#pragma unroll
            for (int mt = 0; mt < 2; mt++) {
                uint32_t ad = sah + (ks2 * 16 + a_kr) * D_AP + a_mrb + mt * 32;
                ldmat4t(ah[mt], ad);
                ldmat4t(al[mt], ad + D_ASTG);
            }
#pragma unroll
            for (int np = 0; np < 4; np++) {
                uint32_t bd = sbh + (b_row0 + np * 16) * D_BP + ks2 * 32 + b_colb;
                uint32_t bh[4], bl[4];
                ldmat4(bh, bd);
                ldmat4(bl, bd + D_BSTG);
#pragma unroll
                for (int mt = 0; mt < 2; mt++) {
                    float* c0 = acc[mt][2 * np];
                    float* c1 = acc[mt][2 * np + 1];
                    mma16816(c0, ah[mt], bh);
                    mma16816(c0, al[mt], bh);
                    mma16816(c0, ah[mt], bl);
                    mma16816(c1, ah[mt], bh + 2);
                    mma16816(c1, al[mt], bh + 2);
                    mma16816(c1, ah[mt], bl + 2);
                }
            }
        }
    }

    const int bb  = (int)(P0 / THW);
    const int tp0 = (int)(P0 % THW);
    const int g = lane >> 2, tq = lane & 3;
#pragma unroll
    for (int mt = 0; mt < 2; mt++) {
        const int pl = wm * 32 + mt * 16 + g;
        const int tp = tp0 + pl;
#pragma unroll
        for (int nt = 0; nt < 8; nt++) {
            const float* c = acc[mt][nt];
            const int ol = wn * 64 + nt * 8 + 2 * tq;
            const float2 s0 = scb[ol];
            const float2 s1 = scb[ol + 1];
            const size_t base0 = ((size_t)bb * Cc + (o0 + ol)) * THW + tp;
            const size_t base1 = base0 + THW;
            float r0 = fmaxf(c[0] * s0.x + s0.y + x[base0],     0.f);
            float r1 = fmaxf(c[1] * s1.x + s1.y + x[base1],     0.f);
            float r2 = fmaxf(c[2] * s0.x + s0.y + x[base0 + 8], 0.f);
            float r3 = fmaxf(c[3] * s1.x + s1.y + x[base1 + 8], 0.f);
            out[base0]     = r0;
            out[base1]     = r1;
            out[base0 + 8] = r2;
            out[base1 + 8] = r3;
        }
    }
}

// ---------------------------------------------------------------------------
extern "C" void kernel_launch(void* const* d_in, const int* in_sizes, int n_in,
                              void* d_out, int out_size) {
    const float* x         = (const float*)d_in[0];
    const float* enc_w     = (const float*)d_in[1];
    const float* enc_gamma = (const float*)d_in[2];
    const float* enc_beta  = (const float*)d_in[3];
    const float* enc_mean  = (const float*)d_in[4];
    const float* enc_var   = (const float*)d_in[5];
    const float* fw        = (const float*)d_in[6];
    const float* dec_w     = (const float*)d_in[7];
    const float* dec_gamma = (const float*)d_in[8];
    const float* dec_beta  = (const float*)d_in[9];
    const float* dec_mean  = (const float*)d_in[10];
    const float* dec_var   = (const float*)d_in[11];
    float* out = (float*)d_out;

    cudaFuncSetAttribute(k_encode, cudaFuncAttributeMaxDynamicSharedMemorySize, SMEM_ENC);
    cudaFuncSetAttribute(k_dec, cudaFuncAttributeMaxDynamicSharedMemorySize, SMEM_DEC);

    k_prep<<<KPAD, Cc>>>(dec_w);
    k_prep_enc<<<CE, Cc>>>(enc_w);
    k_encode<<<dim3(THW / 128, Bsz), 256, SMEM_ENC>>>(x, enc_gamma, enc_beta,
                                                      enc_mean, enc_var);
    k_corr<<<Bsz * Tt * 7, 224>>>(fw);
    k_dec<<<dim3(Cc / 128, NPOS / 128), 256, SMEM_DEC>>>(x, dec_gamma, dec_beta,
                                                         dec_mean, dec_var, out);
}